// round 5
// baseline (speedup 1.0000x reference)
#include <cuda_runtime.h>
#include <cuda_bf16.h>
#include <math.h>
#include <stdint.h>

#define Bb   2
#define Ss   2048
#define Dd   2048
#define Hh   16
#define DHd  128
#define FFf  8192
#define ROWS 4096   // B*S

typedef __nv_bfloat16 bf16;

// ================= scratch (device globals) =================
__device__ bf16  g_h1h[(size_t)ROWS * Dd],  g_h1l[(size_t)ROWS * Dd];
__device__ bf16  g_wqkvh[(size_t)3 * Dd * Dd], g_wqkvl[(size_t)3 * Dd * Dd];
__device__ bf16  g_woh[(size_t)Dd * Dd],    g_wol[(size_t)Dd * Dd];
__device__ bf16  g_fih[(size_t)Dd * FFf],   g_fil[(size_t)Dd * FFf];
__device__ bf16  g_foh[(size_t)Dd * FFf],   g_fol[(size_t)Dd * FFf];
__device__ bf16  g_qkh[(size_t)2 * ROWS * Dd], g_qkl[(size_t)2 * ROWS * Dd];
__device__ float g_v[(size_t)ROWS * Dd];
__device__ bf16  g_vth[(size_t)Bb * Hh * DHd * Ss], g_vtl[(size_t)Bb * Hh * DHd * Ss];
__device__ bf16  g_ah[(size_t)Bb * Hh * Ss * Ss], g_al[(size_t)Bb * Hh * Ss * Ss];
__device__ bf16  g_ctxh[(size_t)ROWS * Dd], g_ctxl[(size_t)ROWS * Dd];
__device__ float g_aproj[(size_t)ROWS * Dd];
__device__ float g_h2[(size_t)ROWS * Dd];
__device__ bf16  g_h2h[(size_t)ROWS * Dd],  g_h2l[(size_t)ROWS * Dd];
__device__ bf16  g_ffnh[(size_t)ROWS * FFf], g_ffnl[(size_t)ROWS * FFf];
__device__ float g_sin[Ss * 64];
__device__ float g_cos[Ss * 64];

// ================= helpers =================
__device__ __forceinline__ uint32_t smem_u32(const void* p) {
    uint32_t a;
    asm("{ .reg .u64 t; cvta.to.shared.u64 t, %1; cvt.u32.u64 %0, t; }" : "=r"(a) : "l"(p));
    return a;
}
__device__ __forceinline__ void ldm4(uint32_t* r, uint32_t addr) {
    asm volatile("ldmatrix.sync.aligned.m8n8.x4.shared.b16 {%0,%1,%2,%3}, [%4];"
        : "=r"(r[0]), "=r"(r[1]), "=r"(r[2]), "=r"(r[3]) : "r"(addr));
}
__device__ __forceinline__ void ldm2(uint32_t* r, uint32_t addr) {
    asm volatile("ldmatrix.sync.aligned.m8n8.x2.shared.b16 {%0,%1}, [%2];"
        : "=r"(r[0]), "=r"(r[1]) : "r"(addr));
}
__device__ __forceinline__ void mma_bf16(float* c, const uint32_t* a, const uint32_t* b) {
    asm volatile(
        "mma.sync.aligned.m16n8k16.row.col.f32.bf16.bf16.f32 "
        "{%0,%1,%2,%3}, {%4,%5,%6,%7}, {%8,%9}, {%0,%1,%2,%3};"
        : "+f"(c[0]), "+f"(c[1]), "+f"(c[2]), "+f"(c[3])
        : "r"(a[0]), "r"(a[1]), "r"(a[2]), "r"(a[3]), "r"(b[0]), "r"(b[1]));
}
__device__ __forceinline__ void cp16(uint32_t dst, const void* src) {
    asm volatile("cp.async.cg.shared.global [%0], [%1], 16;" :: "r"(dst), "l"(src));
}
__device__ __forceinline__ void cp_commit() { asm volatile("cp.async.commit_group;"); }
__device__ __forceinline__ void cp_wait1() { asm volatile("cp.async.wait_group 1;"); }
__device__ __forceinline__ void cp_wait0() { asm volatile("cp.async.wait_group 0;"); }

__device__ __forceinline__ void split2(float x, float y, bf16* ph, bf16* pl) {
    bf16 hx = __float2bfloat16_rn(x), hy = __float2bfloat16_rn(y);
    float fx = __bfloat162float(hx), fy = __bfloat162float(hy);
    __nv_bfloat162 h2; h2.x = hx; h2.y = hy;
    __nv_bfloat162 l2; l2.x = __float2bfloat16_rn(x - fx); l2.y = __float2bfloat16_rn(y - fy);
    *(__nv_bfloat162*)ph = h2;
    *(__nv_bfloat162*)pl = l2;
}

// ================= RoPE tables =================
__global__ void rope_table_kernel() {
    int t = blockIdx.x * 256 + threadIdx.x;
    if (t >= Ss * 64) return;
    int p = t >> 6, i = t & 63;
    double inv = pow(10000.0, -((double)(2 * i)) / 128.0);
    float ang = (float)p * (float)inv;
    g_sin[t] = (float)sin((double)ang);
    g_cos[t] = (float)cos((double)ang);
}

// ================= weight transpose + split =================
__global__ __launch_bounds__(256) void transpose_split(
    const float* __restrict__ in, bf16* __restrict__ oh, bf16* __restrict__ ol,
    int R, int Cc)
{
    __shared__ float t[32][33];
    int bx = blockIdx.x * 32, by = blockIdx.y * 32;
    int tx = threadIdx.x, ty = threadIdx.y;
#pragma unroll
    for (int i = 0; i < 32; i += 8)
        t[ty + i][tx] = in[(size_t)(by + ty + i) * Cc + bx + tx];
    __syncthreads();
#pragma unroll
    for (int i = 0; i < 32; i += 8) {
        float v = t[tx][ty + i];
        size_t o = (size_t)(bx + ty + i) * R + by + tx;
        bf16 h = __float2bfloat16_rn(v);
        oh[o] = h;
        ol[o] = __float2bfloat16_rn(v - __bfloat162float(h));
    }
}

// V^T per head with split: vt[bh][n][s] = v[b][s][h*128+n]
__global__ __launch_bounds__(256) void vtrans_split(
    const float* __restrict__ v, bf16* __restrict__ oh, bf16* __restrict__ ol)
{
    __shared__ float t[32][33];
    int bh = blockIdx.z;
    int b = bh >> 4, h = bh & 15;
    const float* in = v + (size_t)b * Ss * Dd + h * DHd;
    size_t obase = (size_t)bh * DHd * Ss;
    int s0 = blockIdx.x * 32, n0 = blockIdx.y * 32;
    int tx = threadIdx.x, ty = threadIdx.y;
#pragma unroll
    for (int i = 0; i < 32; i += 8)
        t[ty + i][tx] = in[(size_t)(s0 + ty + i) * Dd + n0 + tx];
    __syncthreads();
#pragma unroll
    for (int i = 0; i < 32; i += 8) {
        float val = t[tx][ty + i];
        size_t o = obase + (size_t)(n0 + ty + i) * Ss + s0 + tx;
        bf16 hh = __float2bfloat16_rn(val);
        oh[o] = hh;
        ol[o] = __float2bfloat16_rn(val - __bfloat162float(hh));
    }
}

// ================= LayerNorm (fp32 out optional, hi/lo out) =================
__global__ __launch_bounds__(256) void ln_kernel(
    const float* __restrict__ x, const float* __restrict__ x2,
    const float* __restrict__ g, const float* __restrict__ bta,
    float* __restrict__ outf, bf16* __restrict__ outh, bf16* __restrict__ outl)
{
    __shared__ float red[256];
    int row = blockIdx.x, tid = threadIdx.x;
    size_t base = (size_t)row * Dd;
    float r[8];
    float s = 0.f;
#pragma unroll
    for (int t = 0; t < 8; t++) {
        int i = tid + t * 256;
        float v = x[base + i];
        if (x2) v += x2[base + i];
        r[t] = v; s += v;
    }
    red[tid] = s; __syncthreads();
    for (int o = 128; o > 0; o >>= 1) { if (tid < o) red[tid] += red[tid + o]; __syncthreads(); }
    float mean = red[0] * (1.0f / Dd);
    __syncthreads();
    float vs = 0.f;
#pragma unroll
    for (int t = 0; t < 8; t++) { float d = r[t] - mean; vs += d * d; }
    red[tid] = vs; __syncthreads();
    for (int o = 128; o > 0; o >>= 1) { if (tid < o) red[tid] += red[tid + o]; __syncthreads(); }
    float var = red[0] * (1.0f / Dd);
    float rs = rsqrtf(var + 1e-5f);
#pragma unroll
    for (int t = 0; t < 8; t++) {
        int i = tid + t * 256;
        float v = (r[t] - mean) * rs * g[i] + bta[i];
        if (outf) outf[base + i] = v;
        bf16 h = __float2bfloat16_rn(v);
        outh[base + i] = h;
        outl[base + i] = __float2bfloat16_rn(v - __bfloat162float(h));
    }
}

// ================= bf16x3 mma.sync GEMM, cp.async 3-stage =================
// flags: 1=bias 2=gelu 4=resid 8=qkv(rope+scatter) 16=score 32=ctx 64=hi/lo out 128=fp32 out
#define PP  10240u            // bytes per part (128 rows * 80B)
#define STG (4u * PP)         // per stage
#define SMT (3u * STG)        // 122880

__global__ __launch_bounds__(256) void gemm_bf3(
    const bf16* __restrict__ Ah, const bf16* __restrict__ Al,
    const bf16* __restrict__ Bh, const bf16* __restrict__ Bl,
    const float* __restrict__ bias, const float* __restrict__ resid,
    float* __restrict__ Cf, bf16* __restrict__ Ch, bf16* __restrict__ Cl,
    const int* __restrict__ pid,
    int K, int lda, int ldb, int ldc, int flags)
{
    extern __shared__ char sm[];
    int bx = blockIdx.x, by = blockIdx.y, bz = blockIdx.z;
    const bf16 *Ahp = Ah, *Alp = Al, *Bhp = Bh, *Blp = Bl;
    float* Cfp = Cf;
    bf16 *Chp = Ch, *Clp = Cl;
    int Keff = K;
    if (flags & 16) {                 // scores per (b,h), causal tile skip
        if (bx > by) return;
        int b = bz >> 4, h = bz & 15;
        size_t ao = (size_t)b * Ss * Dd + h * DHd;
        Ahp += ao; Alp += ao; Bhp += ao; Blp += ao;
        Cfp += (size_t)bz * Ss * Ss;
    }
    if (flags & 32) {                 // ctx: attn @ V^T, truncated K
        int b = bz >> 4, h = bz & 15;
        size_t ao = (size_t)bz * Ss * Ss;
        size_t bo = (size_t)bz * DHd * Ss;
        Ahp += ao; Alp += ao; Bhp += bo; Blp += bo;
        size_t co = (size_t)b * Ss * Dd + h * DHd;
        Chp += co; Clp += co;
        Keff = (by + 1) * 128;
    }
    const int tid = threadIdx.x, lane = tid & 31, warp = tid >> 5;
    const int m0 = by * 128, n0 = bx * 128;
    const int wm = (warp >> 2) * 64, wn = (warp & 3) * 32;
    const uint32_t sbase = smem_u32(sm);

    float acc[4][4][4];
#pragma unroll
    for (int i = 0; i < 4; i++)
#pragma unroll
        for (int j = 0; j < 4; j++)
#pragma unroll
            for (int e = 0; e < 4; e++) acc[i][j][e] = 0.f;

#define ISSUE_CHUNK(ST, K0) do { \
    uint32_t sb0 = sbase + (uint32_t)(ST) * STG; \
    _Pragma("unroll") \
    for (int i = 0; i < 2; i++) { \
        int idx = tid + i * 256; \
        int r = idx >> 2; int cc = idx & 3; \
        uint32_t d = sb0 + (uint32_t)r * 80u + (uint32_t)cc * 16u; \
        size_t sa = (size_t)(m0 + r) * lda + (K0) + cc * 8; \
        size_t sb2 = (size_t)(n0 + r) * ldb + (K0) + cc * 8; \
        cp16(d,           Ahp + sa); \
        cp16(d + PP,      Alp + sa); \
        cp16(d + 2u*PP,   Bhp + sb2); \
        cp16(d + 3u*PP,   Blp + sb2); \
    } \
    cp_commit(); \
} while(0)

    const int nch = Keff / 32;
    ISSUE_CHUNK(0, 0);
    if (nch > 1) ISSUE_CHUNK(1, 32);

    const uint32_t a_lane_off = (uint32_t)(wm + (lane & 15)) * 80u + (uint32_t)((lane >> 4) * 16);
    const uint32_t b_lane_off = (uint32_t)(wn + (lane & 7)) * 80u + (uint32_t)(((lane >> 3) & 1) * 16);

    for (int c = 0; c < nch; c++) {
        if (c + 1 < nch) cp_wait1(); else cp_wait0();
        __syncthreads();
        const uint32_t boff = (uint32_t)(c % 3) * STG;
#pragma unroll
        for (int ks = 0; ks < 2; ks++) {
            uint32_t ahi[4][4], alo[4][4], bhi[4][2], blo[4][2];
            uint32_t abase = sbase + boff + a_lane_off + (uint32_t)(ks * 32);
            uint32_t bbase = sbase + boff + 2u * PP + b_lane_off + (uint32_t)(ks * 32);
#pragma unroll
            for (int mti = 0; mti < 4; mti++) {
                ldm4(ahi[mti], abase + (uint32_t)(mti * 16) * 80u);
                ldm4(alo[mti], abase + (uint32_t)(mti * 16) * 80u + PP);
            }
#pragma unroll
            for (int ntj = 0; ntj < 4; ntj++) {
                ldm2(bhi[ntj], bbase + (uint32_t)(ntj * 8) * 80u);
                ldm2(blo[ntj], bbase + (uint32_t)(ntj * 8) * 80u + PP);
            }
#pragma unroll
            for (int mti = 0; mti < 4; mti++)
#pragma unroll
                for (int ntj = 0; ntj < 4; ntj++) {
                    mma_bf16(acc[mti][ntj], ahi[mti], bhi[ntj]);
                    mma_bf16(acc[mti][ntj], ahi[mti], blo[ntj]);
                    mma_bf16(acc[mti][ntj], alo[mti], bhi[ntj]);
                }
        }
        if (c + 2 < nch) ISSUE_CHUNK((c + 2) % 3, (c + 2) * 32);
    }

    // ---------------- epilogue ----------------
#pragma unroll
    for (int mti = 0; mti < 4; mti++) {
#pragma unroll
        for (int ntj = 0; ntj < 4; ntj++) {
            int row = m0 + wm + mti * 16 + (lane >> 2);
            int col = n0 + wn + ntj * 8 + (lane & 3) * 2;
#pragma unroll
            for (int half = 0; half < 2; half++) {
                int rr = row + half * 8;
                float v0 = acc[mti][ntj][half * 2];
                float v1 = acc[mti][ntj][half * 2 + 1];
                if (flags & 1) { v0 += bias[col]; v1 += bias[col + 1]; }
                if (flags & 2) {
                    v0 = 0.5f * v0 * (1.0f + erff(v0 * 0.70710678118654752f));
                    v1 = 0.5f * v1 * (1.0f + erff(v1 * 0.70710678118654752f));
                }
                if (flags & 4) {
                    const float* rp = resid + (size_t)rr * ldc + col;
                    v0 += rp[0]; v1 += rp[1];
                }
                if (flags & 8) {
                    int sel = col >> 11, cl = col & 2047;
                    if (sel == 2) {
                        *(float2*)(Cfp + (size_t)rr * Dd + cl) = make_float2(v0, v1);
                    } else {
                        int b = rr >> 11, s = rr & 2047;
                        int pos = pid[b * Ss + s];
                        int i = (cl & 127) >> 1;
                        float sn = g_sin[pos * 64 + i], cs = g_cos[pos * 64 + i];
                        float r0 = v0 * cs - v1 * sn;
                        float r1 = v1 * cs + v0 * sn;
                        size_t o = (size_t)(sel * ROWS + rr) * Dd + cl;
                        split2(r0, r1, Chp + o, Clp + o);
                    }
                } else if (flags & 64) {
                    size_t o = (size_t)rr * ldc + col;
                    split2(v0, v1, Chp + o, Clp + o);
                } else {
                    *(float2*)(Cfp + (size_t)rr * ldc + col) = make_float2(v0, v1);
                }
            }
        }
    }
}

// ================= row softmax (causal trunc) + bf16 split out =================
__global__ __launch_bounds__(256) void softmax_kernel(
    float* __restrict__ attn, bf16* __restrict__ ah, bf16* __restrict__ al)
{
    int rid = blockIdx.x;
    int qpos = rid & (Ss - 1);
    int L = qpos + 1;
    float* row = attn + (size_t)rid * Ss;
    bf16* rh = ah + (size_t)rid * Ss;
    bf16* rl = al + (size_t)rid * Ss;
    __shared__ float red[256];
    int tid = threadIdx.x;
    float r[8];
    float mx = -3.4e38f;
#pragma unroll
    for (int t = 0; t < 8; t++) {
        int i = tid + t * 256;
        float v = (i < L) ? row[i] : -3.4e38f;
        r[t] = v; mx = fmaxf(mx, v);
    }
    red[tid] = mx; __syncthreads();
    for (int o = 128; o > 0; o >>= 1) { if (tid < o) red[tid] = fmaxf(red[tid], red[tid + o]); __syncthreads(); }
    mx = red[0]; __syncthreads();
    float s = 0.f;
#pragma unroll
    for (int t = 0; t < 8; t++) {
        int i = tid + t * 256;
        float e = (i < L) ? expf(r[t] - mx) : 0.0f;
        r[t] = e; s += e;
    }
    red[tid] = s; __syncthreads();
    for (int o = 128; o > 0; o >>= 1) { if (tid < o) red[tid] += red[tid + o]; __syncthreads(); }
    float inv = 1.0f / red[0];
#pragma unroll
    for (int t = 0; t < 8; t++) {
        int i = tid + t * 256;
        float v = r[t] * inv;
        row[i] = v;
        bf16 h = __float2bfloat16_rn(v);
        rh[i] = h;
        rl[i] = __float2bfloat16_rn(v - __bfloat162float(h));
    }
}

// ================= launch =================
extern "C" void kernel_launch(void* const* d_in, const int* in_sizes, int n_in,
                              void* d_out, int out_size)
{
    const float* hs   = (const float*)d_in[0];
    const int*   pid  = (const int*)  d_in[1];
    const float* wq   = (const float*)d_in[2];
    const float* wk   = (const float*)d_in[3];
    const float* wv   = (const float*)d_in[4];
    const float* wo   = (const float*)d_in[5];
    const float* ln1g = (const float*)d_in[6];
    const float* ln1b = (const float*)d_in[7];
    const float* ln2g = (const float*)d_in[8];
    const float* ln2b = (const float*)d_in[9];
    const float* fiw  = (const float*)d_in[10];
    const float* fib  = (const float*)d_in[11];
    const float* fow  = (const float*)d_in[12];
    const float* fob  = (const float*)d_in[13];

    float* out  = (float*)d_out;
    float* attn = out + (size_t)ROWS * Dd;

    float *v, *aproj, *h2;
    bf16 *h1h, *h1l, *wqkvh, *wqkvl, *woh, *wol, *fih, *fil, *foh, *fol;
    bf16 *qkh, *qkl, *vth, *vtl, *ah, *al, *ctxh, *ctxl, *h2h, *h2l, *ffnh, *ffnl;
    cudaGetSymbolAddress((void**)&v,     g_v);
    cudaGetSymbolAddress((void**)&aproj, g_aproj);
    cudaGetSymbolAddress((void**)&h2,    g_h2);
    cudaGetSymbolAddress((void**)&h1h,   g_h1h);
    cudaGetSymbolAddress((void**)&h1l,   g_h1l);
    cudaGetSymbolAddress((void**)&wqkvh, g_wqkvh);
    cudaGetSymbolAddress((void**)&wqkvl, g_wqkvl);
    cudaGetSymbolAddress((void**)&woh,   g_woh);
    cudaGetSymbolAddress((void**)&wol,   g_wol);
    cudaGetSymbolAddress((void**)&fih,   g_fih);
    cudaGetSymbolAddress((void**)&fil,   g_fil);
    cudaGetSymbolAddress((void**)&foh,   g_foh);
    cudaGetSymbolAddress((void**)&fol,   g_fol);
    cudaGetSymbolAddress((void**)&qkh,   g_qkh);
    cudaGetSymbolAddress((void**)&qkl,   g_qkl);
    cudaGetSymbolAddress((void**)&vth,   g_vth);
    cudaGetSymbolAddress((void**)&vtl,   g_vtl);
    cudaGetSymbolAddress((void**)&ah,    g_ah);
    cudaGetSymbolAddress((void**)&al,    g_al);
    cudaGetSymbolAddress((void**)&ctxh,  g_ctxh);
    cudaGetSymbolAddress((void**)&ctxl,  g_ctxl);
    cudaGetSymbolAddress((void**)&h2h,   g_h2h);
    cudaGetSymbolAddress((void**)&h2l,   g_h2l);
    cudaGetSymbolAddress((void**)&ffnh,  g_ffnh);
    cudaGetSymbolAddress((void**)&ffnl,  g_ffnl);

    cudaFuncSetAttribute(gemm_bf3, cudaFuncAttributeMaxDynamicSharedMemorySize, SMT);

    rope_table_kernel<<<512, 256>>>();

    dim3 tb(32, 8);
    transpose_split<<<dim3(Dd / 32, Dd / 32), tb>>>(wq, wqkvh, wqkvl, Dd, Dd);
    transpose_split<<<dim3(Dd / 32, Dd / 32), tb>>>(wk, wqkvh + (size_t)Dd * Dd, wqkvl + (size_t)Dd * Dd, Dd, Dd);
    transpose_split<<<dim3(Dd / 32, Dd / 32), tb>>>(wv, wqkvh + (size_t)2 * Dd * Dd, wqkvl + (size_t)2 * Dd * Dd, Dd, Dd);
    transpose_split<<<dim3(Dd / 32, Dd / 32), tb>>>(wo, woh, wol, Dd, Dd);
    transpose_split<<<dim3(FFf / 32, Dd / 32), tb>>>(fiw, fih, fil, Dd, FFf);
    transpose_split<<<dim3(Dd / 32, FFf / 32), tb>>>(fow, foh, fol, FFf, Dd);

    // ln1 -> h1 hi/lo
    ln_kernel<<<ROWS, 256>>>(hs, nullptr, ln1g, ln1b, nullptr, h1h, h1l);

    // fused QKV projection; epilogue applies RoPE to q,k and writes hi/lo; v fp32
    gemm_bf3<<<dim3(48, 32), 256, SMT>>>(h1h, h1l, wqkvh, wqkvl,
        nullptr, nullptr, v, qkh, qkl, pid, Dd, Dd, Dd, Dd, 8);

    vtrans_split<<<dim3(Ss / 32, DHd / 32, Bb * Hh), tb>>>(v, vth, vtl);

    // scores (causal) -> softmax(+split) -> ctx
    gemm_bf3<<<dim3(16, 16, Bb * Hh), 256, SMT>>>(qkh, qkl,
        qkh + (size_t)ROWS * Dd, qkl + (size_t)ROWS * Dd,
        nullptr, nullptr, attn, nullptr, nullptr, nullptr, DHd, Dd, Dd, Ss, 16);
    softmax_kernel<<<Bb * Hh * Ss, 256>>>(attn, ah, al);
    gemm_bf3<<<dim3(1, 16, Bb * Hh), 256, SMT>>>(ah, al, vth, vtl,
        nullptr, nullptr, nullptr, ctxh, ctxl, nullptr, Ss, Ss, Ss, Dd, 32 | 64);

    // output projection (fp32 out)
    gemm_bf3<<<dim3(16, 32), 256, SMT>>>(ctxh, ctxl, woh, wol,
        nullptr, nullptr, aproj, nullptr, nullptr, nullptr, Dd, Dd, Dd, Dd, 0);

    // ln2 over (hidden + attn_proj): fp32 + hi/lo
    ln_kernel<<<ROWS, 256>>>(hs, aproj, ln2g, ln2b, h2, h2h, h2l);

    // FFN1: bias+gelu, hi/lo out
    gemm_bf3<<<dim3(64, 32), 256, SMT>>>(h2h, h2l, fih, fil,
        fib, nullptr, nullptr, ffnh, ffnl, nullptr, Dd, Dd, Dd, FFf, 1 | 2 | 64);
    // FFN2: bias+resid, fp32 out
    gemm_bf3<<<dim3(16, 32), 256, SMT>>>(ffnh, ffnl, foh, fol,
        fob, h2, out, nullptr, nullptr, nullptr, FFf, FFf, FFf, Dd, 1 | 4);
}

// round 6
// speedup vs baseline: 1.0828x; 1.0828x over previous
#include <cuda_runtime.h>
#include <cuda_bf16.h>
#include <math.h>
#include <stdint.h>

#define Bb   2
#define Ss   2048
#define Dd   2048
#define Hh   16
#define DHd  128
#define FFf  8192
#define ROWS 4096   // B*S

typedef __nv_bfloat16 bf16;

// ================= scratch (device globals) =================
__device__ bf16  g_h1h[(size_t)ROWS * Dd],  g_h1l[(size_t)ROWS * Dd];
__device__ bf16  g_wqkvh[(size_t)3 * Dd * Dd], g_wqkvl[(size_t)3 * Dd * Dd];
__device__ bf16  g_woh[(size_t)Dd * Dd],    g_wol[(size_t)Dd * Dd];
__device__ bf16  g_fih[(size_t)Dd * FFf],   g_fil[(size_t)Dd * FFf];
__device__ bf16  g_foh[(size_t)Dd * FFf],   g_fol[(size_t)Dd * FFf];
__device__ bf16  g_qkh[(size_t)2 * ROWS * Dd], g_qkl[(size_t)2 * ROWS * Dd];
__device__ float g_v[(size_t)ROWS * Dd];
__device__ bf16  g_vth[(size_t)Bb * Hh * DHd * Ss], g_vtl[(size_t)Bb * Hh * DHd * Ss];
__device__ bf16  g_ah[(size_t)Bb * Hh * Ss * Ss], g_al[(size_t)Bb * Hh * Ss * Ss];
__device__ bf16  g_ctxh[(size_t)ROWS * Dd], g_ctxl[(size_t)ROWS * Dd];
__device__ float g_aproj[(size_t)ROWS * Dd];
__device__ float g_h2[(size_t)ROWS * Dd];
__device__ bf16  g_h2h[(size_t)ROWS * Dd],  g_h2l[(size_t)ROWS * Dd];
__device__ bf16  g_ffnh[(size_t)ROWS * FFf], g_ffnl[(size_t)ROWS * FFf];
__device__ float g_sin[Ss * 64];
__device__ float g_cos[Ss * 64];

// ================= helpers =================
__device__ __forceinline__ uint32_t smem_u32(const void* p) {
    uint32_t a;
    asm("{ .reg .u64 t; cvta.to.shared.u64 t, %1; cvt.u32.u64 %0, t; }" : "=r"(a) : "l"(p));
    return a;
}
__device__ __forceinline__ void ldm4(uint32_t* r, uint32_t addr) {
    asm volatile("ldmatrix.sync.aligned.m8n8.x4.shared.b16 {%0,%1,%2,%3}, [%4];"
        : "=r"(r[0]), "=r"(r[1]), "=r"(r[2]), "=r"(r[3]) : "r"(addr));
}
__device__ __forceinline__ void ldm2(uint32_t* r, uint32_t addr) {
    asm volatile("ldmatrix.sync.aligned.m8n8.x2.shared.b16 {%0,%1}, [%2];"
        : "=r"(r[0]), "=r"(r[1]) : "r"(addr));
}
__device__ __forceinline__ void mma_bf16(float* c, const uint32_t* a, const uint32_t* b) {
    asm volatile(
        "mma.sync.aligned.m16n8k16.row.col.f32.bf16.bf16.f32 "
        "{%0,%1,%2,%3}, {%4,%5,%6,%7}, {%8,%9}, {%0,%1,%2,%3};"
        : "+f"(c[0]), "+f"(c[1]), "+f"(c[2]), "+f"(c[3])
        : "r"(a[0]), "r"(a[1]), "r"(a[2]), "r"(a[3]), "r"(b[0]), "r"(b[1]));
}
__device__ __forceinline__ void cp16(uint32_t dst, const void* src) {
    asm volatile("cp.async.cg.shared.global [%0], [%1], 16;" :: "r"(dst), "l"(src));
}
__device__ __forceinline__ void cp_commit() { asm volatile("cp.async.commit_group;"); }
__device__ __forceinline__ void cp_wait1() { asm volatile("cp.async.wait_group 1;"); }
__device__ __forceinline__ void cp_wait0() { asm volatile("cp.async.wait_group 0;"); }

__device__ __forceinline__ void split2(float x, float y, bf16* ph, bf16* pl) {
    bf16 hx = __float2bfloat16_rn(x), hy = __float2bfloat16_rn(y);
    float fx = __bfloat162float(hx), fy = __bfloat162float(hy);
    __nv_bfloat162 h2; h2.x = hx; h2.y = hy;
    __nv_bfloat162 l2; l2.x = __float2bfloat16_rn(x - fx); l2.y = __float2bfloat16_rn(y - fy);
    *(__nv_bfloat162*)ph = h2;
    *(__nv_bfloat162*)pl = l2;
}

// ================= RoPE tables =================
__global__ void rope_table_kernel() {
    int t = blockIdx.x * 256 + threadIdx.x;
    if (t >= Ss * 64) return;
    int p = t >> 6, i = t & 63;
    double inv = pow(10000.0, -((double)(2 * i)) / 128.0);
    float ang = (float)p * (float)inv;
    g_sin[t] = (float)sin((double)ang);
    g_cos[t] = (float)cos((double)ang);
}

// ================= weight transpose + split =================
__global__ __launch_bounds__(256) void transpose_split(
    const float* __restrict__ in, bf16* __restrict__ oh, bf16* __restrict__ ol,
    int R, int Cc)
{
    __shared__ float t[32][33];
    int bx = blockIdx.x * 32, by = blockIdx.y * 32;
    int tx = threadIdx.x, ty = threadIdx.y;
#pragma unroll
    for (int i = 0; i < 32; i += 8)
        t[ty + i][tx] = in[(size_t)(by + ty + i) * Cc + bx + tx];
    __syncthreads();
#pragma unroll
    for (int i = 0; i < 32; i += 8) {
        float v = t[tx][ty + i];
        size_t o = (size_t)(bx + ty + i) * R + by + tx;
        bf16 h = __float2bfloat16_rn(v);
        oh[o] = h;
        ol[o] = __float2bfloat16_rn(v - __bfloat162float(h));
    }
}

// V^T per head with split
__global__ __launch_bounds__(256) void vtrans_split(
    const float* __restrict__ v, bf16* __restrict__ oh, bf16* __restrict__ ol)
{
    __shared__ float t[32][33];
    int bh = blockIdx.z;
    int b = bh >> 4, h = bh & 15;
    const float* in = v + (size_t)b * Ss * Dd + h * DHd;
    size_t obase = (size_t)bh * DHd * Ss;
    int s0 = blockIdx.x * 32, n0 = blockIdx.y * 32;
    int tx = threadIdx.x, ty = threadIdx.y;
#pragma unroll
    for (int i = 0; i < 32; i += 8)
        t[ty + i][tx] = in[(size_t)(s0 + ty + i) * Dd + n0 + tx];
    __syncthreads();
#pragma unroll
    for (int i = 0; i < 32; i += 8) {
        float val = t[tx][ty + i];
        size_t o = obase + (size_t)(n0 + ty + i) * Ss + s0 + tx;
        bf16 hh = __float2bfloat16_rn(val);
        oh[o] = hh;
        ol[o] = __float2bfloat16_rn(val - __bfloat162float(hh));
    }
}

// ================= LayerNorm =================
__global__ __launch_bounds__(256) void ln_kernel(
    const float* __restrict__ x, const float* __restrict__ x2,
    const float* __restrict__ g, const float* __restrict__ bta,
    float* __restrict__ outf, bf16* __restrict__ outh, bf16* __restrict__ outl)
{
    __shared__ float red[256];
    int row = blockIdx.x, tid = threadIdx.x;
    size_t base = (size_t)row * Dd;
    float r[8];
    float s = 0.f;
#pragma unroll
    for (int t = 0; t < 8; t++) {
        int i = tid + t * 256;
        float v = x[base + i];
        if (x2) v += x2[base + i];
        r[t] = v; s += v;
    }
    red[tid] = s; __syncthreads();
    for (int o = 128; o > 0; o >>= 1) { if (tid < o) red[tid] += red[tid + o]; __syncthreads(); }
    float mean = red[0] * (1.0f / Dd);
    __syncthreads();
    float vs = 0.f;
#pragma unroll
    for (int t = 0; t < 8; t++) { float d = r[t] - mean; vs += d * d; }
    red[tid] = vs; __syncthreads();
    for (int o = 128; o > 0; o >>= 1) { if (tid < o) red[tid] += red[tid + o]; __syncthreads(); }
    float var = red[0] * (1.0f / Dd);
    float rs = rsqrtf(var + 1e-5f);
#pragma unroll
    for (int t = 0; t < 8; t++) {
        int i = tid + t * 256;
        float v = (r[t] - mean) * rs * g[i] + bta[i];
        if (outf) outf[base + i] = v;
        bf16 h = __float2bfloat16_rn(v);
        outh[base + i] = h;
        outl[base + i] = __float2bfloat16_rn(v - __bfloat162float(h));
    }
}

// ================= bf16x3 mma.sync GEMM, templated tile width =================
// flags: 1=bias 2=gelu 4=resid 8=qkv(rope+scatter) 16=score 32=ctx 64=hi/lo out
#define PPA 10240u            // A part bytes (128 rows * 80B)

template<int BN>
__global__ __launch_bounds__(256) void gemm_bf3(
    const bf16* __restrict__ Ah, const bf16* __restrict__ Al,
    const bf16* __restrict__ Bh, const bf16* __restrict__ Bl,
    const float* __restrict__ bias, const float* __restrict__ resid,
    float* __restrict__ Cf, bf16* __restrict__ Ch, bf16* __restrict__ Cl,
    const int* __restrict__ pid,
    int K, int lda, int ldb, int ldc, int flags)
{
    constexpr uint32_t PPB = (uint32_t)BN * 80u;        // B part bytes
    constexpr uint32_t STG = 2u * PPA + 2u * PPB;       // stage bytes
    constexpr int NFR = BN / 32;                        // B frags per warp
    extern __shared__ char sm[];
    int bx = blockIdx.x, by = blockIdx.y, bz = blockIdx.z;
    const bf16 *Ahp = Ah, *Alp = Al, *Bhp = Bh, *Blp = Bl;
    float* Cfp = Cf;
    bf16 *Chp = Ch, *Clp = Cl;
    int Keff = K;
    if (flags & 16) {
        if (bx * BN > by * 128 + 127) return;   // fully masked tile
        int b = bz >> 4, h = bz & 15;
        size_t ao = (size_t)b * Ss * Dd + h * DHd;
        Ahp += ao; Alp += ao; Bhp += ao; Blp += ao;
        Cfp += (size_t)bz * Ss * Ss;
    }
    if (flags & 32) {
        int b = bz >> 4, h = bz & 15;
        size_t ao = (size_t)bz * Ss * Ss;
        size_t bo = (size_t)bz * DHd * Ss;
        Ahp += ao; Alp += ao; Bhp += bo; Blp += bo;
        size_t co = (size_t)b * Ss * Dd + h * DHd;
        Chp += co; Clp += co;
        Keff = (by + 1) * 128;
    }
    const int tid = threadIdx.x, lane = tid & 31, warp = tid >> 5;
    const int m0 = by * 128, n0 = bx * BN;
    const int wm = (warp >> 2) * 64, wn = (warp & 3) * (BN / 4);
    const uint32_t sbase = smem_u32(sm);

    float acc[4][NFR][4];
#pragma unroll
    for (int i = 0; i < 4; i++)
#pragma unroll
        for (int j = 0; j < NFR; j++)
#pragma unroll
            for (int e = 0; e < 4; e++) acc[i][j][e] = 0.f;

#define ISSUE_CHUNK(ST, K0) do { \
    uint32_t sb0 = sbase + (uint32_t)(ST) * STG; \
    _Pragma("unroll") \
    for (int i = 0; i < 2; i++) { \
        int idx = tid + i * 256; \
        int r = idx >> 2; int cc = idx & 3; \
        uint32_t d = sb0 + (uint32_t)r * 80u + (uint32_t)cc * 16u; \
        size_t sa = (size_t)(m0 + r) * lda + (K0) + cc * 8; \
        cp16(d,       Ahp + sa); \
        cp16(d + PPA, Alp + sa); \
    } \
    _Pragma("unroll") \
    for (int i = 0; i < BN / 64; i++) { \
        int idx = tid + i * 256; \
        int r = idx >> 2; int cc = idx & 3; \
        uint32_t d = sb0 + 2u * PPA + (uint32_t)r * 80u + (uint32_t)cc * 16u; \
        size_t sb2 = (size_t)(n0 + r) * ldb + (K0) + cc * 8; \
        cp16(d,       Bhp + sb2); \
        cp16(d + PPB, Blp + sb2); \
    } \
    cp_commit(); \
} while(0)

    const int nch = Keff / 32;
    ISSUE_CHUNK(0, 0);
    if (nch > 1) ISSUE_CHUNK(1, 32);

    const uint32_t a_lane_off = (uint32_t)(wm + (lane & 15)) * 80u + (uint32_t)((lane >> 4) * 16);
    const uint32_t b_lane_off = (uint32_t)(wn + (lane & 7)) * 80u + (uint32_t)(((lane >> 3) & 1) * 16);

    for (int c = 0; c < nch; c++) {
        if (c + 1 < nch) cp_wait1(); else cp_wait0();
        __syncthreads();
        const uint32_t boff = (uint32_t)(c % 3) * STG;
#pragma unroll
        for (int ks = 0; ks < 2; ks++) {
            uint32_t ahi[4][4], alo[4][4];
            uint32_t abase = sbase + boff + a_lane_off + (uint32_t)(ks * 32);
            uint32_t bbase = sbase + boff + 2u * PPA + b_lane_off + (uint32_t)(ks * 32);
#pragma unroll
            for (int mti = 0; mti < 4; mti++) {
                ldm4(ahi[mti], abase + (uint32_t)(mti * 16) * 80u);
                ldm4(alo[mti], abase + (uint32_t)(mti * 16) * 80u + PPA);
            }
#pragma unroll
            for (int ntj = 0; ntj < NFR; ntj++) {
                uint32_t bhi[2], blo[2];
                ldm2(bhi, bbase + (uint32_t)(ntj * 8) * 80u);
                ldm2(blo, bbase + (uint32_t)(ntj * 8) * 80u + PPB);
#pragma unroll
                for (int mti = 0; mti < 4; mti++) {
                    mma_bf16(acc[mti][ntj], ahi[mti], bhi);
                    mma_bf16(acc[mti][ntj], ahi[mti], blo);
                    mma_bf16(acc[mti][ntj], alo[mti], bhi);
                }
            }
        }
        if (c + 2 < nch) ISSUE_CHUNK((c + 2) % 3, (c + 2) * 32);
    }
#undef ISSUE_CHUNK

    // ---------------- epilogue ----------------
#pragma unroll
    for (int mti = 0; mti < 4; mti++) {
#pragma unroll
        for (int ntj = 0; ntj < NFR; ntj++) {
            int row = m0 + wm + mti * 16 + (lane >> 2);
            int col = n0 + wn + ntj * 8 + (lane & 3) * 2;
#pragma unroll
            for (int half = 0; half < 2; half++) {
                int rr = row + half * 8;
                float v0 = acc[mti][ntj][half * 2];
                float v1 = acc[mti][ntj][half * 2 + 1];
                if (flags & 1) { v0 += bias[col]; v1 += bias[col + 1]; }
                if (flags & 2) {
                    v0 = 0.5f * v0 * (1.0f + erff(v0 * 0.70710678118654752f));
                    v1 = 0.5f * v1 * (1.0f + erff(v1 * 0.70710678118654752f));
                }
                if (flags & 4) {
                    const float* rp = resid + (size_t)rr * ldc + col;
                    v0 += rp[0]; v1 += rp[1];
                }
                if (flags & 8) {
                    int sel = col >> 11, cl = col & 2047;
                    if (sel == 2) {
                        *(float2*)(Cfp + (size_t)rr * Dd + cl) = make_float2(v0, v1);
                    } else {
                        int b = rr >> 11, s = rr & 2047;
                        int pos = pid[b * Ss + s];
                        int i = (cl & 127) >> 1;
                        float sn = g_sin[pos * 64 + i], cs = g_cos[pos * 64 + i];
                        float r0 = v0 * cs - v1 * sn;
                        float r1 = v1 * cs + v0 * sn;
                        size_t o = (size_t)(sel * ROWS + rr) * Dd + cl;
                        split2(r0, r1, Chp + o, Clp + o);
                    }
                } else if (flags & 64) {
                    size_t o = (size_t)rr * ldc + col;
                    split2(v0, v1, Chp + o, Clp + o);
                } else {
                    *(float2*)(Cfp + (size_t)rr * ldc + col) = make_float2(v0, v1);
                }
            }
        }
    }
}

// ================= row softmax (causal trunc) + bf16 split out =================
__global__ __launch_bounds__(256) void softmax_kernel(
    float* __restrict__ attn, bf16* __restrict__ ah, bf16* __restrict__ al)
{
    int rid = blockIdx.x;
    int qpos = rid & (Ss - 1);
    int L = qpos + 1;
    float* row = attn + (size_t)rid * Ss;
    bf16* rh = ah + (size_t)rid * Ss;
    bf16* rl = al + (size_t)rid * Ss;
    __shared__ float red[256];
    int tid = threadIdx.x;
    float r[8];
    float mx = -3.4e38f;
#pragma unroll
    for (int t = 0; t < 8; t++) {
        int i = tid + t * 256;
        float v = (i < L) ? row[i] : -3.4e38f;
        r[t] = v; mx = fmaxf(mx, v);
    }
    red[tid] = mx; __syncthreads();
    for (int o = 128; o > 0; o >>= 1) { if (tid < o) red[tid] = fmaxf(red[tid], red[tid + o]); __syncthreads(); }
    mx = red[0]; __syncthreads();
    float s = 0.f;
#pragma unroll
    for (int t = 0; t < 8; t++) {
        int i = tid + t * 256;
        float e = (i < L) ? expf(r[t] - mx) : 0.0f;
        r[t] = e; s += e;
    }
    red[tid] = s; __syncthreads();
    for (int o = 128; o > 0; o >>= 1) { if (tid < o) red[tid] += red[tid + o]; __syncthreads(); }
    float inv = 1.0f / red[0];
#pragma unroll
    for (int t = 0; t < 8; t++) {
        int i = tid + t * 256;
        float v = r[t] * inv;
        row[i] = v;
        bf16 h = __float2bfloat16_rn(v);
        rh[i] = h;
        rl[i] = __float2bfloat16_rn(v - __bfloat162float(h));
    }
}

// ================= launch =================
extern "C" void kernel_launch(void* const* d_in, const int* in_sizes, int n_in,
                              void* d_out, int out_size)
{
    const float* hs   = (const float*)d_in[0];
    const int*   pid  = (const int*)  d_in[1];
    const float* wq   = (const float*)d_in[2];
    const float* wk   = (const float*)d_in[3];
    const float* wv   = (const float*)d_in[4];
    const float* wo   = (const float*)d_in[5];
    const float* ln1g = (const float*)d_in[6];
    const float* ln1b = (const float*)d_in[7];
    const float* ln2g = (const float*)d_in[8];
    const float* ln2b = (const float*)d_in[9];
    const float* fiw  = (const float*)d_in[10];
    const float* fib  = (const float*)d_in[11];
    const float* fow  = (const float*)d_in[12];
    const float* fob  = (const float*)d_in[13];

    float* out  = (float*)d_out;
    float* attn = out + (size_t)ROWS * Dd;

    float *v, *aproj, *h2;
    bf16 *h1h, *h1l, *wqkvh, *wqkvl, *woh, *wol, *fih, *fil, *foh, *fol;
    bf16 *qkh, *qkl, *vth, *vtl, *ah, *al, *ctxh, *ctxl, *h2h, *h2l, *ffnh, *ffnl;
    cudaGetSymbolAddress((void**)&v,     g_v);
    cudaGetSymbolAddress((void**)&aproj, g_aproj);
    cudaGetSymbolAddress((void**)&h2,    g_h2);
    cudaGetSymbolAddress((void**)&h1h,   g_h1h);
    cudaGetSymbolAddress((void**)&h1l,   g_h1l);
    cudaGetSymbolAddress((void**)&wqkvh, g_wqkvh);
    cudaGetSymbolAddress((void**)&wqkvl, g_wqkvl);
    cudaGetSymbolAddress((void**)&woh,   g_woh);
    cudaGetSymbolAddress((void**)&wol,   g_wol);
    cudaGetSymbolAddress((void**)&fih,   g_fih);
    cudaGetSymbolAddress((void**)&fil,   g_fil);
    cudaGetSymbolAddress((void**)&foh,   g_foh);
    cudaGetSymbolAddress((void**)&fol,   g_fol);
    cudaGetSymbolAddress((void**)&qkh,   g_qkh);
    cudaGetSymbolAddress((void**)&qkl,   g_qkl);
    cudaGetSymbolAddress((void**)&vth,   g_vth);
    cudaGetSymbolAddress((void**)&vtl,   g_vtl);
    cudaGetSymbolAddress((void**)&ah,    g_ah);
    cudaGetSymbolAddress((void**)&al,    g_al);
    cudaGetSymbolAddress((void**)&ctxh,  g_ctxh);
    cudaGetSymbolAddress((void**)&ctxl,  g_ctxl);
    cudaGetSymbolAddress((void**)&h2h,   g_h2h);
    cudaGetSymbolAddress((void**)&h2l,   g_h2l);
    cudaGetSymbolAddress((void**)&ffnh,  g_ffnh);
    cudaGetSymbolAddress((void**)&ffnl,  g_ffnl);

    const uint32_t SMT256 = 3u * (2u * PPA + 2u * 256u * 80u);   // 184320
    const uint32_t SMT128 = 3u * (2u * PPA + 2u * 128u * 80u);   // 122880
    cudaFuncSetAttribute(gemm_bf3<256>, cudaFuncAttributeMaxDynamicSharedMemorySize, SMT256);
    cudaFuncSetAttribute(gemm_bf3<128>, cudaFuncAttributeMaxDynamicSharedMemorySize, SMT128);

    rope_table_kernel<<<512, 256>>>();

    dim3 tb(32, 8);
    transpose_split<<<dim3(Dd / 32, Dd / 32), tb>>>(wq, wqkvh, wqkvl, Dd, Dd);
    transpose_split<<<dim3(Dd / 32, Dd / 32), tb>>>(wk, wqkvh + (size_t)Dd * Dd, wqkvl + (size_t)Dd * Dd, Dd, Dd);
    transpose_split<<<dim3(Dd / 32, Dd / 32), tb>>>(wv, wqkvh + (size_t)2 * Dd * Dd, wqkvl + (size_t)2 * Dd * Dd, Dd, Dd);
    transpose_split<<<dim3(Dd / 32, Dd / 32), tb>>>(wo, woh, wol, Dd, Dd);
    transpose_split<<<dim3(FFf / 32, Dd / 32), tb>>>(fiw, fih, fil, Dd, FFf);
    transpose_split<<<dim3(Dd / 32, FFf / 32), tb>>>(fow, foh, fol, FFf, Dd);

    ln_kernel<<<ROWS, 256>>>(hs, nullptr, ln1g, ln1b, nullptr, h1h, h1l);

    // fused QKV projection (RoPE in epilogue)
    gemm_bf3<256><<<dim3(24, 32), 256, SMT256>>>(h1h, h1l, wqkvh, wqkvl,
        nullptr, nullptr, v, qkh, qkl, pid, Dd, Dd, Dd, Dd, 8);

    vtrans_split<<<dim3(Ss / 32, DHd / 32, Bb * Hh), tb>>>(v, vth, vtl);

    // scores (causal) -> softmax(+split) -> ctx
    gemm_bf3<256><<<dim3(8, 16, Bb * Hh), 256, SMT256>>>(qkh, qkl,
        qkh + (size_t)ROWS * Dd, qkl + (size_t)ROWS * Dd,
        nullptr, nullptr, attn, nullptr, nullptr, nullptr, DHd, Dd, Dd, Ss, 16);
    softmax_kernel<<<Bb * Hh * Ss, 256>>>(attn, ah, al);
    gemm_bf3<128><<<dim3(1, 16, Bb * Hh), 256, SMT128>>>(ah, al, vth, vtl,
        nullptr, nullptr, nullptr, ctxh, ctxl, nullptr, Ss, Ss, Ss, Dd, 32 | 64);

    // output projection
    gemm_bf3<256><<<dim3(8, 32), 256, SMT256>>>(ctxh, ctxl, woh, wol,
        nullptr, nullptr, aproj, nullptr, nullptr, nullptr, Dd, Dd, Dd, Dd, 0);

    ln_kernel<<<ROWS, 256>>>(hs, aproj, ln2g, ln2b, h2, h2h, h2l);

    // FFN
    gemm_bf3<256><<<dim3(32, 32), 256, SMT256>>>(h2h, h2l, fih, fil,
        fib, nullptr, nullptr, ffnh, ffnl, nullptr, Dd, Dd, Dd, FFf, 1 | 2 | 64);
    gemm_bf3<256><<<dim3(8, 32), 256, SMT256>>>(ffnh, ffnl, foh, fol,
        fob, h2, out, nullptr, nullptr, nullptr, FFf, FFf, FFf, Dd, 1 | 4);
}

// round 8
// speedup vs baseline: 1.3466x; 1.2436x over previous
#include <cuda_runtime.h>
#include <cuda_bf16.h>
#include <cuda_fp16.h>
#include <math.h>
#include <stdint.h>

#define Bb   2
#define Ss   2048
#define Dd   2048
#define Hh   16
#define DHd  128
#define FFf  8192
#define ROWS 4096   // B*S

typedef __nv_bfloat16 bf16;

// ================= scratch (device globals) =================
__device__ bf16  g_h1h[(size_t)ROWS * Dd],  g_h1l[(size_t)ROWS * Dd];
__device__ bf16  g_wqkvh[(size_t)3 * Dd * Dd], g_wqkvl[(size_t)3 * Dd * Dd];
__device__ __half g_wof16[(size_t)Dd * Dd];
__device__ __half g_fif16[(size_t)Dd * FFf];
__device__ __half g_fof16[(size_t)Dd * FFf];
__device__ bf16  g_qkh[(size_t)2 * ROWS * Dd], g_qkl[(size_t)2 * ROWS * Dd];
__device__ float g_v[(size_t)ROWS * Dd];
__device__ bf16  g_vth[(size_t)Bb * Hh * DHd * Ss], g_vtl[(size_t)Bb * Hh * DHd * Ss];
__device__ bf16  g_ah[(size_t)Bb * Hh * Ss * Ss], g_al[(size_t)Bb * Hh * Ss * Ss];
__device__ __half g_ctxh16[(size_t)ROWS * Dd], g_ctxl16[(size_t)ROWS * Dd];
__device__ float g_aproj[(size_t)ROWS * Dd];
__device__ float g_h2[(size_t)ROWS * Dd];
__device__ __half g_h2h16[(size_t)ROWS * Dd], g_h2l16[(size_t)ROWS * Dd];
__device__ __half g_ffnh16[(size_t)ROWS * FFf], g_ffnl16[(size_t)ROWS * FFf];
__device__ float g_sin[Ss * 64];
__device__ float g_cos[Ss * 64];

// ================= helpers =================
__device__ __forceinline__ uint32_t smem_u32(const void* p) {
    uint32_t a;
    asm("{ .reg .u64 t; cvta.to.shared.u64 t, %1; cvt.u32.u64 %0, t; }" : "=r"(a) : "l"(p));
    return a;
}
__device__ __forceinline__ void ldm4(uint32_t* r, uint32_t addr) {
    asm volatile("ldmatrix.sync.aligned.m8n8.x4.shared.b16 {%0,%1,%2,%3}, [%4];"
        : "=r"(r[0]), "=r"(r[1]), "=r"(r[2]), "=r"(r[3]) : "r"(addr));
}
__device__ __forceinline__ void ldm2(uint32_t* r, uint32_t addr) {
    asm volatile("ldmatrix.sync.aligned.m8n8.x2.shared.b16 {%0,%1}, [%2];"
        : "=r"(r[0]), "=r"(r[1]) : "r"(addr));
}
__device__ __forceinline__ void mma_bf16(float* c, const uint32_t* a, const uint32_t* b) {
    asm volatile(
        "mma.sync.aligned.m16n8k16.row.col.f32.bf16.bf16.f32 "
        "{%0,%1,%2,%3}, {%4,%5,%6,%7}, {%8,%9}, {%0,%1,%2,%3};"
        : "+f"(c[0]), "+f"(c[1]), "+f"(c[2]), "+f"(c[3])
        : "r"(a[0]), "r"(a[1]), "r"(a[2]), "r"(a[3]), "r"(b[0]), "r"(b[1]));
}
__device__ __forceinline__ void mma_fp16(float* c, const uint32_t* a, const uint32_t* b) {
    asm volatile(
        "mma.sync.aligned.m16n8k16.row.col.f32.f16.f16.f32 "
        "{%0,%1,%2,%3}, {%4,%5,%6,%7}, {%8,%9}, {%0,%1,%2,%3};"
        : "+f"(c[0]), "+f"(c[1]), "+f"(c[2]), "+f"(c[3])
        : "r"(a[0]), "r"(a[1]), "r"(a[2]), "r"(a[3]), "r"(b[0]), "r"(b[1]));
}
__device__ __forceinline__ void cp16(uint32_t dst, const void* src) {
    asm volatile("cp.async.cg.shared.global [%0], [%1], 16;" :: "r"(dst), "l"(src));
}
__device__ __forceinline__ void cp_commit() { asm volatile("cp.async.commit_group;"); }
__device__ __forceinline__ void cp_wait1() { asm volatile("cp.async.wait_group 1;"); }
__device__ __forceinline__ void cp_wait0() { asm volatile("cp.async.wait_group 0;"); }

__device__ __forceinline__ void split2(float x, float y, bf16* ph, bf16* pl) {
    bf16 hx = __float2bfloat16_rn(x), hy = __float2bfloat16_rn(y);
    float fx = __bfloat162float(hx), fy = __bfloat162float(hy);
    __nv_bfloat162 h2; h2.x = hx; h2.y = hy;
    __nv_bfloat162 l2; l2.x = __float2bfloat16_rn(x - fx); l2.y = __float2bfloat16_rn(y - fy);
    *(__nv_bfloat162*)ph = h2;
    *(__nv_bfloat162*)pl = l2;
}
__device__ __forceinline__ void split2h(float x, float y, __half* ph, __half* pl) {
    __half hx = __float2half_rn(x), hy = __float2half_rn(y);
    __half2 h2 = __halves2half2(hx, hy);
    __half2 l2 = __floats2half2_rn(x - __half2float(hx), y - __half2float(hy));
    *(__half2*)ph = h2;
    *(__half2*)pl = l2;
}

// ================= RoPE tables =================
__global__ void rope_table_kernel() {
    int t = blockIdx.x * 256 + threadIdx.x;
    if (t >= Ss * 64) return;
    int p = t >> 6, i = t & 63;
    double inv = pow(10000.0, -((double)(2 * i)) / 128.0);
    float ang = (float)p * (float)inv;
    g_sin[t] = (float)sin((double)ang);
    g_cos[t] = (float)cos((double)ang);
}

// ================= weight transpose variants =================
__global__ __launch_bounds__(256) void transpose_split(
    const float* __restrict__ in, bf16* __restrict__ oh, bf16* __restrict__ ol,
    int R, int Cc)
{
    __shared__ float t[32][33];
    int bx = blockIdx.x * 32, by = blockIdx.y * 32;
    int tx = threadIdx.x, ty = threadIdx.y;
#pragma unroll
    for (int i = 0; i < 32; i += 8)
        t[ty + i][tx] = in[(size_t)(by + ty + i) * Cc + bx + tx];
    __syncthreads();
#pragma unroll
    for (int i = 0; i < 32; i += 8) {
        float v = t[tx][ty + i];
        size_t o = (size_t)(bx + ty + i) * R + by + tx;
        bf16 h = __float2bfloat16_rn(v);
        oh[o] = h;
        ol[o] = __float2bfloat16_rn(v - __bfloat162float(h));
    }
}

__global__ __launch_bounds__(256) void transpose_fp16(
    const float* __restrict__ in, __half* __restrict__ oh, int R, int Cc)
{
    __shared__ float t[32][33];
    int bx = blockIdx.x * 32, by = blockIdx.y * 32;
    int tx = threadIdx.x, ty = threadIdx.y;
#pragma unroll
    for (int i = 0; i < 32; i += 8)
        t[ty + i][tx] = in[(size_t)(by + ty + i) * Cc + bx + tx];
    __syncthreads();
#pragma unroll
    for (int i = 0; i < 32; i += 8)
        oh[(size_t)(bx + ty + i) * R + by + tx] = __float2half_rn(t[tx][ty + i]);
}

// V^T per head with split (bf16)
__global__ __launch_bounds__(256) void vtrans_split(
    const float* __restrict__ v, bf16* __restrict__ oh, bf16* __restrict__ ol)
{
    __shared__ float t[32][33];
    int bh = blockIdx.z;
    int b = bh >> 4, h = bh & 15;
    const float* in = v + (size_t)b * Ss * Dd + h * DHd;
    size_t obase = (size_t)bh * DHd * Ss;
    int s0 = blockIdx.x * 32, n0 = blockIdx.y * 32;
    int tx = threadIdx.x, ty = threadIdx.y;
#pragma unroll
    for (int i = 0; i < 32; i += 8)
        t[ty + i][tx] = in[(size_t)(s0 + ty + i) * Dd + n0 + tx];
    __syncthreads();
#pragma unroll
    for (int i = 0; i < 32; i += 8) {
        float val = t[tx][ty + i];
        size_t o = obase + (size_t)(n0 + ty + i) * Ss + s0 + tx;
        bf16 hh = __float2bfloat16_rn(val);
        oh[o] = hh;
        ol[o] = __float2bfloat16_rn(val - __bfloat162float(hh));
    }
}

// ================= LayerNorm =================
__global__ __launch_bounds__(256) void ln_kernel(
    const float* __restrict__ x, const float* __restrict__ x2,
    const float* __restrict__ g, const float* __restrict__ bta,
    float* __restrict__ outf, bf16* __restrict__ outh, bf16* __restrict__ outl,
    __half* __restrict__ o16h, __half* __restrict__ o16l)
{
    __shared__ float red[256];
    int row = blockIdx.x, tid = threadIdx.x;
    size_t base = (size_t)row * Dd;
    float r[8];
    float s = 0.f;
#pragma unroll
    for (int t = 0; t < 8; t++) {
        int i = tid + t * 256;
        float v = x[base + i];
        if (x2) v += x2[base + i];
        r[t] = v; s += v;
    }
    red[tid] = s; __syncthreads();
    for (int o = 128; o > 0; o >>= 1) { if (tid < o) red[tid] += red[tid + o]; __syncthreads(); }
    float mean = red[0] * (1.0f / Dd);
    __syncthreads();
    float vs = 0.f;
#pragma unroll
    for (int t = 0; t < 8; t++) { float d = r[t] - mean; vs += d * d; }
    red[tid] = vs; __syncthreads();
    for (int o = 128; o > 0; o >>= 1) { if (tid < o) red[tid] += red[tid + o]; __syncthreads(); }
    float var = red[0] * (1.0f / Dd);
    float rs = rsqrtf(var + 1e-5f);
#pragma unroll
    for (int t = 0; t < 8; t++) {
        int i = tid + t * 256;
        float v = (r[t] - mean) * rs * g[i] + bta[i];
        if (outf) outf[base + i] = v;
        if (outh) {
            bf16 h = __float2bfloat16_rn(v);
            outh[base + i] = h;
            outl[base + i] = __float2bfloat16_rn(v - __bfloat162float(h));
        }
        if (o16h) {
            __half h = __float2half_rn(v);
            o16h[base + i] = h;
            o16l[base + i] = __float2half_rn(v - __half2float(h));
        }
    }
}

// ================= mixed-precision mma.sync GEMM =================
// MODE 0: bf16x3 (A hi/lo, B hi/lo, 3 MMAs). MODE 1: fp16x2 (A hi/lo, B single, 2 MMAs)
// flags: 1=bias 2=gelu 4=resid 8=qkv(rope+scatter) 16=score 32=ctx 64=bf16 hi/lo out 256=fp16 hi/lo out
#define PPA 10240u            // A part bytes (128 rows * 80B)

template<int BN, int MODE>
__global__ __launch_bounds__(256) void gemm_mp(
    const void* __restrict__ Ahv, const void* __restrict__ Alv,
    const void* __restrict__ Bhv, const void* __restrict__ Blv,
    const float* __restrict__ bias, const float* __restrict__ resid,
    float* __restrict__ Cf, void* __restrict__ Chv, void* __restrict__ Clv,
    const int* __restrict__ pid,
    int K, int lda, int ldb, int ldc, int flags)
{
    constexpr uint32_t PPB = (uint32_t)BN * 80u;
    constexpr uint32_t STG = 2u * PPA + (MODE == 0 ? 2u : 1u) * PPB;
    constexpr int NFR = BN / 32;
    extern __shared__ char sm[];
    int bx = blockIdx.x, by = blockIdx.y, bz = blockIdx.z;
    const uint16_t* Ahp = (const uint16_t*)Ahv;
    const uint16_t* Alp = (const uint16_t*)Alv;
    const uint16_t* Bhp = (const uint16_t*)Bhv;
    const uint16_t* Blp = (const uint16_t*)Blv;
    float* Cfp = Cf;
    uint16_t* Chp = (uint16_t*)Chv;
    uint16_t* Clp = (uint16_t*)Clv;
    int Keff = K;
    if (flags & 16) {
        if (bx * BN > by * 128 + 127) return;
        int b = bz >> 4, h = bz & 15;
        size_t ao = (size_t)b * Ss * Dd + h * DHd;
        Ahp += ao; Alp += ao; Bhp += ao; Blp += ao;
        Cfp += (size_t)bz * Ss * Ss;
    }
    if (flags & 32) {
        by = gridDim.y - 1 - by;
        int b = bz >> 4, h = bz & 15;
        size_t ao = (size_t)bz * Ss * Ss;
        size_t bo = (size_t)bz * DHd * Ss;
        Ahp += ao; Alp += ao; Bhp += bo; Blp += bo;
        size_t co = (size_t)b * Ss * Dd + h * DHd;
        Chp += co; Clp += co;
        Keff = (by + 1) * 128;
    }
    const int tid = threadIdx.x, lane = tid & 31, warp = tid >> 5;
    const int m0 = by * 128, n0 = bx * BN;
    const int wm = (warp >> 2) * 64, wn = (warp & 3) * (BN / 4);
    const uint32_t sbase = smem_u32(sm);

    float acc[4][NFR][4];
#pragma unroll
    for (int i = 0; i < 4; i++)
#pragma unroll
        for (int j = 0; j < NFR; j++)
#pragma unroll
            for (int e = 0; e < 4; e++) acc[i][j][e] = 0.f;

#define ISSUE_CHUNK(ST, K0) do { \
    uint32_t sb0 = sbase + (uint32_t)(ST) * STG; \
    _Pragma("unroll") \
    for (int i = 0; i < 2; i++) { \
        int idx = tid + i * 256; \
        int r = idx >> 2; int cc = idx & 3; \
        uint32_t d = sb0 + (uint32_t)r * 80u + (uint32_t)cc * 16u; \
        size_t sa = (size_t)(m0 + r) * lda + (K0) + cc * 8; \
        cp16(d,       Ahp + sa); \
        cp16(d + PPA, Alp + sa); \
    } \
    _Pragma("unroll") \
    for (int i = 0; i < BN / 64; i++) { \
        int idx = tid + i * 256; \
        int r = idx >> 2; int cc = idx & 3; \
        uint32_t d = sb0 + 2u * PPA + (uint32_t)r * 80u + (uint32_t)cc * 16u; \
        size_t sb2 = (size_t)(n0 + r) * ldb + (K0) + cc * 8; \
        cp16(d, Bhp + sb2); \
        if (MODE == 0) cp16(d + PPB, Blp + sb2); \
    } \
    cp_commit(); \
} while(0)

    const int nch = Keff / 32;
    ISSUE_CHUNK(0, 0);
    if (nch > 1) ISSUE_CHUNK(1, 32);

    const uint32_t a_lane_off = (uint32_t)(wm + (lane & 15)) * 80u + (uint32_t)((lane >> 4) * 16);
    const uint32_t b_lane_off = (uint32_t)(wn + (lane & 7)) * 80u + (uint32_t)(((lane >> 3) & 1) * 16);

    for (int c = 0; c < nch; c++) {
        if (c + 1 < nch) cp_wait1(); else cp_wait0();
        __syncthreads();
        const uint32_t boff = (uint32_t)(c % 3) * STG;
#pragma unroll
        for (int ks = 0; ks < 2; ks++) {
            uint32_t ahi[4][4], alo[4][4];
            uint32_t abase = sbase + boff + a_lane_off + (uint32_t)(ks * 32);
            uint32_t bbase = sbase + boff + 2u * PPA + b_lane_off + (uint32_t)(ks * 32);
#pragma unroll
            for (int mti = 0; mti < 4; mti++) {
                ldm4(ahi[mti], abase + (uint32_t)(mti * 16) * 80u);
                ldm4(alo[mti], abase + (uint32_t)(mti * 16) * 80u + PPA);
            }
#pragma unroll
            for (int ntj = 0; ntj < NFR; ntj++) {
                if (MODE == 0) {
                    uint32_t bhi[2], blo[2];
                    ldm2(bhi, bbase + (uint32_t)(ntj * 8) * 80u);
                    ldm2(blo, bbase + (uint32_t)(ntj * 8) * 80u + PPB);
#pragma unroll
                    for (int mti = 0; mti < 4; mti++) {
                        mma_bf16(acc[mti][ntj], ahi[mti], bhi);
                        mma_bf16(acc[mti][ntj], ahi[mti], blo);
                        mma_bf16(acc[mti][ntj], alo[mti], bhi);
                    }
                } else {
                    uint32_t bh[2];
                    ldm2(bh, bbase + (uint32_t)(ntj * 8) * 80u);
#pragma unroll
                    for (int mti = 0; mti < 4; mti++) {
                        mma_fp16(acc[mti][ntj], ahi[mti], bh);
                        mma_fp16(acc[mti][ntj], alo[mti], bh);
                    }
                }
            }
        }
        if (c + 2 < nch) ISSUE_CHUNK((c + 2) % 3, (c + 2) * 32);
    }
#undef ISSUE_CHUNK

    // ---------------- epilogue ----------------
#pragma unroll
    for (int mti = 0; mti < 4; mti++) {
#pragma unroll
        for (int ntj = 0; ntj < NFR; ntj++) {
            int row = m0 + wm + mti * 16 + (lane >> 2);
            int col = n0 + wn + ntj * 8 + (lane & 3) * 2;
#pragma unroll
            for (int half = 0; half < 2; half++) {
                int rr = row + half * 8;
                float v0 = acc[mti][ntj][half * 2];
                float v1 = acc[mti][ntj][half * 2 + 1];
                if (flags & 1) { v0 += bias[col]; v1 += bias[col + 1]; }
                if (flags & 2) {
                    v0 = 0.5f * v0 * (1.0f + erff(v0 * 0.70710678118654752f));
                    v1 = 0.5f * v1 * (1.0f + erff(v1 * 0.70710678118654752f));
                }
                if (flags & 4) {
                    const float* rp = resid + (size_t)rr * ldc + col;
                    v0 += rp[0]; v1 += rp[1];
                }
                if (flags & 8) {
                    int sel = col >> 11, cl = col & 2047;
                    if (sel == 2) {
                        *(float2*)(Cfp + (size_t)rr * Dd + cl) = make_float2(v0, v1);
                    } else {
                        int b = rr >> 11, s = rr & 2047;
                        int pos = pid[b * Ss + s];
                        int i = (cl & 127) >> 1;
                        float sn = g_sin[pos * 64 + i], cs = g_cos[pos * 64 + i];
                        float r0 = v0 * cs - v1 * sn;
                        float r1 = v1 * cs + v0 * sn;
                        size_t o = (size_t)(sel * ROWS + rr) * Dd + cl;
                        split2(r0, r1, (bf16*)(Chp + o), (bf16*)(Clp + o));
                    }
                } else if (flags & 64) {
                    size_t o = (size_t)rr * ldc + col;
                    split2(v0, v1, (bf16*)(Chp + o), (bf16*)(Clp + o));
                } else if (flags & 256) {
                    size_t o = (size_t)rr * ldc + col;
                    split2h(v0, v1, (__half*)(Chp + o), (__half*)(Clp + o));
                } else {
                    *(float2*)(Cfp + (size_t)rr * ldc + col) = make_float2(v0, v1);
                }
            }
        }
    }
}

// ================= row softmax (causal trunc) + bf16 split out =================
__global__ __launch_bounds__(256) void softmax_kernel(
    float* __restrict__ attn, bf16* __restrict__ ah, bf16* __restrict__ al)
{
    int rid = blockIdx.x;
    int qpos = rid & (Ss - 1);
    int L = qpos + 1;
    float* row = attn + (size_t)rid * Ss;
    bf16* rh = ah + (size_t)rid * Ss;
    bf16* rl = al + (size_t)rid * Ss;
    __shared__ float red[256];
    int tid = threadIdx.x;
    float r[8];
    float mx = -3.4e38f;
#pragma unroll
    for (int t = 0; t < 8; t++) {
        int i = tid + t * 256;
        float v = (i < L) ? row[i] : -3.4e38f;
        r[t] = v; mx = fmaxf(mx, v);
    }
    red[tid] = mx; __syncthreads();
    for (int o = 128; o > 0; o >>= 1) { if (tid < o) red[tid] = fmaxf(red[tid], red[tid + o]); __syncthreads(); }
    mx = red[0]; __syncthreads();
    float s = 0.f;
#pragma unroll
    for (int t = 0; t < 8; t++) {
        int i = tid + t * 256;
        float e = (i < L) ? expf(r[t] - mx) : 0.0f;
        r[t] = e; s += e;
    }
    red[tid] = s; __syncthreads();
    for (int o = 128; o > 0; o >>= 1) { if (tid < o) red[tid] += red[tid + o]; __syncthreads(); }
    float inv = 1.0f / red[0];
#pragma unroll
    for (int t = 0; t < 8; t++) {
        int i = tid + t * 256;
        float v = r[t] * inv;
        row[i] = v;
        bf16 h = __float2bfloat16_rn(v);
        rh[i] = h;
        rl[i] = __float2bfloat16_rn(v - __bfloat162float(h));
    }
}

// ================= launch =================
extern "C" void kernel_launch(void* const* d_in, const int* in_sizes, int n_in,
                              void* d_out, int out_size)
{
    const float* hs   = (const float*)d_in[0];
    const int*   pid  = (const int*)  d_in[1];
    const float* wq   = (const float*)d_in[2];
    const float* wk   = (const float*)d_in[3];
    const float* wv   = (const float*)d_in[4];
    const float* wo   = (const float*)d_in[5];
    const float* ln1g = (const float*)d_in[6];
    const float* ln1b = (const float*)d_in[7];
    const float* ln2g = (const float*)d_in[8];
    const float* ln2b = (const float*)d_in[9];
    const float* fiw  = (const float*)d_in[10];
    const float* fib  = (const float*)d_in[11];
    const float* fow  = (const float*)d_in[12];
    const float* fob  = (const float*)d_in[13];

    float* out  = (float*)d_out;
    float* attn = out + (size_t)ROWS * Dd;

    float *v, *aproj, *h2;
    bf16 *h1h, *h1l, *wqkvh, *wqkvl, *qkh, *qkl, *vth, *vtl, *ah, *al;
    __half *wof, *fif, *fof, *ctxh16, *ctxl16, *h2h16, *h2l16, *ffnh16, *ffnl16;
    cudaGetSymbolAddress((void**)&v,      g_v);
    cudaGetSymbolAddress((void**)&aproj,  g_aproj);
    cudaGetSymbolAddress((void**)&h2,     g_h2);
    cudaGetSymbolAddress((void**)&h1h,    g_h1h);
    cudaGetSymbolAddress((void**)&h1l,    g_h1l);
    cudaGetSymbolAddress((void**)&wqkvh,  g_wqkvh);
    cudaGetSymbolAddress((void**)&wqkvl,  g_wqkvl);
    cudaGetSymbolAddress((void**)&wof,    g_wof16);
    cudaGetSymbolAddress((void**)&fif,    g_fif16);
    cudaGetSymbolAddress((void**)&fof,    g_fof16);
    cudaGetSymbolAddress((void**)&qkh,    g_qkh);
    cudaGetSymbolAddress((void**)&qkl,    g_qkl);
    cudaGetSymbolAddress((void**)&vth,    g_vth);
    cudaGetSymbolAddress((void**)&vtl,    g_vtl);
    cudaGetSymbolAddress((void**)&ah,     g_ah);
    cudaGetSymbolAddress((void**)&al,     g_al);
    cudaGetSymbolAddress((void**)&ctxh16, g_ctxh16);
    cudaGetSymbolAddress((void**)&ctxl16, g_ctxl16);
    cudaGetSymbolAddress((void**)&h2h16,  g_h2h16);
    cudaGetSymbolAddress((void**)&h2l16,  g_h2l16);
    cudaGetSymbolAddress((void**)&ffnh16, g_ffnh16);
    cudaGetSymbolAddress((void**)&ffnl16, g_ffnl16);

    const uint32_t SMT256_0 = 3u * (2u * PPA + 2u * 256u * 80u);   // 184320
    const uint32_t SMT128_0 = 3u * (2u * PPA + 2u * 128u * 80u);   // 122880
    const uint32_t SMT256_1 = 3u * (2u * PPA + 1u * 256u * 80u);   // 122880
    cudaFuncSetAttribute(gemm_mp<256, 0>, cudaFuncAttributeMaxDynamicSharedMemorySize, SMT256_0);
    cudaFuncSetAttribute(gemm_mp<128, 0>, cudaFuncAttributeMaxDynamicSharedMemorySize, SMT128_0);
    cudaFuncSetAttribute(gemm_mp<256, 1>, cudaFuncAttributeMaxDynamicSharedMemorySize, SMT256_1);

    rope_table_kernel<<<512, 256>>>();

    dim3 tb(32, 8);
    transpose_split<<<dim3(Dd / 32, Dd / 32), tb>>>(wq, wqkvh, wqkvl, Dd, Dd);
    transpose_split<<<dim3(Dd / 32, Dd / 32), tb>>>(wk, wqkvh + (size_t)Dd * Dd, wqkvl + (size_t)Dd * Dd, Dd, Dd);
    transpose_split<<<dim3(Dd / 32, Dd / 32), tb>>>(wv, wqkvh + (size_t)2 * Dd * Dd, wqkvl + (size_t)2 * Dd * Dd, Dd, Dd);
    transpose_fp16<<<dim3(Dd / 32, Dd / 32), tb>>>(wo, wof, Dd, Dd);
    transpose_fp16<<<dim3(FFf / 32, Dd / 32), tb>>>(fiw, fif, Dd, FFf);
    transpose_fp16<<<dim3(Dd / 32, FFf / 32), tb>>>(fow, fof, FFf, Dd);

    ln_kernel<<<ROWS, 256>>>(hs, nullptr, ln1g, ln1b, nullptr, h1h, h1l, nullptr, nullptr);

    // fused QKV projection (bf16x3, RoPE in epilogue)
    gemm_mp<256, 0><<<dim3(24, 32), 256, SMT256_0>>>(h1h, h1l, wqkvh, wqkvl,
        nullptr, nullptr, v, qkh, qkl, pid, Dd, Dd, Dd, Dd, 8);

    vtrans_split<<<dim3(Ss / 32, DHd / 32, Bb * Hh), tb>>>(v, vth, vtl);

    // scores (bf16x3, causal) -> softmax(+split) -> ctx (bf16x3, fp16 out)
    gemm_mp<256, 0><<<dim3(8, 16, Bb * Hh), 256, SMT256_0>>>(qkh, qkl,
        qkh + (size_t)ROWS * Dd, qkl + (size_t)ROWS * Dd,
        nullptr, nullptr, attn, nullptr, nullptr, nullptr, DHd, Dd, Dd, Ss, 16);
    softmax_kernel<<<Bb * Hh * Ss, 256>>>(attn, ah, al);
    gemm_mp<128, 0><<<dim3(1, 16, Bb * Hh), 256, SMT128_0>>>(ah, al, vth, vtl,
        nullptr, nullptr, nullptr, ctxh16, ctxl16, nullptr, Ss, Ss, Ss, Dd, 32 | 256);

    // output projection (fp16x2)
    gemm_mp<256, 1><<<dim3(8, 32), 256, SMT256_1>>>(ctxh16, ctxl16, wof, nullptr,
        nullptr, nullptr, aproj, nullptr, nullptr, nullptr, Dd, Dd, Dd, Dd, 0);

    ln_kernel<<<ROWS, 256>>>(hs, aproj, ln2g, ln2b, h2, nullptr, nullptr, h2h16, h2l16);

    // FFN (fp16x2)
    gemm_mp<256, 1><<<dim3(32, 32), 256, SMT256_1>>>(h2h16, h2l16, fif, nullptr,
        fib, nullptr, nullptr, ffnh16, ffnl16, nullptr, Dd, Dd, Dd, FFf, 1 | 2 | 256);
    gemm_mp<256, 1><<<dim3(8, 32), 256, SMT256_1>>>(ffnh16, ffnl16, fof, nullptr,
        fob, h2, out, nullptr, nullptr, nullptr, FFf, FFf, FFf, Dd, 1 | 4);
}

// round 9
// speedup vs baseline: 1.3911x; 1.0331x over previous
#include <cuda_runtime.h>
#include <cuda_bf16.h>
#include <cuda_fp16.h>
#include <math.h>
#include <stdint.h>

#define Bb   2
#define Ss   2048
#define Dd   2048
#define Hh   16
#define DHd  128
#define FFf  8192
#define ROWS 4096   // B*S

typedef __nv_bfloat16 bf16;

// ================= scratch (device globals) =================
__device__ bf16  g_h1h[(size_t)ROWS * Dd],  g_h1l[(size_t)ROWS * Dd];
__device__ bf16  g_wqkvh[(size_t)3 * Dd * Dd], g_wqkvl[(size_t)3 * Dd * Dd];
__device__ __half g_wof16[(size_t)Dd * Dd];
__device__ __half g_fif16[(size_t)Dd * FFf];
__device__ __half g_fof16[(size_t)Dd * FFf];
__device__ bf16  g_qkh[(size_t)2 * ROWS * Dd], g_qkl[(size_t)2 * ROWS * Dd];
__device__ float g_v[(size_t)ROWS * Dd];
__device__ __half g_vt16[(size_t)Bb * Hh * DHd * Ss];
__device__ __half g_ah16[(size_t)Bb * Hh * Ss * Ss], g_al16[(size_t)Bb * Hh * Ss * Ss];
__device__ __half g_ctxh16[(size_t)ROWS * Dd], g_ctxl16[(size_t)ROWS * Dd];
__device__ float g_aproj[(size_t)ROWS * Dd];
__device__ float g_h2[(size_t)ROWS * Dd];
__device__ __half g_h2h16[(size_t)ROWS * Dd], g_h2l16[(size_t)ROWS * Dd];
__device__ __half g_ffnh16[(size_t)ROWS * FFf], g_ffnl16[(size_t)ROWS * FFf];
__device__ float g_sin[Ss * 64];
__device__ float g_cos[Ss * 64];

// ================= helpers =================
__device__ __forceinline__ uint32_t smem_u32(const void* p) {
    uint32_t a;
    asm("{ .reg .u64 t; cvta.to.shared.u64 t, %1; cvt.u32.u64 %0, t; }" : "=r"(a) : "l"(p));
    return a;
}
__device__ __forceinline__ void ldm4(uint32_t* r, uint32_t addr) {
    asm volatile("ldmatrix.sync.aligned.m8n8.x4.shared.b16 {%0,%1,%2,%3}, [%4];"
        : "=r"(r[0]), "=r"(r[1]), "=r"(r[2]), "=r"(r[3]) : "r"(addr));
}
__device__ __forceinline__ void ldm2(uint32_t* r, uint32_t addr) {
    asm volatile("ldmatrix.sync.aligned.m8n8.x2.shared.b16 {%0,%1}, [%2];"
        : "=r"(r[0]), "=r"(r[1]) : "r"(addr));
}
__device__ __forceinline__ void mma_bf16(float* c, const uint32_t* a, const uint32_t* b) {
    asm volatile(
        "mma.sync.aligned.m16n8k16.row.col.f32.bf16.bf16.f32 "
        "{%0,%1,%2,%3}, {%4,%5,%6,%7}, {%8,%9}, {%0,%1,%2,%3};"
        : "+f"(c[0]), "+f"(c[1]), "+f"(c[2]), "+f"(c[3])
        : "r"(a[0]), "r"(a[1]), "r"(a[2]), "r"(a[3]), "r"(b[0]), "r"(b[1]));
}
__device__ __forceinline__ void mma_fp16(float* c, const uint32_t* a, const uint32_t* b) {
    asm volatile(
        "mma.sync.aligned.m16n8k16.row.col.f32.f16.f16.f32 "
        "{%0,%1,%2,%3}, {%4,%5,%6,%7}, {%8,%9}, {%0,%1,%2,%3};"
        : "+f"(c[0]), "+f"(c[1]), "+f"(c[2]), "+f"(c[3])
        : "r"(a[0]), "r"(a[1]), "r"(a[2]), "r"(a[3]), "r"(b[0]), "r"(b[1]));
}
__device__ __forceinline__ void cp16(uint32_t dst, const void* src) {
    asm volatile("cp.async.cg.shared.global [%0], [%1], 16;" :: "r"(dst), "l"(src));
}
__device__ __forceinline__ void cp_commit() { asm volatile("cp.async.commit_group;"); }
__device__ __forceinline__ void cp_wait1() { asm volatile("cp.async.wait_group 1;"); }
__device__ __forceinline__ void cp_wait0() { asm volatile("cp.async.wait_group 0;"); }

__device__ __forceinline__ void split2(float x, float y, bf16* ph, bf16* pl) {
    bf16 hx = __float2bfloat16_rn(x), hy = __float2bfloat16_rn(y);
    float fx = __bfloat162float(hx), fy = __bfloat162float(hy);
    __nv_bfloat162 h2; h2.x = hx; h2.y = hy;
    __nv_bfloat162 l2; l2.x = __float2bfloat16_rn(x - fx); l2.y = __float2bfloat16_rn(y - fy);
    *(__nv_bfloat162*)ph = h2;
    *(__nv_bfloat162*)pl = l2;
}
__device__ __forceinline__ void split2h(float x, float y, __half* ph, __half* pl) {
    __half hx = __float2half_rn(x), hy = __float2half_rn(y);
    __half2 h2 = __halves2half2(hx, hy);
    __half2 l2 = __floats2half2_rn(x - __half2float(hx), y - __half2float(hy));
    *(__half2*)ph = h2;
    *(__half2*)pl = l2;
}

// ================= RoPE tables =================
__global__ void rope_table_kernel() {
    int t = blockIdx.x * 256 + threadIdx.x;
    if (t >= Ss * 64) return;
    int p = t >> 6, i = t & 63;
    double inv = pow(10000.0, -((double)(2 * i)) / 128.0);
    float ang = (float)p * (float)inv;
    g_sin[t] = (float)sin((double)ang);
    g_cos[t] = (float)cos((double)ang);
}

// ================= weight transpose variants (vectorized stores) =================
// input tile: rows by..by+63, cols bx..bx+31. output tile: rows bx..bx+31, cols by..by+63.
__global__ __launch_bounds__(256) void transpose_split(
    const float* __restrict__ in, bf16* __restrict__ oh, bf16* __restrict__ ol,
    int R, int Cc)
{
    __shared__ float t[64][33];
    int bx = blockIdx.x * 32, by = blockIdx.y * 64;
    int tx = threadIdx.x, ty = threadIdx.y;  // (32,8)
#pragma unroll
    for (int i = 0; i < 64; i += 8)
        t[ty + i][tx] = in[(size_t)(by + ty + i) * Cc + bx + tx];
    __syncthreads();
#pragma unroll
    for (int i = 0; i < 32; i += 8) {
        int r = ty + i;
        float v0 = t[2 * tx][r], v1 = t[2 * tx + 1][r];
        size_t o = (size_t)(bx + r) * R + by + 2 * tx;
        split2(v0, v1, oh + o, ol + o);
    }
}

__global__ __launch_bounds__(256) void transpose_fp16(
    const float* __restrict__ in, __half* __restrict__ oh, int R, int Cc)
{
    __shared__ float t[64][33];
    int bx = blockIdx.x * 32, by = blockIdx.y * 64;
    int tx = threadIdx.x, ty = threadIdx.y;
#pragma unroll
    for (int i = 0; i < 64; i += 8)
        t[ty + i][tx] = in[(size_t)(by + ty + i) * Cc + bx + tx];
    __syncthreads();
#pragma unroll
    for (int i = 0; i < 32; i += 8) {
        int r = ty + i;
        __half2 h2 = __floats2half2_rn(t[2 * tx][r], t[2 * tx + 1][r]);
        *(__half2*)(oh + (size_t)(bx + r) * R + by + 2 * tx) = h2;
    }
}

// V^T per head, single fp16: vt[bh][n][s] = v[b][s][h*128+n]
__global__ __launch_bounds__(256) void vtrans_fp16(
    const float* __restrict__ v, __half* __restrict__ oh)
{
    __shared__ float t[64][33];
    int bh = blockIdx.z;
    int b = bh >> 4, h = bh & 15;
    const float* in = v + (size_t)b * Ss * Dd + h * DHd;
    size_t obase = (size_t)bh * DHd * Ss;
    int n0 = blockIdx.x * 32, s0 = blockIdx.y * 64;
    int tx = threadIdx.x, ty = threadIdx.y;
#pragma unroll
    for (int i = 0; i < 64; i += 8)
        t[ty + i][tx] = in[(size_t)(s0 + ty + i) * Dd + n0 + tx];
    __syncthreads();
#pragma unroll
    for (int i = 0; i < 32; i += 8) {
        int r = ty + i;
        __half2 h2 = __floats2half2_rn(t[2 * tx][r], t[2 * tx + 1][r]);
        *(__half2*)(oh + obase + (size_t)(n0 + r) * Ss + s0 + 2 * tx) = h2;
    }
}

// ================= LayerNorm =================
__global__ __launch_bounds__(256) void ln_kernel(
    const float* __restrict__ x, const float* __restrict__ x2,
    const float* __restrict__ g, const float* __restrict__ bta,
    float* __restrict__ outf, bf16* __restrict__ outh, bf16* __restrict__ outl,
    __half* __restrict__ o16h, __half* __restrict__ o16l)
{
    __shared__ float red[256];
    int row = blockIdx.x, tid = threadIdx.x;
    size_t base = (size_t)row * Dd;
    float r[8];
    float s = 0.f;
#pragma unroll
    for (int t = 0; t < 8; t++) {
        int i = tid + t * 256;
        float v = x[base + i];
        if (x2) v += x2[base + i];
        r[t] = v; s += v;
    }
    red[tid] = s; __syncthreads();
    for (int o = 128; o > 0; o >>= 1) { if (tid < o) red[tid] += red[tid + o]; __syncthreads(); }
    float mean = red[0] * (1.0f / Dd);
    __syncthreads();
    float vs = 0.f;
#pragma unroll
    for (int t = 0; t < 8; t++) { float d = r[t] - mean; vs += d * d; }
    red[tid] = vs; __syncthreads();
    for (int o = 128; o > 0; o >>= 1) { if (tid < o) red[tid] += red[tid + o]; __syncthreads(); }
    float var = red[0] * (1.0f / Dd);
    float rs = rsqrtf(var + 1e-5f);
#pragma unroll
    for (int t = 0; t < 8; t++) {
        int i = tid + t * 256;
        float v = (r[t] - mean) * rs * g[i] + bta[i];
        if (outf) outf[base + i] = v;
        if (outh) {
            bf16 h = __float2bfloat16_rn(v);
            outh[base + i] = h;
            outl[base + i] = __float2bfloat16_rn(v - __bfloat162float(h));
        }
        if (o16h) {
            __half h = __float2half_rn(v);
            o16h[base + i] = h;
            o16l[base + i] = __float2half_rn(v - __half2float(h));
        }
    }
}

// ================= mixed-precision mma.sync GEMM =================
// MODE 0: bf16x3 (A hi/lo, B hi/lo, 3 MMAs). MODE 1: fp16x2 (A hi/lo, B single, 2 MMAs)
// flags: 1=bias 2=gelu 4=resid 8=qkv(rope+scatter) 16=score 32=ctx 64=bf16 hi/lo out 256=fp16 hi/lo out
#define PPA 10240u            // A part bytes (128 rows * 80B)

template<int BN, int MODE>
__global__ __launch_bounds__(256) void gemm_mp(
    const void* __restrict__ Ahv, const void* __restrict__ Alv,
    const void* __restrict__ Bhv, const void* __restrict__ Blv,
    const float* __restrict__ bias, const float* __restrict__ resid,
    float* __restrict__ Cf, void* __restrict__ Chv, void* __restrict__ Clv,
    const int* __restrict__ pid,
    int K, int lda, int ldb, int ldc, int flags)
{
    constexpr uint32_t PPB = (uint32_t)BN * 80u;
    constexpr uint32_t STG = 2u * PPA + (MODE == 0 ? 2u : 1u) * PPB;
    constexpr int NFR = BN / 32;
    extern __shared__ char sm[];
    int bx = blockIdx.x, by = blockIdx.y, bz = blockIdx.z;
    const uint16_t* Ahp = (const uint16_t*)Ahv;
    const uint16_t* Alp = (const uint16_t*)Alv;
    const uint16_t* Bhp = (const uint16_t*)Bhv;
    const uint16_t* Blp = (const uint16_t*)Blv;
    float* Cfp = Cf;
    uint16_t* Chp = (uint16_t*)Chv;
    uint16_t* Clp = (uint16_t*)Clv;
    int Keff = K;
    if (flags & 16) {
        if (bx * BN > by * 128 + 127) return;
        int b = bz >> 4, h = bz & 15;
        size_t ao = (size_t)b * Ss * Dd + h * DHd;
        Ahp += ao; Alp += ao; Bhp += ao; Blp += ao;
        Cfp += (size_t)bz * Ss * Ss;
    }
    if (flags & 32) {
        by = gridDim.y - 1 - by;
        int b = bz >> 4, h = bz & 15;
        size_t ao = (size_t)bz * Ss * Ss;
        size_t bo = (size_t)bz * DHd * Ss;
        Ahp += ao; Alp += ao; Bhp += bo; Blp += bo;
        size_t co = (size_t)b * Ss * Dd + h * DHd;
        Chp += co; Clp += co;
        Keff = (by + 1) * 128;
    }
    const int tid = threadIdx.x, lane = tid & 31, warp = tid >> 5;
    const int m0 = by * 128, n0 = bx * BN;
    const int wm = (warp >> 2) * 64, wn = (warp & 3) * (BN / 4);
    const uint32_t sbase = smem_u32(sm);

    float acc[4][NFR][4];
#pragma unroll
    for (int i = 0; i < 4; i++)
#pragma unroll
        for (int j = 0; j < NFR; j++)
#pragma unroll
            for (int e = 0; e < 4; e++) acc[i][j][e] = 0.f;

#define ISSUE_CHUNK(ST, K0) do { \
    uint32_t sb0 = sbase + (uint32_t)(ST) * STG; \
    _Pragma("unroll") \
    for (int i = 0; i < 2; i++) { \
        int idx = tid + i * 256; \
        int r = idx >> 2; int cc = idx & 3; \
        uint32_t d = sb0 + (uint32_t)r * 80u + (uint32_t)cc * 16u; \
        size_t sa = (size_t)(m0 + r) * lda + (K0) + cc * 8; \
        cp16(d,       Ahp + sa); \
        cp16(d + PPA, Alp + sa); \
    } \
    _Pragma("unroll") \
    for (int i = 0; i < BN / 64; i++) { \
        int idx = tid + i * 256; \
        int r = idx >> 2; int cc = idx & 3; \
        uint32_t d = sb0 + 2u * PPA + (uint32_t)r * 80u + (uint32_t)cc * 16u; \
        size_t sb2 = (size_t)(n0 + r) * ldb + (K0) + cc * 8; \
        cp16(d, Bhp + sb2); \
        if (MODE == 0) cp16(d + PPB, Blp + sb2); \
    } \
    cp_commit(); \
} while(0)

    const int nch = Keff / 32;
    ISSUE_CHUNK(0, 0);
    if (nch > 1) ISSUE_CHUNK(1, 32);

    const uint32_t a_lane_off = (uint32_t)(wm + (lane & 15)) * 80u + (uint32_t)((lane >> 4) * 16);
    const uint32_t b_lane_off = (uint32_t)(wn + (lane & 7)) * 80u + (uint32_t)(((lane >> 3) & 1) * 16);

    for (int c = 0; c < nch; c++) {
        if (c + 1 < nch) cp_wait1(); else cp_wait0();
        __syncthreads();
        const uint32_t boff = (uint32_t)(c % 3) * STG;
#pragma unroll
        for (int ks = 0; ks < 2; ks++) {
            uint32_t ahi[4][4], alo[4][4];
            uint32_t abase = sbase + boff + a_lane_off + (uint32_t)(ks * 32);
            uint32_t bbase = sbase + boff + 2u * PPA + b_lane_off + (uint32_t)(ks * 32);
#pragma unroll
            for (int mti = 0; mti < 4; mti++) {
                ldm4(ahi[mti], abase + (uint32_t)(mti * 16) * 80u);
                ldm4(alo[mti], abase + (uint32_t)(mti * 16) * 80u + PPA);
            }
#pragma unroll
            for (int ntj = 0; ntj < NFR; ntj++) {
                if (MODE == 0) {
                    uint32_t bhi[2], blo[2];
                    ldm2(bhi, bbase + (uint32_t)(ntj * 8) * 80u);
                    ldm2(blo, bbase + (uint32_t)(ntj * 8) * 80u + PPB);
#pragma unroll
                    for (int mti = 0; mti < 4; mti++) {
                        mma_bf16(acc[mti][ntj], ahi[mti], bhi);
                        mma_bf16(acc[mti][ntj], ahi[mti], blo);
                        mma_bf16(acc[mti][ntj], alo[mti], bhi);
                    }
                } else {
                    uint32_t bh[2];
                    ldm2(bh, bbase + (uint32_t)(ntj * 8) * 80u);
#pragma unroll
                    for (int mti = 0; mti < 4; mti++) {
                        mma_fp16(acc[mti][ntj], ahi[mti], bh);
                        mma_fp16(acc[mti][ntj], alo[mti], bh);
                    }
                }
            }
        }
        if (c + 2 < nch) ISSUE_CHUNK((c + 2) % 3, (c + 2) * 32);
    }
#undef ISSUE_CHUNK

    // ---------------- epilogue ----------------
#pragma unroll
    for (int mti = 0; mti < 4; mti++) {
#pragma unroll
        for (int ntj = 0; ntj < NFR; ntj++) {
            int row = m0 + wm + mti * 16 + (lane >> 2);
            int col = n0 + wn + ntj * 8 + (lane & 3) * 2;
#pragma unroll
            for (int half = 0; half < 2; half++) {
                int rr = row + half * 8;
                float v0 = acc[mti][ntj][half * 2];
                float v1 = acc[mti][ntj][half * 2 + 1];
                if (flags & 1) { v0 += bias[col]; v1 += bias[col + 1]; }
                if (flags & 2) {
                    v0 = 0.5f * v0 * (1.0f + erff(v0 * 0.70710678118654752f));
                    v1 = 0.5f * v1 * (1.0f + erff(v1 * 0.70710678118654752f));
                }
                if (flags & 4) {
                    const float* rp = resid + (size_t)rr * ldc + col;
                    v0 += rp[0]; v1 += rp[1];
                }
                if (flags & 8) {
                    int sel = col >> 11, cl = col & 2047;
                    if (sel == 2) {
                        *(float2*)(Cfp + (size_t)rr * Dd + cl) = make_float2(v0, v1);
                    } else {
                        int b = rr >> 11, s = rr & 2047;
                        int pos = pid[b * Ss + s];
                        int i = (cl & 127) >> 1;
                        float sn = g_sin[pos * 64 + i], cs = g_cos[pos * 64 + i];
                        float r0 = v0 * cs - v1 * sn;
                        float r1 = v1 * cs + v0 * sn;
                        size_t o = (size_t)(sel * ROWS + rr) * Dd + cl;
                        split2(r0, r1, (bf16*)(Chp + o), (bf16*)(Clp + o));
                    }
                } else if (flags & 64) {
                    size_t o = (size_t)rr * ldc + col;
                    split2(v0, v1, (bf16*)(Chp + o), (bf16*)(Clp + o));
                } else if (flags & 256) {
                    size_t o = (size_t)rr * ldc + col;
                    split2h(v0, v1, (__half*)(Chp + o), (__half*)(Clp + o));
                } else {
                    *(float2*)(Cfp + (size_t)rr * ldc + col) = make_float2(v0, v1);
                }
            }
        }
    }
}

// ================= row softmax (causal trunc) + fp16 split out =================
__global__ __launch_bounds__(256) void softmax_kernel(
    float* __restrict__ attn, __half* __restrict__ ah, __half* __restrict__ al)
{
    int rid = blockIdx.x;
    int qpos = rid & (Ss - 1);
    int L = qpos + 1;
    int Lpad = ((qpos >> 7) + 1) << 7;       // roundup(L,128): fp16 region read by ctx
    float* row = attn + (size_t)rid * Ss;
    __half* rh = ah + (size_t)rid * Ss;
    __half* rl = al + (size_t)rid * Ss;
    __shared__ float red[256];
    int tid = threadIdx.x;
    float r[8];
    float mx = -3.4e38f;
#pragma unroll
    for (int t = 0; t < 8; t++) {
        int i = tid + t * 256;
        float v = (i < L) ? row[i] : -3.4e38f;
        r[t] = v; mx = fmaxf(mx, v);
    }
    red[tid] = mx; __syncthreads();
    for (int o = 128; o > 0; o >>= 1) { if (tid < o) red[tid] = fmaxf(red[tid], red[tid + o]); __syncthreads(); }
    mx = red[0]; __syncthreads();
    float s = 0.f;
#pragma unroll
    for (int t = 0; t < 8; t++) {
        int i = tid + t * 256;
        float e = (i < L) ? expf(r[t] - mx) : 0.0f;
        r[t] = e; s += e;
    }
    red[tid] = s; __syncthreads();
    for (int o = 128; o > 0; o >>= 1) { if (tid < o) red[tid] += red[tid + o]; __syncthreads(); }
    float inv = 1.0f / red[0];
#pragma unroll
    for (int t = 0; t < 8; t++) {
        int i = tid + t * 256;
        float v = r[t] * inv;
        row[i] = v;                          // fp32 graded output: full row (zeros above diag)
        if (i < Lpad) {                      // fp16 split: only the region ctx reads
            __half h = __float2half_rn(v);
            rh[i] = h;
            rl[i] = __float2half_rn(v - __half2float(h));
        }
    }
}

// ================= launch =================
extern "C" void kernel_launch(void* const* d_in, const int* in_sizes, int n_in,
                              void* d_out, int out_size)
{
    const float* hs   = (const float*)d_in[0];
    const int*   pid  = (const int*)  d_in[1];
    const float* wq   = (const float*)d_in[2];
    const float* wk   = (const float*)d_in[3];
    const float* wv   = (const float*)d_in[4];
    const float* wo   = (const float*)d_in[5];
    const float* ln1g = (const float*)d_in[6];
    const float* ln1b = (const float*)d_in[7];
    const float* ln2g = (const float*)d_in[8];
    const float* ln2b = (const float*)d_in[9];
    const float* fiw  = (const float*)d_in[10];
    const float* fib  = (const float*)d_in[11];
    const float* fow  = (const float*)d_in[12];
    const float* fob  = (const float*)d_in[13];

    float* out  = (float*)d_out;
    float* attn = out + (size_t)ROWS * Dd;

    float *v, *aproj, *h2;
    bf16 *h1h, *h1l, *wqkvh, *wqkvl, *qkh, *qkl;
    __half *wof, *fif, *fof, *vt16, *ah16, *al16;
    __half *ctxh16, *ctxl16, *h2h16, *h2l16, *ffnh16, *ffnl16;
    cudaGetSymbolAddress((void**)&v,      g_v);
    cudaGetSymbolAddress((void**)&aproj,  g_aproj);
    cudaGetSymbolAddress((void**)&h2,     g_h2);
    cudaGetSymbolAddress((void**)&h1h,    g_h1h);
    cudaGetSymbolAddress((void**)&h1l,    g_h1l);
    cudaGetSymbolAddress((void**)&wqkvh,  g_wqkvh);
    cudaGetSymbolAddress((void**)&wqkvl,  g_wqkvl);
    cudaGetSymbolAddress((void**)&wof,    g_wof16);
    cudaGetSymbolAddress((void**)&fif,    g_fif16);
    cudaGetSymbolAddress((void**)&fof,    g_fof16);
    cudaGetSymbolAddress((void**)&qkh,    g_qkh);
    cudaGetSymbolAddress((void**)&qkl,    g_qkl);
    cudaGetSymbolAddress((void**)&vt16,   g_vt16);
    cudaGetSymbolAddress((void**)&ah16,   g_ah16);
    cudaGetSymbolAddress((void**)&al16,   g_al16);
    cudaGetSymbolAddress((void**)&ctxh16, g_ctxh16);
    cudaGetSymbolAddress((void**)&ctxl16, g_ctxl16);
    cudaGetSymbolAddress((void**)&h2h16,  g_h2h16);
    cudaGetSymbolAddress((void**)&h2l16,  g_h2l16);
    cudaGetSymbolAddress((void**)&ffnh16, g_ffnh16);
    cudaGetSymbolAddress((void**)&ffnl16, g_ffnl16);

    const uint32_t SMT256_0 = 3u * (2u * PPA + 2u * 256u * 80u);   // 184320
    const uint32_t SMT128_1 = 3u * (2u * PPA + 1u * 128u * 80u);   // 92160 -> 2 CTAs/SM
    const uint32_t SMT256_1 = 3u * (2u * PPA + 1u * 256u * 80u);   // 122880
    cudaFuncSetAttribute(gemm_mp<256, 0>, cudaFuncAttributeMaxDynamicSharedMemorySize, SMT256_0);
    cudaFuncSetAttribute(gemm_mp<128, 1>, cudaFuncAttributeMaxDynamicSharedMemorySize, SMT128_1);
    cudaFuncSetAttribute(gemm_mp<256, 1>, cudaFuncAttributeMaxDynamicSharedMemorySize, SMT256_1);

    rope_table_kernel<<<512, 256>>>();

    dim3 tb(32, 8);
    transpose_split<<<dim3(Dd / 32, Dd / 64), tb>>>(wq, wqkvh, wqkvl, Dd, Dd);
    transpose_split<<<dim3(Dd / 32, Dd / 64), tb>>>(wk, wqkvh + (size_t)Dd * Dd, wqkvl + (size_t)Dd * Dd, Dd, Dd);
    transpose_split<<<dim3(Dd / 32, Dd / 64), tb>>>(wv, wqkvh + (size_t)2 * Dd * Dd, wqkvl + (size_t)2 * Dd * Dd, Dd, Dd);
    transpose_fp16<<<dim3(Dd / 32, Dd / 64), tb>>>(wo, wof, Dd, Dd);
    transpose_fp16<<<dim3(FFf / 32, Dd / 64), tb>>>(fiw, fif, Dd, FFf);
    transpose_fp16<<<dim3(Dd / 32, FFf / 64), tb>>>(fow, fof, FFf, Dd);

    ln_kernel<<<ROWS, 256>>>(hs, nullptr, ln1g, ln1b, nullptr, h1h, h1l, nullptr, nullptr);

    // fused QKV projection (bf16x3, RoPE in epilogue)
    gemm_mp<256, 0><<<dim3(24, 32), 256, SMT256_0>>>(h1h, h1l, wqkvh, wqkvl,
        nullptr, nullptr, v, qkh, qkl, pid, Dd, Dd, Dd, Dd, 8);

    vtrans_fp16<<<dim3(DHd / 32, Ss / 64, Bb * Hh), tb>>>(v, vt16);

    // scores (bf16x3, causal) -> softmax(+fp16 split) -> ctx (fp16x2)
    gemm_mp<256, 0><<<dim3(8, 16, Bb * Hh), 256, SMT256_0>>>(qkh, qkl,
        qkh + (size_t)ROWS * Dd, qkl + (size_t)ROWS * Dd,
        nullptr, nullptr, attn, nullptr, nullptr, nullptr, DHd, Dd, Dd, Ss, 16);
    softmax_kernel<<<Bb * Hh * Ss, 256>>>(attn, ah16, al16);
    gemm_mp<128, 1><<<dim3(1, 16, Bb * Hh), 256, SMT128_1>>>(ah16, al16, vt16, nullptr,
        nullptr, nullptr, nullptr, ctxh16, ctxl16, nullptr, Ss, Ss, Ss, Dd, 32 | 256);

    // output projection (fp16x2, BN=128 for 2 CTAs/SM)
    gemm_mp<128, 1><<<dim3(16, 32), 256, SMT128_1>>>(ctxh16, ctxl16, wof, nullptr,
        nullptr, nullptr, aproj, nullptr, nullptr, nullptr, Dd, Dd, Dd, Dd, 0);

    ln_kernel<<<ROWS, 256>>>(hs, aproj, ln2g, ln2b, h2, nullptr, nullptr, h2h16, h2l16);

    // FFN (fp16x2): FFN1 wide tile, FFN2 BN=128 for occupancy
    gemm_mp<256, 1><<<dim3(32, 32), 256, SMT256_1>>>(h2h16, h2l16, fif, nullptr,
        fib, nullptr, nullptr, ffnh16, ffnl16, nullptr, Dd, Dd, Dd, FFf, 1 | 2 | 256);
    gemm_mp<128, 1><<<dim3(16, 32), 256, SMT128_1>>>(ffnh16, ffnl16, fof, nullptr,
        fob, h2, out, nullptr, nullptr, nullptr, FFf, FFf, FFf, Dd, 1 | 4);
}

// round 10
// speedup vs baseline: 1.8603x; 1.3373x over previous
#include <cuda_runtime.h>
#include <cuda_bf16.h>
#include <cuda_fp16.h>
#include <math.h>
#include <stdint.h>

#define Bb   2
#define Ss   2048
#define Dd   2048
#define Hh   16
#define DHd  128
#define FFf  8192
#define ROWS 4096   // B*S

typedef __nv_bfloat16 bf16;

// ================= scratch (device globals) =================
__device__ bf16  g_h1h[(size_t)ROWS * Dd],  g_h1l[(size_t)ROWS * Dd];
__device__ __half g_h116[(size_t)ROWS * Dd];
__device__ bf16  g_wqkh[(size_t)2 * Dd * Dd], g_wqkl[(size_t)2 * Dd * Dd];
__device__ __half g_wvt16[(size_t)Dd * Dd];
__device__ __half g_wof16[(size_t)Dd * Dd];
__device__ __half g_fif16[(size_t)Dd * FFf];
__device__ __half g_fof16[(size_t)Dd * FFf];
__device__ bf16  g_qkh[(size_t)2 * ROWS * Dd], g_qkl[(size_t)2 * ROWS * Dd];
__device__ float g_v[(size_t)ROWS * Dd];
__device__ __half g_vt16[(size_t)Bb * Hh * DHd * Ss];
__device__ __half g_ah16[(size_t)Bb * Hh * Ss * Ss], g_al16[(size_t)Bb * Hh * Ss * Ss];
__device__ __half g_ctxh16[(size_t)ROWS * Dd], g_ctxl16[(size_t)ROWS * Dd];
__device__ float g_aproj[(size_t)ROWS * Dd];
__device__ float g_h2[(size_t)ROWS * Dd];
__device__ __half g_h216[(size_t)ROWS * Dd];
__device__ __half g_ffn16[(size_t)ROWS * FFf];
__device__ float g_sin[Ss * 64];
__device__ float g_cos[Ss * 64];

// ================= helpers =================
__device__ __forceinline__ uint32_t smem_u32(const void* p) {
    uint32_t a;
    asm("{ .reg .u64 t; cvta.to.shared.u64 t, %1; cvt.u32.u64 %0, t; }" : "=r"(a) : "l"(p));
    return a;
}
__device__ __forceinline__ void ldm4(uint32_t* r, uint32_t addr) {
    asm volatile("ldmatrix.sync.aligned.m8n8.x4.shared.b16 {%0,%1,%2,%3}, [%4];"
        : "=r"(r[0]), "=r"(r[1]), "=r"(r[2]), "=r"(r[3]) : "r"(addr));
}
__device__ __forceinline__ void ldm2(uint32_t* r, uint32_t addr) {
    asm volatile("ldmatrix.sync.aligned.m8n8.x2.shared.b16 {%0,%1}, [%2];"
        : "=r"(r[0]), "=r"(r[1]) : "r"(addr));
}
__device__ __forceinline__ void mma_bf16(float* c, const uint32_t* a, const uint32_t* b) {
    asm volatile(
        "mma.sync.aligned.m16n8k16.row.col.f32.bf16.bf16.f32 "
        "{%0,%1,%2,%3}, {%4,%5,%6,%7}, {%8,%9}, {%0,%1,%2,%3};"
        : "+f"(c[0]), "+f"(c[1]), "+f"(c[2]), "+f"(c[3])
        : "r"(a[0]), "r"(a[1]), "r"(a[2]), "r"(a[3]), "r"(b[0]), "r"(b[1]));
}
__device__ __forceinline__ void mma_fp16(float* c, const uint32_t* a, const uint32_t* b) {
    asm volatile(
        "mma.sync.aligned.m16n8k16.row.col.f32.f16.f16.f32 "
        "{%0,%1,%2,%3}, {%4,%5,%6,%7}, {%8,%9}, {%0,%1,%2,%3};"
        : "+f"(c[0]), "+f"(c[1]), "+f"(c[2]), "+f"(c[3])
        : "r"(a[0]), "r"(a[1]), "r"(a[2]), "r"(a[3]), "r"(b[0]), "r"(b[1]));
}
__device__ __forceinline__ void cp16(uint32_t dst, const void* src) {
    asm volatile("cp.async.cg.shared.global [%0], [%1], 16;" :: "r"(dst), "l"(src));
}
__device__ __forceinline__ void cp_commit() { asm volatile("cp.async.commit_group;"); }
__device__ __forceinline__ void cp_wait1() { asm volatile("cp.async.wait_group 1;"); }
__device__ __forceinline__ void cp_wait0() { asm volatile("cp.async.wait_group 0;"); }

__device__ __forceinline__ void split2(float x, float y, bf16* ph, bf16* pl) {
    bf16 hx = __float2bfloat16_rn(x), hy = __float2bfloat16_rn(y);
    float fx = __bfloat162float(hx), fy = __bfloat162float(hy);
    __nv_bfloat162 h2; h2.x = hx; h2.y = hy;
    __nv_bfloat162 l2; l2.x = __float2bfloat16_rn(x - fx); l2.y = __float2bfloat16_rn(y - fy);
    *(__nv_bfloat162*)ph = h2;
    *(__nv_bfloat162*)pl = l2;
}
__device__ __forceinline__ void split2h(float x, float y, __half* ph, __half* pl) {
    __half hx = __float2half_rn(x), hy = __float2half_rn(y);
    __half2 h2 = __halves2half2(hx, hy);
    __half2 l2 = __floats2half2_rn(x - __half2float(hx), y - __half2float(hy));
    *(__half2*)ph = h2;
    *(__half2*)pl = l2;
}

// ================= RoPE tables =================
__global__ void rope_table_kernel() {
    int t = blockIdx.x * 256 + threadIdx.x;
    if (t >= Ss * 64) return;
    int p = t >> 6, i = t & 63;
    double inv = pow(10000.0, -((double)(2 * i)) / 128.0);
    float ang = (float)p * (float)inv;
    g_sin[t] = (float)sin((double)ang);
    g_cos[t] = (float)cos((double)ang);
}

// ================= weight transpose variants (vectorized stores) =================
__global__ __launch_bounds__(256) void transpose_split(
    const float* __restrict__ in, bf16* __restrict__ oh, bf16* __restrict__ ol,
    int R, int Cc)
{
    __shared__ float t[64][33];
    int bx = blockIdx.x * 32, by = blockIdx.y * 64;
    int tx = threadIdx.x, ty = threadIdx.y;  // (32,8)
#pragma unroll
    for (int i = 0; i < 64; i += 8)
        t[ty + i][tx] = in[(size_t)(by + ty + i) * Cc + bx + tx];
    __syncthreads();
#pragma unroll
    for (int i = 0; i < 32; i += 8) {
        int r = ty + i;
        float v0 = t[2 * tx][r], v1 = t[2 * tx + 1][r];
        size_t o = (size_t)(bx + r) * R + by + 2 * tx;
        split2(v0, v1, oh + o, ol + o);
    }
}

__global__ __launch_bounds__(256) void transpose_fp16(
    const float* __restrict__ in, __half* __restrict__ oh, int R, int Cc)
{
    __shared__ float t[64][33];
    int bx = blockIdx.x * 32, by = blockIdx.y * 64;
    int tx = threadIdx.x, ty = threadIdx.y;
#pragma unroll
    for (int i = 0; i < 64; i += 8)
        t[ty + i][tx] = in[(size_t)(by + ty + i) * Cc + bx + tx];
    __syncthreads();
#pragma unroll
    for (int i = 0; i < 32; i += 8) {
        int r = ty + i;
        __half2 h2 = __floats2half2_rn(t[2 * tx][r], t[2 * tx + 1][r]);
        *(__half2*)(oh + (size_t)(bx + r) * R + by + 2 * tx) = h2;
    }
}

// V^T per head, single fp16: vt[bh][n][s] = v[b][s][h*128+n]
__global__ __launch_bounds__(256) void vtrans_fp16(
    const float* __restrict__ v, __half* __restrict__ oh)
{
    __shared__ float t[64][33];
    int bh = blockIdx.z;
    int b = bh >> 4, h = bh & 15;
    const float* in = v + (size_t)b * Ss * Dd + h * DHd;
    size_t obase = (size_t)bh * DHd * Ss;
    int n0 = blockIdx.x * 32, s0 = blockIdx.y * 64;
    int tx = threadIdx.x, ty = threadIdx.y;
#pragma unroll
    for (int i = 0; i < 64; i += 8)
        t[ty + i][tx] = in[(size_t)(s0 + ty + i) * Dd + n0 + tx];
    __syncthreads();
#pragma unroll
    for (int i = 0; i < 32; i += 8) {
        int r = ty + i;
        __half2 h2 = __floats2half2_rn(t[2 * tx][r], t[2 * tx + 1][r]);
        *(__half2*)(oh + obase + (size_t)(n0 + r) * Ss + s0 + 2 * tx) = h2;
    }
}

// ================= LayerNorm =================
__global__ __launch_bounds__(256) void ln_kernel(
    const float* __restrict__ x, const float* __restrict__ x2,
    const float* __restrict__ g, const float* __restrict__ bta,
    float* __restrict__ outf, bf16* __restrict__ outh, bf16* __restrict__ outl,
    __half* __restrict__ o16)
{
    __shared__ float red[256];
    int row = blockIdx.x, tid = threadIdx.x;
    size_t base = (size_t)row * Dd;
    float r[8];
    float s = 0.f;
#pragma unroll
    for (int t = 0; t < 8; t++) {
        int i = tid + t * 256;
        float v = x[base + i];
        if (x2) v += x2[base + i];
        r[t] = v; s += v;
    }
    red[tid] = s; __syncthreads();
    for (int o = 128; o > 0; o >>= 1) { if (tid < o) red[tid] += red[tid + o]; __syncthreads(); }
    float mean = red[0] * (1.0f / Dd);
    __syncthreads();
    float vs = 0.f;
#pragma unroll
    for (int t = 0; t < 8; t++) { float d = r[t] - mean; vs += d * d; }
    red[tid] = vs; __syncthreads();
    for (int o = 128; o > 0; o >>= 1) { if (tid < o) red[tid] += red[tid + o]; __syncthreads(); }
    float var = red[0] * (1.0f / Dd);
    float rs = rsqrtf(var + 1e-5f);
#pragma unroll
    for (int t = 0; t < 8; t++) {
        int i = tid + t * 256;
        float v = (r[t] - mean) * rs * g[i] + bta[i];
        if (outf) outf[base + i] = v;
        if (outh) {
            bf16 h = __float2bfloat16_rn(v);
            outh[base + i] = h;
            outl[base + i] = __float2bfloat16_rn(v - __bfloat162float(h));
        }
        if (o16) o16[base + i] = __float2half_rn(v);
    }
}

// ================= mixed-precision mma.sync GEMM =================
// MODE 0: bf16x3 (A hi/lo, B hi/lo, 3 MMAs)
// MODE 1: fp16x2 (A hi/lo, B single, 2 MMAs)
// MODE 2: fp16x1 (A single, B single, 1 MMA)
// flags: 1=bias 2=gelu 4=resid 8=qkv(rope+scatter) 16=score 32=ctx
//        64=bf16 hi/lo out 256=fp16 hi/lo out 512=fp16 single out
#define PPA 10240u            // A part bytes (128 rows * 80B)

template<int BN, int MODE, int MINCTAS>
__global__ __launch_bounds__(256, MINCTAS) void gemm_mp(
    const void* __restrict__ Ahv, const void* __restrict__ Alv,
    const void* __restrict__ Bhv, const void* __restrict__ Blv,
    const float* __restrict__ bias, const float* __restrict__ resid,
    float* __restrict__ Cf, void* __restrict__ Chv, void* __restrict__ Clv,
    const int* __restrict__ pid,
    int K, int lda, int ldb, int ldc, int flags)
{
    constexpr uint32_t PPB = (uint32_t)BN * 80u;
    constexpr uint32_t APARTS = (MODE == 2) ? 1u : 2u;
    constexpr uint32_t BPARTS = (MODE == 0) ? 2u : 1u;
    constexpr uint32_t STG = APARTS * PPA + BPARTS * PPB;
    constexpr int NFR = BN / 32;
    extern __shared__ char sm[];
    int bx = blockIdx.x, by = blockIdx.y, bz = blockIdx.z;
    const uint16_t* Ahp = (const uint16_t*)Ahv;
    const uint16_t* Alp = (const uint16_t*)Alv;
    const uint16_t* Bhp = (const uint16_t*)Bhv;
    const uint16_t* Blp = (const uint16_t*)Blv;
    float* Cfp = Cf;
    uint16_t* Chp = (uint16_t*)Chv;
    uint16_t* Clp = (uint16_t*)Clv;
    int Keff = K;
    if (flags & 16) {
        if (bx * BN > by * 128 + 127) return;
        int b = bz >> 4, h = bz & 15;
        size_t ao = (size_t)b * Ss * Dd + h * DHd;
        Ahp += ao; Alp += ao; Bhp += ao; Blp += ao;
        Cfp += (size_t)bz * Ss * Ss;
    }
    if (flags & 32) {
        by = gridDim.y - 1 - by;
        int b = bz >> 4, h = bz & 15;
        size_t ao = (size_t)bz * Ss * Ss;
        size_t bo = (size_t)bz * DHd * Ss;
        Ahp += ao; Alp += ao; Bhp += bo; Blp += bo;
        size_t co = (size_t)b * Ss * Dd + h * DHd;
        Chp += co; Clp += co;
        Keff = (by + 1) * 128;
    }
    const int tid = threadIdx.x, lane = tid & 31, warp = tid >> 5;
    const int m0 = by * 128, n0 = bx * BN;
    const int wm = (warp >> 2) * 64, wn = (warp & 3) * (BN / 4);
    const uint32_t sbase = smem_u32(sm);

    float acc[4][NFR][4];
#pragma unroll
    for (int i = 0; i < 4; i++)
#pragma unroll
        for (int j = 0; j < NFR; j++)
#pragma unroll
            for (int e = 0; e < 4; e++) acc[i][j][e] = 0.f;

#define ISSUE_CHUNK(ST, K0) do { \
    uint32_t sb0 = sbase + (uint32_t)(ST) * STG; \
    _Pragma("unroll") \
    for (int i = 0; i < 2; i++) { \
        int idx = tid + i * 256; \
        int r = idx >> 2; int cc = idx & 3; \
        uint32_t d = sb0 + (uint32_t)r * 80u + (uint32_t)cc * 16u; \
        size_t sa = (size_t)(m0 + r) * lda + (K0) + cc * 8; \
        cp16(d, Ahp + sa); \
        if (MODE != 2) cp16(d + PPA, Alp + sa); \
    } \
    _Pragma("unroll") \
    for (int i = 0; i < BN / 64; i++) { \
        int idx = tid + i * 256; \
        int r = idx >> 2; int cc = idx & 3; \
        uint32_t d = sb0 + APARTS * PPA + (uint32_t)r * 80u + (uint32_t)cc * 16u; \
        size_t sb2 = (size_t)(n0 + r) * ldb + (K0) + cc * 8; \
        cp16(d, Bhp + sb2); \
        if (MODE == 0) cp16(d + PPB, Blp + sb2); \
    } \
    cp_commit(); \
} while(0)

    const int nch = Keff / 32;
    ISSUE_CHUNK(0, 0);
    if (nch > 1) ISSUE_CHUNK(1, 32);

    const uint32_t a_lane_off = (uint32_t)(wm + (lane & 15)) * 80u + (uint32_t)((lane >> 4) * 16);
    const uint32_t b_lane_off = (uint32_t)(wn + (lane & 7)) * 80u + (uint32_t)(((lane >> 3) & 1) * 16);

    for (int c = 0; c < nch; c++) {
        if (c + 1 < nch) cp_wait1(); else cp_wait0();
        __syncthreads();
        const uint32_t boff = (uint32_t)(c % 3) * STG;
#pragma unroll
        for (int ks = 0; ks < 2; ks++) {
            uint32_t ahi[4][4], alo[4][4];
            uint32_t abase = sbase + boff + a_lane_off + (uint32_t)(ks * 32);
            uint32_t bbase = sbase + boff + APARTS * PPA + b_lane_off + (uint32_t)(ks * 32);
#pragma unroll
            for (int mti = 0; mti < 4; mti++) {
                ldm4(ahi[mti], abase + (uint32_t)(mti * 16) * 80u);
                if (MODE != 2) ldm4(alo[mti], abase + (uint32_t)(mti * 16) * 80u + PPA);
            }
#pragma unroll
            for (int ntj = 0; ntj < NFR; ntj++) {
                if (MODE == 0) {
                    uint32_t bhi[2], blo[2];
                    ldm2(bhi, bbase + (uint32_t)(ntj * 8) * 80u);
                    ldm2(blo, bbase + (uint32_t)(ntj * 8) * 80u + PPB);
#pragma unroll
                    for (int mti = 0; mti < 4; mti++) {
                        mma_bf16(acc[mti][ntj], ahi[mti], bhi);
                        mma_bf16(acc[mti][ntj], ahi[mti], blo);
                        mma_bf16(acc[mti][ntj], alo[mti], bhi);
                    }
                } else if (MODE == 1) {
                    uint32_t bh[2];
                    ldm2(bh, bbase + (uint32_t)(ntj * 8) * 80u);
#pragma unroll
                    for (int mti = 0; mti < 4; mti++) {
                        mma_fp16(acc[mti][ntj], ahi[mti], bh);
                        mma_fp16(acc[mti][ntj], alo[mti], bh);
                    }
                } else {
                    uint32_t bh[2];
                    ldm2(bh, bbase + (uint32_t)(ntj * 8) * 80u);
#pragma unroll
                    for (int mti = 0; mti < 4; mti++)
                        mma_fp16(acc[mti][ntj], ahi[mti], bh);
                }
            }
        }
        if (c + 2 < nch) ISSUE_CHUNK((c + 2) % 3, (c + 2) * 32);
    }
#undef ISSUE_CHUNK

    // ---------------- epilogue ----------------
#pragma unroll
    for (int mti = 0; mti < 4; mti++) {
#pragma unroll
        for (int ntj = 0; ntj < NFR; ntj++) {
            int row = m0 + wm + mti * 16 + (lane >> 2);
            int col = n0 + wn + ntj * 8 + (lane & 3) * 2;
#pragma unroll
            for (int half = 0; half < 2; half++) {
                int rr = row + half * 8;
                float v0 = acc[mti][ntj][half * 2];
                float v1 = acc[mti][ntj][half * 2 + 1];
                if (flags & 1) { v0 += bias[col]; v1 += bias[col + 1]; }
                if (flags & 2) {
                    v0 = 0.5f * v0 * (1.0f + erff(v0 * 0.70710678118654752f));
                    v1 = 0.5f * v1 * (1.0f + erff(v1 * 0.70710678118654752f));
                }
                if (flags & 4) {
                    const float* rp = resid + (size_t)rr * ldc + col;
                    v0 += rp[0]; v1 += rp[1];
                }
                if (flags & 8) {
                    int sel = col >> 11, cl = col & 2047;
                    int b = rr >> 11, s = rr & 2047;
                    int pos = pid[b * Ss + s];
                    int i = (cl & 127) >> 1;
                    float sn = g_sin[pos * 64 + i], cs = g_cos[pos * 64 + i];
                    float r0 = v0 * cs - v1 * sn;
                    float r1 = v1 * cs + v0 * sn;
                    size_t o = (size_t)(sel * ROWS + rr) * Dd + cl;
                    split2(r0, r1, (bf16*)(Chp + o), (bf16*)(Clp + o));
                } else if (flags & 64) {
                    size_t o = (size_t)rr * ldc + col;
                    split2(v0, v1, (bf16*)(Chp + o), (bf16*)(Clp + o));
                } else if (flags & 256) {
                    size_t o = (size_t)rr * ldc + col;
                    split2h(v0, v1, (__half*)(Chp + o), (__half*)(Clp + o));
                } else if (flags & 512) {
                    size_t o = (size_t)rr * ldc + col;
                    *(__half2*)((__half*)Chp + o) = __floats2half2_rn(v0, v1);
                } else {
                    *(float2*)(Cfp + (size_t)rr * ldc + col) = make_float2(v0, v1);
                }
            }
        }
    }
}

// ================= row softmax (causal trunc) + fp16 split out =================
__global__ __launch_bounds__(256) void softmax_kernel(
    float* __restrict__ attn, __half* __restrict__ ah, __half* __restrict__ al)
{
    int rid = blockIdx.x;
    int qpos = rid & (Ss - 1);
    int L = qpos + 1;
    int Lpad = ((qpos >> 7) + 1) << 7;       // roundup(L,128): fp16 region read by ctx
    float* row = attn + (size_t)rid * Ss;
    __half* rh = ah + (size_t)rid * Ss;
    __half* rl = al + (size_t)rid * Ss;
    __shared__ float red[256];
    int tid = threadIdx.x;
    float r[8];
    float mx = -3.4e38f;
#pragma unroll
    for (int t = 0; t < 8; t++) {
        int i = tid + t * 256;
        float v = (i < L) ? row[i] : -3.4e38f;
        r[t] = v; mx = fmaxf(mx, v);
    }
    red[tid] = mx; __syncthreads();
    for (int o = 128; o > 0; o >>= 1) { if (tid < o) red[tid] = fmaxf(red[tid], red[tid + o]); __syncthreads(); }
    mx = red[0]; __syncthreads();
    float s = 0.f;
#pragma unroll
    for (int t = 0; t < 8; t++) {
        int i = tid + t * 256;
        float e = (i < L) ? expf(r[t] - mx) : 0.0f;
        r[t] = e; s += e;
    }
    red[tid] = s; __syncthreads();
    for (int o = 128; o > 0; o >>= 1) { if (tid < o) red[tid] += red[tid + o]; __syncthreads(); }
    float inv = 1.0f / red[0];
#pragma unroll
    for (int t = 0; t < 8; t++) {
        int i = tid + t * 256;
        float v = r[t] * inv;
        row[i] = v;
        if (i < Lpad) {
            __half h = __float2half_rn(v);
            rh[i] = h;
            rl[i] = __float2half_rn(v - __half2float(h));
        }
    }
}

// ================= launch =================
extern "C" void kernel_launch(void* const* d_in, const int* in_sizes, int n_in,
                              void* d_out, int out_size)
{
    const float* hs   = (const float*)d_in[0];
    const int*   pid  = (const int*)  d_in[1];
    const float* wq   = (const float*)d_in[2];
    const float* wk   = (const float*)d_in[3];
    const float* wv   = (const float*)d_in[4];
    const float* wo   = (const float*)d_in[5];
    const float* ln1g = (const float*)d_in[6];
    const float* ln1b = (const float*)d_in[7];
    const float* ln2g = (const float*)d_in[8];
    const float* ln2b = (const float*)d_in[9];
    const float* fiw  = (const float*)d_in[10];
    const float* fib  = (const float*)d_in[11];
    const float* fow  = (const float*)d_in[12];
    const float* fob  = (const float*)d_in[13];

    float* out  = (float*)d_out;
    float* attn = out + (size_t)ROWS * Dd;

    float *v, *aproj, *h2;
    bf16 *h1h, *h1l, *wqkh, *wqkl, *qkh, *qkl;
    __half *h116, *wvt, *wof, *fif, *fof, *vt16, *ah16, *al16;
    __half *ctxh16, *ctxl16, *h216, *ffn16;
    cudaGetSymbolAddress((void**)&v,      g_v);
    cudaGetSymbolAddress((void**)&aproj,  g_aproj);
    cudaGetSymbolAddress((void**)&h2,     g_h2);
    cudaGetSymbolAddress((void**)&h1h,    g_h1h);
    cudaGetSymbolAddress((void**)&h1l,    g_h1l);
    cudaGetSymbolAddress((void**)&h116,   g_h116);
    cudaGetSymbolAddress((void**)&wqkh,   g_wqkh);
    cudaGetSymbolAddress((void**)&wqkl,   g_wqkl);
    cudaGetSymbolAddress((void**)&wvt,    g_wvt16);
    cudaGetSymbolAddress((void**)&wof,    g_wof16);
    cudaGetSymbolAddress((void**)&fif,    g_fif16);
    cudaGetSymbolAddress((void**)&fof,    g_fof16);
    cudaGetSymbolAddress((void**)&qkh,    g_qkh);
    cudaGetSymbolAddress((void**)&qkl,    g_qkl);
    cudaGetSymbolAddress((void**)&vt16,   g_vt16);
    cudaGetSymbolAddress((void**)&ah16,   g_ah16);
    cudaGetSymbolAddress((void**)&al16,   g_al16);
    cudaGetSymbolAddress((void**)&ctxh16, g_ctxh16);
    cudaGetSymbolAddress((void**)&ctxl16, g_ctxl16);
    cudaGetSymbolAddress((void**)&h216,   g_h216);
    cudaGetSymbolAddress((void**)&ffn16,  g_ffn16);

    const uint32_t SMT256_0 = 3u * (2u * PPA + 2u * 256u * 80u);   // 184320
    const uint32_t SMT128_1 = 3u * (2u * PPA + 1u * 128u * 80u);   // 92160
    const uint32_t SMT128_2 = 3u * (1u * PPA + 1u * 128u * 80u);   // 61440
    cudaFuncSetAttribute((const void*)gemm_mp<256, 0, 1>, cudaFuncAttributeMaxDynamicSharedMemorySize, SMT256_0);
    cudaFuncSetAttribute((const void*)gemm_mp<128, 1, 2>, cudaFuncAttributeMaxDynamicSharedMemorySize, SMT128_1);
    cudaFuncSetAttribute((const void*)gemm_mp<128, 2, 2>, cudaFuncAttributeMaxDynamicSharedMemorySize, SMT128_2);

    rope_table_kernel<<<512, 256>>>();

    dim3 tb(32, 8);
    transpose_split<<<dim3(Dd / 32, Dd / 64), tb>>>(wq, wqkh, wqkl, Dd, Dd);
    transpose_split<<<dim3(Dd / 32, Dd / 64), tb>>>(wk, wqkh + (size_t)Dd * Dd, wqkl + (size_t)Dd * Dd, Dd, Dd);
    transpose_fp16<<<dim3(Dd / 32, Dd / 64), tb>>>(wv, wvt, Dd, Dd);
    transpose_fp16<<<dim3(Dd / 32, Dd / 64), tb>>>(wo, wof, Dd, Dd);
    transpose_fp16<<<dim3(FFf / 32, Dd / 64), tb>>>(fiw, fif, Dd, FFf);
    transpose_fp16<<<dim3(Dd / 32, FFf / 64), tb>>>(fow, fof, FFf, Dd);

    // ln1 -> bf16 hi/lo (for qk) + fp16 single (for v)
    ln_kernel<<<ROWS, 256>>>(hs, nullptr, ln1g, ln1b, nullptr, h1h, h1l, h116);

    // qk projection (bf16x3, RoPE in epilogue); v projection (fp16x1)
    gemm_mp<256, 0, 1><<<dim3(16, 32), 256, SMT256_0>>>(h1h, h1l, wqkh, wqkl,
        nullptr, nullptr, nullptr, qkh, qkl, pid, Dd, Dd, Dd, Dd, 8);
    gemm_mp<128, 2, 2><<<dim3(16, 32), 256, SMT128_2>>>(h116, nullptr, wvt, nullptr,
        nullptr, nullptr, v, nullptr, nullptr, nullptr, Dd, Dd, Dd, Dd, 0);

    vtrans_fp16<<<dim3(DHd / 32, Ss / 64, Bb * Hh), tb>>>(v, vt16);

    // scores (bf16x3, causal) -> softmax(+fp16 split) -> ctx (fp16x2)
    gemm_mp<256, 0, 1><<<dim3(8, 16, Bb * Hh), 256, SMT256_0>>>(qkh, qkl,
        qkh + (size_t)ROWS * Dd, qkl + (size_t)ROWS * Dd,
        nullptr, nullptr, attn, nullptr, nullptr, nullptr, DHd, Dd, Dd, Ss, 16);
    softmax_kernel<<<Bb * Hh * Ss, 256>>>(attn, ah16, al16);
    gemm_mp<128, 1, 2><<<dim3(1, 16, Bb * Hh), 256, SMT128_1>>>(ah16, al16, vt16, nullptr,
        nullptr, nullptr, nullptr, ctxh16, ctxl16, nullptr, Ss, Ss, Ss, Dd, 32 | 256);

    // output projection (fp16x2)
    gemm_mp<128, 1, 2><<<dim3(16, 32), 256, SMT128_1>>>(ctxh16, ctxl16, wof, nullptr,
        nullptr, nullptr, aproj, nullptr, nullptr, nullptr, Dd, Dd, Dd, Dd, 0);

    // ln2 -> fp32 + fp16 single
    ln_kernel<<<ROWS, 256>>>(hs, aproj, ln2g, ln2b, h2, nullptr, nullptr, h216);

    // FFN (fp16x1)
    gemm_mp<128, 2, 2><<<dim3(64, 32), 256, SMT128_2>>>(h216, nullptr, fif, nullptr,
        fib, nullptr, nullptr, ffn16, nullptr, nullptr, Dd, Dd, Dd, FFf, 1 | 2 | 512);
    gemm_mp<128, 2, 2><<<dim3(16, 32), 256, SMT128_2>>>(ffn16, nullptr, fof, nullptr,
        fob, h2, out, nullptr, nullptr, nullptr, FFf, FFf, FFf, Dd, 1 | 4);
}

// round 11
// speedup vs baseline: 1.8632x; 1.0015x over previous
#include <cuda_runtime.h>
#include <cuda_bf16.h>
#include <cuda_fp16.h>
#include <math.h>
#include <stdint.h>

#define Bb   2
#define Ss   2048
#define Dd   2048
#define Hh   16
#define DHd  128
#define FFf  8192
#define ROWS 4096   // B*S

typedef __nv_bfloat16 bf16;

// ================= scratch (device globals) =================
__device__ bf16  g_h1h[(size_t)ROWS * Dd],  g_h1l[(size_t)ROWS * Dd];
__device__ __half g_h116[(size_t)ROWS * Dd];
__device__ bf16  g_wqkh[(size_t)2 * Dd * Dd], g_wqkl[(size_t)2 * Dd * Dd];
__device__ __half g_wvt16[(size_t)Dd * Dd];
__device__ __half g_wof16[(size_t)Dd * Dd];
__device__ __half g_fif16[(size_t)Dd * FFf];
__device__ __half g_fof16[(size_t)Dd * FFf];
__device__ bf16  g_qkh[(size_t)2 * ROWS * Dd], g_qkl[(size_t)2 * ROWS * Dd];
__device__ __half g_v16[(size_t)ROWS * Dd];
__device__ __half g_vt16[(size_t)Bb * Hh * DHd * Ss];
__device__ __half g_ah16[(size_t)Bb * Hh * Ss * Ss], g_al16[(size_t)Bb * Hh * Ss * Ss];
__device__ __half g_ctxh16[(size_t)ROWS * Dd], g_ctxl16[(size_t)ROWS * Dd];
__device__ float g_aproj[(size_t)ROWS * Dd];
__device__ float g_h2[(size_t)ROWS * Dd];
__device__ __half g_h216[(size_t)ROWS * Dd];
__device__ __half g_ffn16[(size_t)ROWS * FFf];
__device__ float g_sin[Ss * 64];
__device__ float g_cos[Ss * 64];

// ================= helpers =================
__device__ __forceinline__ uint32_t smem_u32(const void* p) {
    uint32_t a;
    asm("{ .reg .u64 t; cvta.to.shared.u64 t, %1; cvt.u32.u64 %0, t; }" : "=r"(a) : "l"(p));
    return a;
}
__device__ __forceinline__ void ldm4(uint32_t* r, uint32_t addr) {
    asm volatile("ldmatrix.sync.aligned.m8n8.x4.shared.b16 {%0,%1,%2,%3}, [%4];"
        : "=r"(r[0]), "=r"(r[1]), "=r"(r[2]), "=r"(r[3]) : "r"(addr));
}
__device__ __forceinline__ void ldm2(uint32_t* r, uint32_t addr) {
    asm volatile("ldmatrix.sync.aligned.m8n8.x2.shared.b16 {%0,%1}, [%2];"
        : "=r"(r[0]), "=r"(r[1]) : "r"(addr));
}
__device__ __forceinline__ void mma_bf16(float* c, const uint32_t* a, const uint32_t* b) {
    asm volatile(
        "mma.sync.aligned.m16n8k16.row.col.f32.bf16.bf16.f32 "
        "{%0,%1,%2,%3}, {%4,%5,%6,%7}, {%8,%9}, {%0,%1,%2,%3};"
        : "+f"(c[0]), "+f"(c[1]), "+f"(c[2]), "+f"(c[3])
        : "r"(a[0]), "r"(a[1]), "r"(a[2]), "r"(a[3]), "r"(b[0]), "r"(b[1]));
}
__device__ __forceinline__ void mma_fp16(float* c, const uint32_t* a, const uint32_t* b) {
    asm volatile(
        "mma.sync.aligned.m16n8k16.row.col.f32.f16.f16.f32 "
        "{%0,%1,%2,%3}, {%4,%5,%6,%7}, {%8,%9}, {%0,%1,%2,%3};"
        : "+f"(c[0]), "+f"(c[1]), "+f"(c[2]), "+f"(c[3])
        : "r"(a[0]), "r"(a[1]), "r"(a[2]), "r"(a[3]), "r"(b[0]), "r"(b[1]));
}
__device__ __forceinline__ void cp16(uint32_t dst, const void* src) {
    asm volatile("cp.async.cg.shared.global [%0], [%1], 16;" :: "r"(dst), "l"(src));
}
__device__ __forceinline__ void cp_commit() { asm volatile("cp.async.commit_group;"); }
__device__ __forceinline__ void cp_wait1() { asm volatile("cp.async.wait_group 1;"); }
__device__ __forceinline__ void cp_wait0() { asm volatile("cp.async.wait_group 0;"); }

__device__ __forceinline__ void split2(float x, float y, bf16* ph, bf16* pl) {
    bf16 hx = __float2bfloat16_rn(x), hy = __float2bfloat16_rn(y);
    float fx = __bfloat162float(hx), fy = __bfloat162float(hy);
    __nv_bfloat162 h2; h2.x = hx; h2.y = hy;
    __nv_bfloat162 l2; l2.x = __float2bfloat16_rn(x - fx); l2.y = __float2bfloat16_rn(y - fy);
    *(__nv_bfloat162*)ph = h2;
    *(__nv_bfloat162*)pl = l2;
}
__device__ __forceinline__ void split2h(float x, float y, __half* ph, __half* pl) {
    __half hx = __float2half_rn(x), hy = __float2half_rn(y);
    __half2 h2 = __halves2half2(hx, hy);
    __half2 l2 = __floats2half2_rn(x - __half2float(hx), y - __half2float(hy));
    *(__half2*)ph = h2;
    *(__half2*)pl = l2;
}

// ================= fused prep: 6 weight transposes + rope table =================
__device__ __forceinline__ void dev_tsplit(
    float (*t)[33], const float* __restrict__ in,
    bf16* __restrict__ oh, bf16* __restrict__ ol,
    int R, int Cc, int bxb, int byb)
{
    int bx = bxb * 32, by = byb * 64;
    int tx = threadIdx.x & 31, ty = threadIdx.x >> 5;
#pragma unroll
    for (int i = 0; i < 64; i += 8)
        t[ty + i][tx] = in[(size_t)(by + ty + i) * Cc + bx + tx];
    __syncthreads();
#pragma unroll
    for (int i = 0; i < 32; i += 8) {
        int r = ty + i;
        size_t o = (size_t)(bx + r) * R + by + 2 * tx;
        split2(t[2 * tx][r], t[2 * tx + 1][r], oh + o, ol + o);
    }
}
__device__ __forceinline__ void dev_tfp16(
    float (*t)[33], const float* __restrict__ in, __half* __restrict__ oh,
    int R, int Cc, int bxb, int byb)
{
    int bx = bxb * 32, by = byb * 64;
    int tx = threadIdx.x & 31, ty = threadIdx.x >> 5;
#pragma unroll
    for (int i = 0; i < 64; i += 8)
        t[ty + i][tx] = in[(size_t)(by + ty + i) * Cc + bx + tx];
    __syncthreads();
#pragma unroll
    for (int i = 0; i < 32; i += 8) {
        int r = ty + i;
        __half2 h2 = __floats2half2_rn(t[2 * tx][r], t[2 * tx + 1][r]);
        *(__half2*)(oh + (size_t)(bx + r) * R + by + 2 * tx) = h2;
    }
}

__global__ __launch_bounds__(256) void prep_kernel(
    const float* __restrict__ wq, const float* __restrict__ wk,
    const float* __restrict__ wv, const float* __restrict__ wo,
    const float* __restrict__ fiw, const float* __restrict__ fow,
    bf16* __restrict__ wqkh, bf16* __restrict__ wqkl,
    __half* __restrict__ wvt, __half* __restrict__ wof,
    __half* __restrict__ fif, __half* __restrict__ fof)
{
    __shared__ float t[64][33];
    int id = blockIdx.x;
    if (id < 2048) {                                  // wq -> bf16 hi/lo
        dev_tsplit(t, wq, wqkh, wqkl, Dd, Dd, id & 63, id >> 6);
    } else if (id < 4096) {                           // wk
        id -= 2048;
        dev_tsplit(t, wk, wqkh + (size_t)Dd * Dd, wqkl + (size_t)Dd * Dd, Dd, Dd, id & 63, id >> 6);
    } else if (id < 6144) {                           // wv -> fp16
        id -= 4096;
        dev_tfp16(t, wv, wvt, Dd, Dd, id & 63, id >> 6);
    } else if (id < 8192) {                           // wo -> fp16
        id -= 6144;
        dev_tfp16(t, wo, wof, Dd, Dd, id & 63, id >> 6);
    } else if (id < 16384) {                          // fiw: grid (256, 32)
        id -= 8192;
        dev_tfp16(t, fiw, fif, Dd, FFf, id & 255, id >> 8);
    } else if (id < 24576) {                          // fow: grid (64, 128)
        id -= 16384;
        dev_tfp16(t, fow, fof, FFf, Dd, id & 63, id >> 6);
    } else {                                          // rope table (512 blocks)
        int tt = (id - 24576) * 256 + threadIdx.x;
        int p = tt >> 6, i = tt & 63;
        double inv = pow(10000.0, -((double)(2 * i)) / 128.0);
        float ang = (float)p * (float)inv;
        g_sin[tt] = (float)sin((double)ang);
        g_cos[tt] = (float)cos((double)ang);
    }
}

// V^T per head, fp16 in/out: vt[bh][n][s] = v16[b][s][h*128+n]
__global__ __launch_bounds__(256) void vtrans_h(
    const __half* __restrict__ v, __half* __restrict__ oh)
{
    __shared__ float t[64][33];
    int bh = blockIdx.z;
    int b = bh >> 4, h = bh & 15;
    const __half* in = v + (size_t)b * Ss * Dd + h * DHd;
    size_t obase = (size_t)bh * DHd * Ss;
    int n0 = blockIdx.x * 32, s0 = blockIdx.y * 64;
    int tx = threadIdx.x, ty = threadIdx.y;
#pragma unroll
    for (int i = 0; i < 64; i += 8)
        t[ty + i][tx] = __half2float(in[(size_t)(s0 + ty + i) * Dd + n0 + tx]);
    __syncthreads();
#pragma unroll
    for (int i = 0; i < 32; i += 8) {
        int r = ty + i;
        __half2 h2 = __floats2half2_rn(t[2 * tx][r], t[2 * tx + 1][r]);
        *(__half2*)(oh + obase + (size_t)(n0 + r) * Ss + s0 + 2 * tx) = h2;
    }
}

// ================= LayerNorm =================
__global__ __launch_bounds__(256) void ln_kernel(
    const float* __restrict__ x, const float* __restrict__ x2,
    const float* __restrict__ g, const float* __restrict__ bta,
    float* __restrict__ outf, bf16* __restrict__ outh, bf16* __restrict__ outl,
    __half* __restrict__ o16)
{
    __shared__ float red[256];
    int row = blockIdx.x, tid = threadIdx.x;
    size_t base = (size_t)row * Dd;
    float r[8];
    float s = 0.f;
#pragma unroll
    for (int t = 0; t < 8; t++) {
        int i = tid + t * 256;
        float v = x[base + i];
        if (x2) v += x2[base + i];
        r[t] = v; s += v;
    }
    red[tid] = s; __syncthreads();
    for (int o = 128; o > 0; o >>= 1) { if (tid < o) red[tid] += red[tid + o]; __syncthreads(); }
    float mean = red[0] * (1.0f / Dd);
    __syncthreads();
    float vs = 0.f;
#pragma unroll
    for (int t = 0; t < 8; t++) { float d = r[t] - mean; vs += d * d; }
    red[tid] = vs; __syncthreads();
    for (int o = 128; o > 0; o >>= 1) { if (tid < o) red[tid] += red[tid + o]; __syncthreads(); }
    float var = red[0] * (1.0f / Dd);
    float rs = rsqrtf(var + 1e-5f);
#pragma unroll
    for (int t = 0; t < 8; t++) {
        int i = tid + t * 256;
        float v = (r[t] - mean) * rs * g[i] + bta[i];
        if (outf) outf[base + i] = v;
        if (outh) {
            bf16 h = __float2bfloat16_rn(v);
            outh[base + i] = h;
            outl[base + i] = __float2bfloat16_rn(v - __bfloat162float(h));
        }
        if (o16) o16[base + i] = __float2half_rn(v);
    }
}

// ================= mixed-precision mma.sync GEMM =================
// MODE 0: bf16x3. MODE 1: fp16x2. MODE 2: fp16x1.
// flags: 1=bias 2=gelu 4=resid 8=qkv(rope+scatter) 16=score 32=ctx
//        64=bf16 hi/lo out 256=fp16 hi/lo out 512=fp16 single out
#define PPA 10240u            // A part bytes (128 rows * 80B)

template<int BN, int MODE, int MINCTAS>
__global__ __launch_bounds__(256, MINCTAS) void gemm_mp(
    const void* __restrict__ Ahv, const void* __restrict__ Alv,
    const void* __restrict__ Bhv, const void* __restrict__ Blv,
    const float* __restrict__ bias, const float* __restrict__ resid,
    float* __restrict__ Cf, void* __restrict__ Chv, void* __restrict__ Clv,
    const int* __restrict__ pid,
    int K, int lda, int ldb, int ldc, int flags)
{
    constexpr uint32_t PPB = (uint32_t)BN * 80u;
    constexpr uint32_t APARTS = (MODE == 2) ? 1u : 2u;
    constexpr uint32_t BPARTS = (MODE == 0) ? 2u : 1u;
    constexpr uint32_t STG = APARTS * PPA + BPARTS * PPB;
    constexpr int NFR = BN / 32;
    extern __shared__ char sm[];
    int bx = blockIdx.x, by = blockIdx.y, bz = blockIdx.z;
    const uint16_t* Ahp = (const uint16_t*)Ahv;
    const uint16_t* Alp = (const uint16_t*)Alv;
    const uint16_t* Bhp = (const uint16_t*)Bhv;
    const uint16_t* Blp = (const uint16_t*)Blv;
    float* Cfp = Cf;
    uint16_t* Chp = (uint16_t*)Chv;
    uint16_t* Clp = (uint16_t*)Clv;
    int Keff = K;
    if (flags & 16) {
        if (bx * BN > by * 128 + 127) return;
        int b = bz >> 4, h = bz & 15;
        size_t ao = (size_t)b * Ss * Dd + h * DHd;
        Ahp += ao; Alp += ao; Bhp += ao; Blp += ao;
        Cfp += (size_t)bz * Ss * Ss;
    }
    if (flags & 32) {
        // grid (32, 16): x = head (fast axis), y reversed -> globally descending Keff
        bz = blockIdx.x;
        by = gridDim.y - 1 - blockIdx.y;
        bx = 0;
        int b = bz >> 4, h = bz & 15;
        size_t ao = (size_t)bz * Ss * Ss;
        size_t bo = (size_t)bz * DHd * Ss;
        Ahp += ao; Alp += ao; Bhp += bo; Blp += bo;
        size_t co = (size_t)b * Ss * Dd + h * DHd;
        Chp += co; Clp += co;
        Keff = (by + 1) * 128;
    }
    const int tid = threadIdx.x, lane = tid & 31, warp = tid >> 5;
    const int m0 = by * 128, n0 = bx * BN;
    const int wm = (warp >> 2) * 64, wn = (warp & 3) * (BN / 4);
    const uint32_t sbase = smem_u32(sm);

    float acc[4][NFR][4];
#pragma unroll
    for (int i = 0; i < 4; i++)
#pragma unroll
        for (int j = 0; j < NFR; j++)
#pragma unroll
            for (int e = 0; e < 4; e++) acc[i][j][e] = 0.f;

#define ISSUE_CHUNK(ST, K0) do { \
    uint32_t sb0 = sbase + (uint32_t)(ST) * STG; \
    _Pragma("unroll") \
    for (int i = 0; i < 2; i++) { \
        int idx = tid + i * 256; \
        int r = idx >> 2; int cc = idx & 3; \
        uint32_t d = sb0 + (uint32_t)r * 80u + (uint32_t)cc * 16u; \
        size_t sa = (size_t)(m0 + r) * lda + (K0) + cc * 8; \
        cp16(d, Ahp + sa); \
        if (MODE != 2) cp16(d + PPA, Alp + sa); \
    } \
    _Pragma("unroll") \
    for (int i = 0; i < BN / 64; i++) { \
        int idx = tid + i * 256; \
        int r = idx >> 2; int cc = idx & 3; \
        uint32_t d = sb0 + APARTS * PPA + (uint32_t)r * 80u + (uint32_t)cc * 16u; \
        size_t sb2 = (size_t)(n0 + r) * ldb + (K0) + cc * 8; \
        cp16(d, Bhp + sb2); \
        if (MODE == 0) cp16(d + PPB, Blp + sb2); \
    } \
    cp_commit(); \
} while(0)

    const int nch = Keff / 32;
    ISSUE_CHUNK(0, 0);
    if (nch > 1) ISSUE_CHUNK(1, 32);

    const uint32_t a_lane_off = (uint32_t)(wm + (lane & 15)) * 80u + (uint32_t)((lane >> 4) * 16);
    const uint32_t b_lane_off = (uint32_t)(wn + (lane & 7)) * 80u + (uint32_t)(((lane >> 3) & 1) * 16);

    for (int c = 0; c < nch; c++) {
        if (c + 1 < nch) cp_wait1(); else cp_wait0();
        __syncthreads();
        const uint32_t boff = (uint32_t)(c % 3) * STG;
#pragma unroll
        for (int ks = 0; ks < 2; ks++) {
            uint32_t ahi[4][4], alo[4][4];
            uint32_t abase = sbase + boff + a_lane_off + (uint32_t)(ks * 32);
            uint32_t bbase = sbase + boff + APARTS * PPA + b_lane_off + (uint32_t)(ks * 32);
#pragma unroll
            for (int mti = 0; mti < 4; mti++) {
                ldm4(ahi[mti], abase + (uint32_t)(mti * 16) * 80u);
                if (MODE != 2) ldm4(alo[mti], abase + (uint32_t)(mti * 16) * 80u + PPA);
            }
#pragma unroll
            for (int ntj = 0; ntj < NFR; ntj++) {
                if (MODE == 0) {
                    uint32_t bhi[2], blo[2];
                    ldm2(bhi, bbase + (uint32_t)(ntj * 8) * 80u);
                    ldm2(blo, bbase + (uint32_t)(ntj * 8) * 80u + PPB);
#pragma unroll
                    for (int mti = 0; mti < 4; mti++) {
                        mma_bf16(acc[mti][ntj], ahi[mti], bhi);
                        mma_bf16(acc[mti][ntj], ahi[mti], blo);
                        mma_bf16(acc[mti][ntj], alo[mti], bhi);
                    }
                } else if (MODE == 1) {
                    uint32_t bh[2];
                    ldm2(bh, bbase + (uint32_t)(ntj * 8) * 80u);
#pragma unroll
                    for (int mti = 0; mti < 4; mti++) {
                        mma_fp16(acc[mti][ntj], ahi[mti], bh);
                        mma_fp16(acc[mti][ntj], alo[mti], bh);
                    }
                } else {
                    uint32_t bh[2];
                    ldm2(bh, bbase + (uint32_t)(ntj * 8) * 80u);
#pragma unroll
                    for (int mti = 0; mti < 4; mti++)
                        mma_fp16(acc[mti][ntj], ahi[mti], bh);
                }
            }
        }
        if (c + 2 < nch) ISSUE_CHUNK((c + 2) % 3, (c + 2) * 32);
    }
#undef ISSUE_CHUNK

    // ---------------- epilogue ----------------
#pragma unroll
    for (int mti = 0; mti < 4; mti++) {
#pragma unroll
        for (int ntj = 0; ntj < NFR; ntj++) {
            int row = m0 + wm + mti * 16 + (lane >> 2);
            int col = n0 + wn + ntj * 8 + (lane & 3) * 2;
#pragma unroll
            for (int half = 0; half < 2; half++) {
                int rr = row + half * 8;
                float v0 = acc[mti][ntj][half * 2];
                float v1 = acc[mti][ntj][half * 2 + 1];
                if (flags & 1) { v0 += bias[col]; v1 += bias[col + 1]; }
                if (flags & 2) {
                    v0 = 0.5f * v0 * (1.0f + erff(v0 * 0.70710678118654752f));
                    v1 = 0.5f * v1 * (1.0f + erff(v1 * 0.70710678118654752f));
                }
                if (flags & 4) {
                    const float* rp = resid + (size_t)rr * ldc + col;
                    v0 += rp[0]; v1 += rp[1];
                }
                if (flags & 8) {
                    int sel = col >> 11, cl = col & 2047;
                    int b = rr >> 11, s = rr & 2047;
                    int pos = pid[b * Ss + s];
                    int i = (cl & 127) >> 1;
                    float sn = g_sin[pos * 64 + i], cs = g_cos[pos * 64 + i];
                    float r0 = v0 * cs - v1 * sn;
                    float r1 = v1 * cs + v0 * sn;
                    size_t o = (size_t)(sel * ROWS + rr) * Dd + cl;
                    split2(r0, r1, (bf16*)(Chp + o), (bf16*)(Clp + o));
                } else if (flags & 64) {
                    size_t o = (size_t)rr * ldc + col;
                    split2(v0, v1, (bf16*)(Chp + o), (bf16*)(Clp + o));
                } else if (flags & 256) {
                    size_t o = (size_t)rr * ldc + col;
                    split2h(v0, v1, (__half*)(Chp + o), (__half*)(Clp + o));
                } else if (flags & 512) {
                    size_t o = (size_t)rr * ldc + col;
                    *(__half2*)((__half*)Chp + o) = __floats2half2_rn(v0, v1);
                } else {
                    *(float2*)(Cfp + (size_t)rr * ldc + col) = make_float2(v0, v1);
                }
            }
        }
    }
}

// ================= row softmax (causal trunc, vectorized) + fp16 split out =================
__global__ __launch_bounds__(256) void softmax_kernel(
    float* __restrict__ attn, __half* __restrict__ ah, __half* __restrict__ al)
{
    int rid = blockIdx.x;
    int qpos = rid & (Ss - 1);
    int L = qpos + 1;
    int Lpad = ((qpos >> 7) + 1) << 7;       // roundup(L,128): fp16 region read by ctx
    float* row = attn + (size_t)rid * Ss;
    __half* rh = ah + (size_t)rid * Ss;
    __half* rl = al + (size_t)rid * Ss;
    __shared__ float red[256];
    int tid = threadIdx.x;
    int base = tid * 8;
    float4 ra = *(const float4*)(row + base);
    float4 rb = *(const float4*)(row + base + 4);
    float r[8] = {ra.x, ra.y, ra.z, ra.w, rb.x, rb.y, rb.z, rb.w};
    float mx = -3.4e38f;
#pragma unroll
    for (int t = 0; t < 8; t++) {
        if (base + t >= L) r[t] = -3.4e38f;
        mx = fmaxf(mx, r[t]);
    }
    red[tid] = mx; __syncthreads();
    for (int o = 128; o > 0; o >>= 1) { if (tid < o) red[tid] = fmaxf(red[tid], red[tid + o]); __syncthreads(); }
    mx = red[0]; __syncthreads();
    float s = 0.f;
#pragma unroll
    for (int t = 0; t < 8; t++) {
        float e = (base + t < L) ? expf(r[t] - mx) : 0.0f;
        r[t] = e; s += e;
    }
    red[tid] = s; __syncthreads();
    for (int o = 128; o > 0; o >>= 1) { if (tid < o) red[tid] += red[tid + o]; __syncthreads(); }
    float inv = 1.0f / red[0];
#pragma unroll
    for (int t = 0; t < 8; t++) r[t] *= inv;
    // fp32 graded output (zeros above diagonal), vectorized
    *(float4*)(row + base)     = make_float4(r[0], r[1], r[2], r[3]);
    *(float4*)(row + base + 4) = make_float4(r[4], r[5], r[6], r[7]);
    // fp16 hi/lo: only the region ctx reads (Lpad multiple of 128, base multiple of 8)
    if (base < Lpad) {
        __half2 hh[4], ll[4];
#pragma unroll
        for (int j = 0; j < 4; j++) {
            __half h0 = __float2half_rn(r[2 * j]), h1 = __float2half_rn(r[2 * j + 1]);
            hh[j] = __halves2half2(h0, h1);
            ll[j] = __floats2half2_rn(r[2 * j] - __half2float(h0), r[2 * j + 1] - __half2float(h1));
        }
        *(uint4*)(rh + base) = *(uint4*)hh;
        *(uint4*)(rl + base) = *(uint4*)ll;
    }
}

// ================= launch =================
extern "C" void kernel_launch(void* const* d_in, const int* in_sizes, int n_in,
                              void* d_out, int out_size)
{
    const float* hs   = (const float*)d_in[0];
    const int*   pid  = (const int*)  d_in[1];
    const float* wq   = (const float*)d_in[2];
    const float* wk   = (const float*)d_in[3];
    const float* wv   = (const float*)d_in[4];
    const float* wo   = (const float*)d_in[5];
    const float* ln1g = (const float*)d_in[6];
    const float* ln1b = (const float*)d_in[7];
    const float* ln2g = (const float*)d_in[8];
    const float* ln2b = (const float*)d_in[9];
    const float* fiw  = (const float*)d_in[10];
    const float* fib  = (const float*)d_in[11];
    const float* fow  = (const float*)d_in[12];
    const float* fob  = (const float*)d_in[13];

    float* out  = (float*)d_out;
    float* attn = out + (size_t)ROWS * Dd;

    float *aproj, *h2;
    bf16 *h1h, *h1l, *wqkh, *wqkl, *qkh, *qkl;
    __half *h116, *wvt, *wof, *fif, *fof, *v16, *vt16, *ah16, *al16;
    __half *ctxh16, *ctxl16, *h216, *ffn16;
    cudaGetSymbolAddress((void**)&aproj,  g_aproj);
    cudaGetSymbolAddress((void**)&h2,     g_h2);
    cudaGetSymbolAddress((void**)&h1h,    g_h1h);
    cudaGetSymbolAddress((void**)&h1l,    g_h1l);
    cudaGetSymbolAddress((void**)&h116,   g_h116);
    cudaGetSymbolAddress((void**)&wqkh,   g_wqkh);
    cudaGetSymbolAddress((void**)&wqkl,   g_wqkl);
    cudaGetSymbolAddress((void**)&wvt,    g_wvt16);
    cudaGetSymbolAddress((void**)&wof,    g_wof16);
    cudaGetSymbolAddress((void**)&fif,    g_fif16);
    cudaGetSymbolAddress((void**)&fof,    g_fof16);
    cudaGetSymbolAddress((void**)&qkh,    g_qkh);
    cudaGetSymbolAddress((void**)&qkl,    g_qkl);
    cudaGetSymbolAddress((void**)&v16,    g_v16);
    cudaGetSymbolAddress((void**)&vt16,   g_vt16);
    cudaGetSymbolAddress((void**)&ah16,   g_ah16);
    cudaGetSymbolAddress((void**)&al16,   g_al16);
    cudaGetSymbolAddress((void**)&ctxh16, g_ctxh16);
    cudaGetSymbolAddress((void**)&ctxl16, g_ctxl16);
    cudaGetSymbolAddress((void**)&h216,   g_h216);
    cudaGetSymbolAddress((void**)&ffn16,  g_ffn16);

    const uint32_t SMT256_0 = 3u * (2u * PPA + 2u * 256u * 80u);   // 184320
    const uint32_t SMT128_1 = 3u * (2u * PPA + 1u * 128u * 80u);   // 92160
    const uint32_t SMT128_2 = 3u * (1u * PPA + 1u * 128u * 80u);   // 61440
    cudaFuncSetAttribute((const void*)gemm_mp<256, 0, 1>, cudaFuncAttributeMaxDynamicSharedMemorySize, SMT256_0);
    cudaFuncSetAttribute((const void*)gemm_mp<128, 1, 2>, cudaFuncAttributeMaxDynamicSharedMemorySize, SMT128_1);
    cudaFuncSetAttribute((const void*)gemm_mp<128, 2, 2>, cudaFuncAttributeMaxDynamicSharedMemorySize, SMT128_2);

    // fused prep: all weight transposes + rope table in one launch
    prep_kernel<<<25088, 256>>>(wq, wk, wv, wo, fiw, fow,
                                wqkh, wqkl, wvt, wof, fif, fof);

    // ln1 -> bf16 hi/lo (for qk) + fp16 single (for v)
    ln_kernel<<<ROWS, 256>>>(hs, nullptr, ln1g, ln1b, nullptr, h1h, h1l, h116);

    // qk projection (bf16x3, RoPE in epilogue); v projection (fp16x1, fp16 out)
    gemm_mp<256, 0, 1><<<dim3(16, 32), 256, SMT256_0>>>(h1h, h1l, wqkh, wqkl,
        nullptr, nullptr, nullptr, qkh, qkl, pid, Dd, Dd, Dd, Dd, 8);
    gemm_mp<128, 2, 2><<<dim3(16, 32), 256, SMT128_2>>>(h116, nullptr, wvt, nullptr,
        nullptr, nullptr, nullptr, v16, nullptr, nullptr, Dd, Dd, Dd, Dd, 512);

    dim3 tb(32, 8);
    vtrans_h<<<dim3(DHd / 32, Ss / 64, Bb * Hh), tb>>>(v16, vt16);

    // scores (bf16x3, causal) -> softmax(+fp16 split) -> ctx (fp16x2, global desc order)
    gemm_mp<256, 0, 1><<<dim3(8, 16, Bb * Hh), 256, SMT256_0>>>(qkh, qkl,
        qkh + (size_t)ROWS * Dd, qkl + (size_t)ROWS * Dd,
        nullptr, nullptr, attn, nullptr, nullptr, nullptr, DHd, Dd, Dd, Ss, 16);
    softmax_kernel<<<Bb * Hh * Ss, 256>>>(attn, ah16, al16);
    gemm_mp<128, 1, 2><<<dim3(Bb * Hh, 16), 256, SMT128_1>>>(ah16, al16, vt16, nullptr,
        nullptr, nullptr, nullptr, ctxh16, ctxl16, nullptr, Ss, Ss, Ss, Dd, 32 | 256);

    // output projection (fp16x2)
    gemm_mp<128, 1, 2><<<dim3(16, 32), 256, SMT128_1>>>(ctxh16, ctxl16, wof, nullptr,
        nullptr, nullptr, aproj, nullptr, nullptr, nullptr, Dd, Dd, Dd, Dd, 0);

    // ln2 -> fp32 + fp16 single
    ln_kernel<<<ROWS, 256>>>(hs, aproj, ln2g, ln2b, h2, nullptr, nullptr, h216);

    // FFN (fp16x1)
    gemm_mp<128, 2, 2><<<dim3(64, 32), 256, SMT128_2>>>(h216, nullptr, fif, nullptr,
        fib, nullptr, nullptr, ffn16, nullptr, nullptr, Dd, Dd, Dd, FFf, 1 | 2 | 512);
    gemm_mp<128, 2, 2><<<dim3(16, 32), 256, SMT128_2>>>(ffn16, nullptr, fof, nullptr,
        fob, h2, out, nullptr, nullptr, nullptr, FFf, FFf, FFf, Dd, 1 | 4);
}

// round 12
// speedup vs baseline: 1.8683x; 1.0027x over previous
#include <cuda_runtime.h>
#include <cuda_bf16.h>
#include <cuda_fp16.h>
#include <math.h>
#include <stdint.h>

#define Bb   2
#define Ss   2048
#define Dd   2048
#define Hh   16
#define DHd  128
#define FFf  8192
#define ROWS 4096   // B*S

typedef __nv_bfloat16 bf16;

// ================= scratch (device globals) =================
__device__ bf16  g_h1h[(size_t)ROWS * Dd],  g_h1l[(size_t)ROWS * Dd];
__device__ __half g_h116[(size_t)ROWS * Dd];
__device__ bf16  g_wqkh[(size_t)2 * Dd * Dd], g_wqkl[(size_t)2 * Dd * Dd];
__device__ __half g_wvt16[(size_t)Dd * Dd];
__device__ __half g_wof16[(size_t)Dd * Dd];
__device__ __half g_fif16[(size_t)Dd * FFf];
__device__ __half g_fof16[(size_t)Dd * FFf];
__device__ bf16  g_qkh[(size_t)2 * ROWS * Dd], g_qkl[(size_t)2 * ROWS * Dd];
__device__ __half g_v16[(size_t)ROWS * Dd];
__device__ __half g_vt16[(size_t)Bb * Hh * DHd * Ss];
__device__ __half g_ah16[(size_t)Bb * Hh * Ss * Ss], g_al16[(size_t)Bb * Hh * Ss * Ss];
__device__ __half g_ctxh16[(size_t)ROWS * Dd], g_ctxl16[(size_t)ROWS * Dd];
__device__ float g_aproj[(size_t)ROWS * Dd];
__device__ float g_h2[(size_t)ROWS * Dd];
__device__ __half g_h216[(size_t)ROWS * Dd];
__device__ __half g_ffn16[(size_t)ROWS * FFf];
__device__ float g_sin[Ss * 64];
__device__ float g_cos[Ss * 64];

// ================= helpers =================
__device__ __forceinline__ uint32_t smem_u32(const void* p) {
    uint32_t a;
    asm("{ .reg .u64 t; cvta.to.shared.u64 t, %1; cvt.u32.u64 %0, t; }" : "=r"(a) : "l"(p));
    return a;
}
__device__ __forceinline__ void ldm4(uint32_t* r, uint32_t addr) {
    asm volatile("ldmatrix.sync.aligned.m8n8.x4.shared.b16 {%0,%1,%2,%3}, [%4];"
        : "=r"(r[0]), "=r"(r[1]), "=r"(r[2]), "=r"(r[3]) : "r"(addr));
}
__device__ __forceinline__ void mma_bf16(float* c, const uint32_t* a, const uint32_t* b) {
    asm volatile(
        "mma.sync.aligned.m16n8k16.row.col.f32.bf16.bf16.f32 "
        "{%0,%1,%2,%3}, {%4,%5,%6,%7}, {%8,%9}, {%0,%1,%2,%3};"
        : "+f"(c[0]), "+f"(c[1]), "+f"(c[2]), "+f"(c[3])
        : "r"(a[0]), "r"(a[1]), "r"(a[2]), "r"(a[3]), "r"(b[0]), "r"(b[1]));
}
__device__ __forceinline__ void mma_fp16(float* c, const uint32_t* a, const uint32_t* b) {
    asm volatile(
        "mma.sync.aligned.m16n8k16.row.col.f32.f16.f16.f32 "
        "{%0,%1,%2,%3}, {%4,%5,%6,%7}, {%8,%9}, {%0,%1,%2,%3};"
        : "+f"(c[0]), "+f"(c[1]), "+f"(c[2]), "+f"(c[3])
        : "r"(a[0]), "r"(a[1]), "r"(a[2]), "r"(a[3]), "r"(b[0]), "r"(b[1]));
}
__device__ __forceinline__ void cp16(uint32_t dst, const void* src) {
    asm volatile("cp.async.cg.shared.global [%0], [%1], 16;" :: "r"(dst), "l"(src));
}
__device__ __forceinline__ void cp_commit() { asm volatile("cp.async.commit_group;"); }
__device__ __forceinline__ void cp_wait2() { asm volatile("cp.async.wait_group 2;"); }
__device__ __forceinline__ void cp_wait1() { asm volatile("cp.async.wait_group 1;"); }
__device__ __forceinline__ void cp_wait0() { asm volatile("cp.async.wait_group 0;"); }

__device__ __forceinline__ void split2(float x, float y, bf16* ph, bf16* pl) {
    bf16 hx = __float2bfloat16_rn(x), hy = __float2bfloat16_rn(y);
    float fx = __bfloat162float(hx), fy = __bfloat162float(hy);
    __nv_bfloat162 h2; h2.x = hx; h2.y = hy;
    __nv_bfloat162 l2; l2.x = __float2bfloat16_rn(x - fx); l2.y = __float2bfloat16_rn(y - fy);
    *(__nv_bfloat162*)ph = h2;
    *(__nv_bfloat162*)pl = l2;
}
__device__ __forceinline__ void split2h(float x, float y, __half* ph, __half* pl) {
    __half hx = __float2half_rn(x), hy = __float2half_rn(y);
    __half2 h2 = __halves2half2(hx, hy);
    __half2 l2 = __floats2half2_rn(x - __half2float(hx), y - __half2float(hy));
    *(__half2*)ph = h2;
    *(__half2*)pl = l2;
}

// ================= fused prep: 6 weight transposes + rope table =================
__device__ __forceinline__ void dev_tsplit(
    float (*t)[33], const float* __restrict__ in,
    bf16* __restrict__ oh, bf16* __restrict__ ol,
    int R, int Cc, int bxb, int byb)
{
    int bx = bxb * 32, by = byb * 64;
    int tx = threadIdx.x & 31, ty = threadIdx.x >> 5;
#pragma unroll
    for (int i = 0; i < 64; i += 8)
        t[ty + i][tx] = in[(size_t)(by + ty + i) * Cc + bx + tx];
    __syncthreads();
#pragma unroll
    for (int i = 0; i < 32; i += 8) {
        int r = ty + i;
        size_t o = (size_t)(bx + r) * R + by + 2 * tx;
        split2(t[2 * tx][r], t[2 * tx + 1][r], oh + o, ol + o);
    }
}
__device__ __forceinline__ void dev_tfp16(
    float (*t)[33], const float* __restrict__ in, __half* __restrict__ oh,
    int R, int Cc, int bxb, int byb)
{
    int bx = bxb * 32, by = byb * 64;
    int tx = threadIdx.x & 31, ty = threadIdx.x >> 5;
#pragma unroll
    for (int i = 0; i < 64; i += 8)
        t[ty + i][tx] = in[(size_t)(by + ty + i) * Cc + bx + tx];
    __syncthreads();
#pragma unroll
    for (int i = 0; i < 32; i += 8) {
        int r = ty + i;
        __half2 h2 = __floats2half2_rn(t[2 * tx][r], t[2 * tx + 1][r]);
        *(__half2*)(oh + (size_t)(bx + r) * R + by + 2 * tx) = h2;
    }
}

__global__ __launch_bounds__(256) void prep_kernel(
    const float* __restrict__ wq, const float* __restrict__ wk,
    const float* __restrict__ wv, const float* __restrict__ wo,
    const float* __restrict__ fiw, const float* __restrict__ fow,
    bf16* __restrict__ wqkh, bf16* __restrict__ wqkl,
    __half* __restrict__ wvt, __half* __restrict__ wof,
    __half* __restrict__ fif, __half* __restrict__ fof)
{
    __shared__ float t[64][33];
    int id = blockIdx.x;
    if (id < 2048) {
        dev_tsplit(t, wq, wqkh, wqkl, Dd, Dd, id & 63, id >> 6);
    } else if (id < 4096) {
        id -= 2048;
        dev_tsplit(t, wk, wqkh + (size_t)Dd * Dd, wqkl + (size_t)Dd * Dd, Dd, Dd, id & 63, id >> 6);
    } else if (id < 6144) {
        id -= 4096;
        dev_tfp16(t, wv, wvt, Dd, Dd, id & 63, id >> 6);
    } else if (id < 8192) {
        id -= 6144;
        dev_tfp16(t, wo, wof, Dd, Dd, id & 63, id >> 6);
    } else if (id < 16384) {
        id -= 8192;
        dev_tfp16(t, fiw, fif, Dd, FFf, id & 255, id >> 8);
    } else if (id < 24576) {
        id -= 16384;
        dev_tfp16(t, fow, fof, FFf, Dd, id & 63, id >> 6);
    } else {
        int tt = (id - 24576) * 256 + threadIdx.x;
        int p = tt >> 6, i = tt & 63;
        double inv = pow(10000.0, -((double)(2 * i)) / 128.0);
        float ang = (float)p * (float)inv;
        g_sin[tt] = (float)sin((double)ang);
        g_cos[tt] = (float)cos((double)ang);
    }
}

// V^T per head, fp16 in/out
__global__ __launch_bounds__(256) void vtrans_h(
    const __half* __restrict__ v, __half* __restrict__ oh)
{
    __shared__ float t[64][33];
    int bh = blockIdx.z;
    int b = bh >> 4, h = bh & 15;
    const __half* in = v + (size_t)b * Ss * Dd + h * DHd;
    size_t obase = (size_t)bh * DHd * Ss;
    int n0 = blockIdx.x * 32, s0 = blockIdx.y * 64;
    int tx = threadIdx.x, ty = threadIdx.y;
#pragma unroll
    for (int i = 0; i < 64; i += 8)
        t[ty + i][tx] = __half2float(in[(size_t)(s0 + ty + i) * Dd + n0 + tx]);
    __syncthreads();
#pragma unroll
    for (int i = 0; i < 32; i += 8) {
        int r = ty + i;
        __half2 h2 = __floats2half2_rn(t[2 * tx][r], t[2 * tx + 1][r]);
        *(__half2*)(oh + obase + (size_t)(n0 + r) * Ss + s0 + 2 * tx) = h2;
    }
}

// ================= LayerNorm =================
__global__ __launch_bounds__(256) void ln_kernel(
    const float* __restrict__ x, const float* __restrict__ x2,
    const float* __restrict__ g, const float* __restrict__ bta,
    float* __restrict__ outf, bf16* __restrict__ outh, bf16* __restrict__ outl,
    __half* __restrict__ o16)
{
    __shared__ float red[256];
    int row = blockIdx.x, tid = threadIdx.x;
    size_t base = (size_t)row * Dd;
    float r[8];
    float s = 0.f;
#pragma unroll
    for (int t = 0; t < 8; t++) {
        int i = tid + t * 256;
        float v = x[base + i];
        if (x2) v += x2[base + i];
        r[t] = v; s += v;
    }
    red[tid] = s; __syncthreads();
    for (int o = 128; o > 0; o >>= 1) { if (tid < o) red[tid] += red[tid + o]; __syncthreads(); }
    float mean = red[0] * (1.0f / Dd);
    __syncthreads();
    float vs = 0.f;
#pragma unroll
    for (int t = 0; t < 8; t++) { float d = r[t] - mean; vs += d * d; }
    red[tid] = vs; __syncthreads();
    for (int o = 128; o > 0; o >>= 1) { if (tid < o) red[tid] += red[tid + o]; __syncthreads(); }
    float var = red[0] * (1.0f / Dd);
    float rs = rsqrtf(var + 1e-5f);
#pragma unroll
    for (int t = 0; t < 8; t++) {
        int i = tid + t * 256;
        float v = (r[t] - mean) * rs * g[i] + bta[i];
        if (outf) outf[base + i] = v;
        if (outh) {
            bf16 h = __float2bfloat16_rn(v);
            outh[base + i] = h;
            outl[base + i] = __float2bfloat16_rn(v - __bfloat162float(h));
        }
        if (o16) o16[base + i] = __float2half_rn(v);
    }
}

// ================= mixed-precision mma.sync GEMM =================
// MODE 0: bf16x3. MODE 1: fp16x2. MODE 2: fp16x1.
// flags: 1=bias 2=gelu 4=resid 8=qkv(rope+scatter) 16=score 32=ctx
//        64=bf16 hi/lo out 256=fp16 hi/lo out 512=fp16 single out
#define PPA 10240u            // A part bytes (128 rows * 80B)

template<int BN, int MODE, int MINCTAS, int NSTG>
__global__ __launch_bounds__(256, MINCTAS) void gemm_mp(
    const void* __restrict__ Ahv, const void* __restrict__ Alv,
    const void* __restrict__ Bhv, const void* __restrict__ Blv,
    const float* __restrict__ bias, const float* __restrict__ resid,
    float* __restrict__ Cf, void* __restrict__ Chv, void* __restrict__ Clv,
    const int* __restrict__ pid,
    int K, int lda, int ldb, int ldc, int flags)
{
    constexpr uint32_t PPB = (uint32_t)BN * 80u;
    constexpr uint32_t APARTS = (MODE == 2) ? 1u : 2u;
    constexpr uint32_t BPARTS = (MODE == 0) ? 2u : 1u;
    constexpr uint32_t STG = APARTS * PPA + BPARTS * PPB;
    constexpr int NFR = BN / 32;
    constexpr int NPAIR = NFR / 2;
    extern __shared__ char sm[];
    int bx = blockIdx.x, by = blockIdx.y, bz = blockIdx.z;
    const uint16_t* Ahp = (const uint16_t*)Ahv;
    const uint16_t* Alp = (const uint16_t*)Alv;
    const uint16_t* Bhp = (const uint16_t*)Bhv;
    const uint16_t* Blp = (const uint16_t*)Blv;
    float* Cfp = Cf;
    uint16_t* Chp = (uint16_t*)Chv;
    uint16_t* Clp = (uint16_t*)Clv;
    int Keff = K;
    if (flags & 16) {
        if (bx * BN > by * 128 + 127) return;
        int b = bz >> 4, h = bz & 15;
        size_t ao = (size_t)b * Ss * Dd + h * DHd;
        Ahp += ao; Alp += ao; Bhp += ao; Blp += ao;
        Cfp += (size_t)bz * Ss * Ss;
    }
    if (flags & 32) {
        bz = blockIdx.x;
        by = gridDim.y - 1 - blockIdx.y;
        bx = 0;
        int b = bz >> 4, h = bz & 15;
        size_t ao = (size_t)bz * Ss * Ss;
        size_t bo = (size_t)bz * DHd * Ss;
        Ahp += ao; Alp += ao; Bhp += bo; Blp += bo;
        size_t co = (size_t)b * Ss * Dd + h * DHd;
        Chp += co; Clp += co;
        Keff = (by + 1) * 128;
    }
    const int tid = threadIdx.x, lane = tid & 31, warp = tid >> 5;
    const int m0 = by * 128, n0 = bx * BN;
    const int wm = (warp >> 2) * 64, wn = (warp & 3) * (BN / 4);
    const uint32_t sbase = smem_u32(sm);

    float acc[4][NFR][4];
#pragma unroll
    for (int i = 0; i < 4; i++)
#pragma unroll
        for (int j = 0; j < NFR; j++)
#pragma unroll
            for (int e = 0; e < 4; e++) acc[i][j][e] = 0.f;

#define ISSUE_CHUNK(ST, K0) do { \
    uint32_t sb0 = sbase + (uint32_t)(ST) * STG; \
    _Pragma("unroll") \
    for (int i = 0; i < 2; i++) { \
        int idx = tid + i * 256; \
        int r = idx >> 2; int cc = idx & 3; \
        uint32_t d = sb0 + (uint32_t)r * 80u + (uint32_t)cc * 16u; \
        size_t sa = (size_t)(m0 + r) * lda + (K0) + cc * 8; \
        cp16(d, Ahp + sa); \
        if (MODE != 2) cp16(d + PPA, Alp + sa); \
    } \
    _Pragma("unroll") \
    for (int i = 0; i < BN / 64; i++) { \
        int idx = tid + i * 256; \
        int r = idx >> 2; int cc = idx & 3; \
        uint32_t d = sb0 + APARTS * PPA + (uint32_t)r * 80u + (uint32_t)cc * 16u; \
        size_t sb2 = (size_t)(n0 + r) * ldb + (K0) + cc * 8; \
        cp16(d, Bhp + sb2); \
        if (MODE == 0) cp16(d + PPB, Blp + sb2); \
    } \
    cp_commit(); \
} while(0)

    const int nch = Keff / 32;
#pragma unroll
    for (int s = 0; s < NSTG - 1; s++)
        if (s < nch) ISSUE_CHUNK(s, s * 32);

    const uint32_t a_lane_off = (uint32_t)(wm + (lane & 15)) * 80u + (uint32_t)((lane >> 4) * 16);
    // B x4 pairing: lanes 0-15 -> rows wn..wn+7 (k lo / k hi), lanes 16-31 -> rows wn+8..wn+15
    const uint32_t b_lane_off = (uint32_t)(wn + ((lane >> 4) * 8) + (lane & 7)) * 80u
                              + (uint32_t)(((lane >> 3) & 1) * 16);

    for (int c = 0; c < nch; c++) {
        int rem = nch - 1 - c;
        if (NSTG >= 4 && rem >= 2) cp_wait2();
        else if (rem >= 1) cp_wait1();
        else cp_wait0();
        __syncthreads();
        const uint32_t boff = (uint32_t)(c % NSTG) * STG;
#pragma unroll
        for (int ks = 0; ks < 2; ks++) {
            uint32_t ahi[4][4], alo[4][4];
            uint32_t abase = sbase + boff + a_lane_off + (uint32_t)(ks * 32);
            uint32_t bbase = sbase + boff + APARTS * PPA + b_lane_off + (uint32_t)(ks * 32);
#pragma unroll
            for (int mti = 0; mti < 4; mti++) {
                ldm4(ahi[mti], abase + (uint32_t)(mti * 16) * 80u);
                if (MODE != 2) ldm4(alo[mti], abase + (uint32_t)(mti * 16) * 80u + PPA);
            }
#pragma unroll
            for (int p = 0; p < NPAIR; p++) {
                uint32_t bh4[4];
                ldm4(bh4, bbase + (uint32_t)(p * 16) * 80u);   // 2 frags: ntj=2p, 2p+1
                if (MODE == 0) {
                    uint32_t bl4[4];
                    ldm4(bl4, bbase + (uint32_t)(p * 16) * 80u + PPB);
#pragma unroll
                    for (int mti = 0; mti < 4; mti++) {
                        mma_bf16(acc[mti][2 * p],     ahi[mti], bh4);
                        mma_bf16(acc[mti][2 * p + 1], ahi[mti], bh4 + 2);
                    }
#pragma unroll
                    for (int mti = 0; mti < 4; mti++) {
                        mma_bf16(acc[mti][2 * p],     ahi[mti], bl4);
                        mma_bf16(acc[mti][2 * p + 1], ahi[mti], bl4 + 2);
                    }
#pragma unroll
                    for (int mti = 0; mti < 4; mti++) {
                        mma_bf16(acc[mti][2 * p],     alo[mti], bh4);
                        mma_bf16(acc[mti][2 * p + 1], alo[mti], bh4 + 2);
                    }
                } else if (MODE == 1) {
#pragma unroll
                    for (int mti = 0; mti < 4; mti++) {
                        mma_fp16(acc[mti][2 * p],     ahi[mti], bh4);
                        mma_fp16(acc[mti][2 * p + 1], ahi[mti], bh4 + 2);
                    }
#pragma unroll
                    for (int mti = 0; mti < 4; mti++) {
                        mma_fp16(acc[mti][2 * p],     alo[mti], bh4);
                        mma_fp16(acc[mti][2 * p + 1], alo[mti], bh4 + 2);
                    }
                } else {
#pragma unroll
                    for (int mti = 0; mti < 4; mti++) {
                        mma_fp16(acc[mti][2 * p],     ahi[mti], bh4);
                        mma_fp16(acc[mti][2 * p + 1], ahi[mti], bh4 + 2);
                    }
                }
            }
        }
        if (c + NSTG - 1 < nch) ISSUE_CHUNK((c + NSTG - 1) % NSTG, (c + NSTG - 1) * 32);
    }
#undef ISSUE_CHUNK

    // ---------------- epilogue ----------------
#pragma unroll
    for (int mti = 0; mti < 4; mti++) {
#pragma unroll
        for (int ntj = 0; ntj < NFR; ntj++) {
            int row = m0 + wm + mti * 16 + (lane >> 2);
            int col = n0 + wn + ntj * 8 + (lane & 3) * 2;
#pragma unroll
            for (int half = 0; half < 2; half++) {
                int rr = row + half * 8;
                float v0 = acc[mti][ntj][half * 2];
                float v1 = acc[mti][ntj][half * 2 + 1];
                if (flags & 1) { v0 += bias[col]; v1 += bias[col + 1]; }
                if (flags & 2) {
                    v0 = 0.5f * v0 * (1.0f + erff(v0 * 0.70710678118654752f));
                    v1 = 0.5f * v1 * (1.0f + erff(v1 * 0.70710678118654752f));
                }
                if (flags & 4) {
                    const float* rp = resid + (size_t)rr * ldc + col;
                    v0 += rp[0]; v1 += rp[1];
                }
                if (flags & 8) {
                    int sel = col >> 11, cl = col & 2047;
                    int b = rr >> 11, s = rr & 2047;
                    int pos = pid[b * Ss + s];
                    int i = (cl & 127) >> 1;
                    float sn = g_sin[pos * 64 + i], cs = g_cos[pos * 64 + i];
                    float r0 = v0 * cs - v1 * sn;
                    float r1 = v1 * cs + v0 * sn;
                    size_t o = (size_t)(sel * ROWS + rr) * Dd + cl;
                    split2(r0, r1, (bf16*)(Chp + o), (bf16*)(Clp + o));
                } else if (flags & 64) {
                    size_t o = (size_t)rr * ldc + col;
                    split2(v0, v1, (bf16*)(Chp + o), (bf16*)(Clp + o));
                } else if (flags & 256) {
                    size_t o = (size_t)rr * ldc + col;
                    split2h(v0, v1, (__half*)(Chp + o), (__half*)(Clp + o));
                } else if (flags & 512) {
                    size_t o = (size_t)rr * ldc + col;
                    *(__half2*)((__half*)Chp + o) = __floats2half2_rn(v0, v1);
                } else {
                    *(float2*)(Cfp + (size_t)rr * ldc + col) = make_float2(v0, v1);
                }
            }
        }
    }
}

// ================= row softmax (causal trunc, vectorized) + fp16 split out =================
__global__ __launch_bounds__(256) void softmax_kernel(
    float* __restrict__ attn, __half* __restrict__ ah, __half* __restrict__ al)
{
    int rid = blockIdx.x;
    int qpos = rid & (Ss - 1);
    int L = qpos + 1;
    int Lpad = ((qpos >> 7) + 1) << 7;
    float* row = attn + (size_t)rid * Ss;
    __half* rh = ah + (size_t)rid * Ss;
    __half* rl = al + (size_t)rid * Ss;
    __shared__ float red[256];
    int tid = threadIdx.x;
    int base = tid * 8;
    float4 ra = *(const float4*)(row + base);
    float4 rb = *(const float4*)(row + base + 4);
    float r[8] = {ra.x, ra.y, ra.z, ra.w, rb.x, rb.y, rb.z, rb.w};
    float mx = -3.4e38f;
#pragma unroll
    for (int t = 0; t < 8; t++) {
        if (base + t >= L) r[t] = -3.4e38f;
        mx = fmaxf(mx, r[t]);
    }
    red[tid] = mx; __syncthreads();
    for (int o = 128; o > 0; o >>= 1) { if (tid < o) red[tid] = fmaxf(red[tid], red[tid + o]); __syncthreads(); }
    mx = red[0]; __syncthreads();
    float s = 0.f;
#pragma unroll
    for (int t = 0; t < 8; t++) {
        float e = (base + t < L) ? expf(r[t] - mx) : 0.0f;
        r[t] = e; s += e;
    }
    red[tid] = s; __syncthreads();
    for (int o = 128; o > 0; o >>= 1) { if (tid < o) red[tid] += red[tid + o]; __syncthreads(); }
    float inv = 1.0f / red[0];
#pragma unroll
    for (int t = 0; t < 8; t++) r[t] *= inv;
    *(float4*)(row + base)     = make_float4(r[0], r[1], r[2], r[3]);
    *(float4*)(row + base + 4) = make_float4(r[4], r[5], r[6], r[7]);
    if (base < Lpad) {
        __half2 hh[4], ll[4];
#pragma unroll
        for (int j = 0; j < 4; j++) {
            __half h0 = __float2half_rn(r[2 * j]), h1 = __float2half_rn(r[2 * j + 1]);
            hh[j] = __halves2half2(h0, h1);
            ll[j] = __floats2half2_rn(r[2 * j] - __half2float(h0), r[2 * j + 1] - __half2float(h1));
        }
        *(uint4*)(rh + base) = *(uint4*)hh;
        *(uint4*)(rl + base) = *(uint4*)ll;
    }
}

// ================= launch =================
extern "C" void kernel_launch(void* const* d_in, const int* in_sizes, int n_in,
                              void* d_out, int out_size)
{
    const float* hs   = (const float*)d_in[0];
    const int*   pid  = (const int*)  d_in[1];
    const float* wq   = (const float*)d_in[2];
    const float* wk   = (const float*)d_in[3];
    const float* wv   = (const float*)d_in[4];
    const float* wo   = (const float*)d_in[5];
    const float* ln1g = (const float*)d_in[6];
    const float* ln1b = (const float*)d_in[7];
    const float* ln2g = (const float*)d_in[8];
    const float* ln2b = (const float*)d_in[9];
    const float* fiw  = (const float*)d_in[10];
    const float* fib  = (const float*)d_in[11];
    const float* fow  = (const float*)d_in[12];
    const float* fob  = (const float*)d_in[13];

    float* out  = (float*)d_out;
    float* attn = out + (size_t)ROWS * Dd;

    float *aproj, *h2;
    bf16 *h1h, *h1l, *wqkh, *wqkl, *qkh, *qkl;
    __half *h116, *wvt, *wof, *fif, *fof, *v16, *vt16, *ah16, *al16;
    __half *ctxh16, *ctxl16, *h216, *ffn16;
    cudaGetSymbolAddress((void**)&aproj,  g_aproj);
    cudaGetSymbolAddress((void**)&h2,     g_h2);
    cudaGetSymbolAddress((void**)&h1h,    g_h1h);
    cudaGetSymbolAddress((void**)&h1l,    g_h1l);
    cudaGetSymbolAddress((void**)&h116,   g_h116);
    cudaGetSymbolAddress((void**)&wqkh,   g_wqkh);
    cudaGetSymbolAddress((void**)&wqkl,   g_wqkl);
    cudaGetSymbolAddress((void**)&wvt,    g_wvt16);
    cudaGetSymbolAddress((void**)&wof,    g_wof16);
    cudaGetSymbolAddress((void**)&fif,    g_fif16);
    cudaGetSymbolAddress((void**)&fof,    g_fof16);
    cudaGetSymbolAddress((void**)&qkh,    g_qkh);
    cudaGetSymbolAddress((void**)&qkl,    g_qkl);
    cudaGetSymbolAddress((void**)&v16,    g_v16);
    cudaGetSymbolAddress((void**)&vt16,   g_vt16);
    cudaGetSymbolAddress((void**)&ah16,   g_ah16);
    cudaGetSymbolAddress((void**)&al16,   g_al16);
    cudaGetSymbolAddress((void**)&ctxh16, g_ctxh16);
    cudaGetSymbolAddress((void**)&ctxl16, g_ctxl16);
    cudaGetSymbolAddress((void**)&h216,   g_h216);
    cudaGetSymbolAddress((void**)&ffn16,  g_ffn16);

    const uint32_t SMT256_0 = 3u * (2u * PPA + 2u * 256u * 80u);   // 184320, 1 CTA
    const uint32_t SMT128_1 = 3u * (2u * PPA + 1u * 128u * 80u);   // 92160, 2 CTAs
    const uint32_t SMT128_2 = 4u * (1u * PPA + 1u * 128u * 80u);   // 81920, 2 CTAs
    cudaFuncSetAttribute((const void*)gemm_mp<256, 0, 1, 3>, cudaFuncAttributeMaxDynamicSharedMemorySize, SMT256_0);
    cudaFuncSetAttribute((const void*)gemm_mp<128, 1, 2, 3>, cudaFuncAttributeMaxDynamicSharedMemorySize, SMT128_1);
    cudaFuncSetAttribute((const void*)gemm_mp<128, 2, 2, 4>, cudaFuncAttributeMaxDynamicSharedMemorySize, SMT128_2);

    // fused prep: all weight transposes + rope table in one launch
    prep_kernel<<<25088, 256>>>(wq, wk, wv, wo, fiw, fow,
                                wqkh, wqkl, wvt, wof, fif, fof);

    // ln1 -> bf16 hi/lo (for qk) + fp16 single (for v)
    ln_kernel<<<ROWS, 256>>>(hs, nullptr, ln1g, ln1b, nullptr, h1h, h1l, h116);

    // qk projection (bf16x3, RoPE in epilogue); v projection (fp16x1, fp16 out)
    gemm_mp<256, 0, 1, 3><<<dim3(16, 32), 256, SMT256_0>>>(h1h, h1l, wqkh, wqkl,
        nullptr, nullptr, nullptr, qkh, qkl, pid, Dd, Dd, Dd, Dd, 8);
    gemm_mp<128, 2, 2, 4><<<dim3(16, 32), 256, SMT128_2>>>(h116, nullptr, wvt, nullptr,
        nullptr, nullptr, nullptr, v16, nullptr, nullptr, Dd, Dd, Dd, Dd, 512);

    dim3 tb(32, 8);
    vtrans_h<<<dim3(DHd / 32, Ss / 64, Bb * Hh), tb>>>(v16, vt16);

    // scores (bf16x3, causal) -> softmax(+fp16 split) -> ctx (fp16x2, global desc order)
    gemm_mp<256, 0, 1, 3><<<dim3(8, 16, Bb * Hh), 256, SMT256_0>>>(qkh, qkl,
        qkh + (size_t)ROWS * Dd, qkl + (size_t)ROWS * Dd,
        nullptr, nullptr, attn, nullptr, nullptr, nullptr, DHd, Dd, Dd, Ss, 16);
    softmax_kernel<<<Bb * Hh * Ss, 256>>>(attn, ah16, al16);
    gemm_mp<128, 1, 2, 3><<<dim3(Bb * Hh, 16), 256, SMT128_1>>>(ah16, al16, vt16, nullptr,
        nullptr, nullptr, nullptr, ctxh16, ctxl16, nullptr, Ss, Ss, Ss, Dd, 32 | 256);

    // output projection (fp16x2)
    gemm_mp<128, 1, 2, 3><<<dim3(16, 32), 256, SMT128_1>>>(ctxh16, ctxl16, wof, nullptr,
        nullptr, nullptr, aproj, nullptr, nullptr, nullptr, Dd, Dd, Dd, Dd, 0);

    // ln2 -> fp32 + fp16 single
    ln_kernel<<<ROWS, 256>>>(hs, aproj, ln2g, ln2b, h2, nullptr, nullptr, h216);

    // FFN (fp16x1)
    gemm_mp<128, 2, 2, 4><<<dim3(64, 32), 256, SMT128_2>>>(h216, nullptr, fif, nullptr,
        fib, nullptr, nullptr, ffn16, nullptr, nullptr, Dd, Dd, Dd, FFf, 1 | 2 | 512);
    gemm_mp<128, 2, 2, 4><<<dim3(16, 32), 256, SMT128_2>>>(ffn16, nullptr, fof, nullptr,
        fob, h2, out, nullptr, nullptr, nullptr, FFf, FFf, FFf, Dd, 1 | 4);
}

// round 13
// speedup vs baseline: 1.9540x; 1.0459x over previous
#include <cuda_runtime.h>
#include <cuda_bf16.h>
#include <cuda_fp16.h>
#include <math.h>
#include <stdint.h>

#define Bb   2
#define Ss   2048
#define Dd   2048
#define Hh   16
#define DHd  128
#define FFf  8192
#define ROWS 4096   // B*S

typedef __nv_bfloat16 bf16;

// ================= scratch (device globals) =================
__device__ bf16  g_h1h[(size_t)ROWS * Dd],  g_h1l[(size_t)ROWS * Dd];
__device__ __half g_h116[(size_t)ROWS * Dd];
__device__ bf16  g_wqkh[(size_t)2 * Dd * Dd], g_wqkl[(size_t)2 * Dd * Dd];
__device__ __half g_wvt16[(size_t)Dd * Dd];
__device__ __half g_wof16[(size_t)Dd * Dd];
__device__ __half g_fif16[(size_t)Dd * FFf];
__device__ __half g_fof16[(size_t)Dd * FFf];
__device__ bf16  g_qkh[(size_t)2 * ROWS * Dd], g_qkl[(size_t)2 * ROWS * Dd];
__device__ __half g_v16[(size_t)ROWS * Dd];
__device__ __half g_vt16[(size_t)Bb * Hh * DHd * Ss];
__device__ __half g_ah16[(size_t)Bb * Hh * Ss * Ss], g_al16[(size_t)Bb * Hh * Ss * Ss];
__device__ __half g_ctxh16[(size_t)ROWS * Dd], g_ctxl16[(size_t)ROWS * Dd];
__device__ float g_aproj[(size_t)ROWS * Dd];
__device__ float g_h2[(size_t)ROWS * Dd];
__device__ __half g_h216[(size_t)ROWS * Dd];
__device__ __half g_ffn16[(size_t)ROWS * FFf];
__device__ float g_sin[Ss * 64];
__device__ float g_cos[Ss * 64];

// ================= helpers =================
__device__ __forceinline__ uint32_t smem_u32(const void* p) {
    uint32_t a;
    asm("{ .reg .u64 t; cvta.to.shared.u64 t, %1; cvt.u32.u64 %0, t; }" : "=r"(a) : "l"(p));
    return a;
}
__device__ __forceinline__ void ldm4(uint32_t* r, uint32_t addr) {
    asm volatile("ldmatrix.sync.aligned.m8n8.x4.shared.b16 {%0,%1,%2,%3}, [%4];"
        : "=r"(r[0]), "=r"(r[1]), "=r"(r[2]), "=r"(r[3]) : "r"(addr));
}
__device__ __forceinline__ void mma_bf16(float* c, const uint32_t* a, const uint32_t* b) {
    asm volatile(
        "mma.sync.aligned.m16n8k16.row.col.f32.bf16.bf16.f32 "
        "{%0,%1,%2,%3}, {%4,%5,%6,%7}, {%8,%9}, {%0,%1,%2,%3};"
        : "+f"(c[0]), "+f"(c[1]), "+f"(c[2]), "+f"(c[3])
        : "r"(a[0]), "r"(a[1]), "r"(a[2]), "r"(a[3]), "r"(b[0]), "r"(b[1]));
}
__device__ __forceinline__ void mma_fp16(float* c, const uint32_t* a, const uint32_t* b) {
    asm volatile(
        "mma.sync.aligned.m16n8k16.row.col.f32.f16.f16.f32 "
        "{%0,%1,%2,%3}, {%4,%5,%6,%7}, {%8,%9}, {%0,%1,%2,%3};"
        : "+f"(c[0]), "+f"(c[1]), "+f"(c[2]), "+f"(c[3])
        : "r"(a[0]), "r"(a[1]), "r"(a[2]), "r"(a[3]), "r"(b[0]), "r"(b[1]));
}
__device__ __forceinline__ void cp16(uint32_t dst, const void* src) {
    asm volatile("cp.async.cg.shared.global [%0], [%1], 16;" :: "r"(dst), "l"(src));
}
__device__ __forceinline__ void cp_commit() { asm volatile("cp.async.commit_group;"); }
__device__ __forceinline__ void cp_wait2() { asm volatile("cp.async.wait_group 2;"); }
__device__ __forceinline__ void cp_wait1() { asm volatile("cp.async.wait_group 1;"); }
__device__ __forceinline__ void cp_wait0() { asm volatile("cp.async.wait_group 0;"); }

__device__ __forceinline__ void split2(float x, float y, bf16* ph, bf16* pl) {
    bf16 hx = __float2bfloat16_rn(x), hy = __float2bfloat16_rn(y);
    float fx = __bfloat162float(hx), fy = __bfloat162float(hy);
    __nv_bfloat162 h2; h2.x = hx; h2.y = hy;
    __nv_bfloat162 l2; l2.x = __float2bfloat16_rn(x - fx); l2.y = __float2bfloat16_rn(y - fy);
    *(__nv_bfloat162*)ph = h2;
    *(__nv_bfloat162*)pl = l2;
}
__device__ __forceinline__ void split2h(float x, float y, __half* ph, __half* pl) {
    __half hx = __float2half_rn(x), hy = __float2half_rn(y);
    __half2 h2 = __halves2half2(hx, hy);
    __half2 l2 = __floats2half2_rn(x - __half2float(hx), y - __half2float(hy));
    *(__half2*)ph = h2;
    *(__half2*)pl = l2;
}

// ================= fused prep: 6 weight transposes + rope table =================
__device__ __forceinline__ void dev_tsplit(
    float (*t)[33], const float* __restrict__ in,
    bf16* __restrict__ oh, bf16* __restrict__ ol,
    int R, int Cc, int bxb, int byb)
{
    int bx = bxb * 32, by = byb * 64;
    int tx = threadIdx.x & 31, ty = threadIdx.x >> 5;
#pragma unroll
    for (int i = 0; i < 64; i += 8)
        t[ty + i][tx] = in[(size_t)(by + ty + i) * Cc + bx + tx];
    __syncthreads();
#pragma unroll
    for (int i = 0; i < 32; i += 8) {
        int r = ty + i;
        size_t o = (size_t)(bx + r) * R + by + 2 * tx;
        split2(t[2 * tx][r], t[2 * tx + 1][r], oh + o, ol + o);
    }
}
__device__ __forceinline__ void dev_tfp16(
    float (*t)[33], const float* __restrict__ in, __half* __restrict__ oh,
    int R, int Cc, int bxb, int byb)
{
    int bx = bxb * 32, by = byb * 64;
    int tx = threadIdx.x & 31, ty = threadIdx.x >> 5;
#pragma unroll
    for (int i = 0; i < 64; i += 8)
        t[ty + i][tx] = in[(size_t)(by + ty + i) * Cc + bx + tx];
    __syncthreads();
#pragma unroll
    for (int i = 0; i < 32; i += 8) {
        int r = ty + i;
        __half2 h2 = __floats2half2_rn(t[2 * tx][r], t[2 * tx + 1][r]);
        *(__half2*)(oh + (size_t)(bx + r) * R + by + 2 * tx) = h2;
    }
}

__global__ __launch_bounds__(256) void prep_kernel(
    const float* __restrict__ wq, const float* __restrict__ wk,
    const float* __restrict__ wv, const float* __restrict__ wo,
    const float* __restrict__ fiw, const float* __restrict__ fow,
    bf16* __restrict__ wqkh, bf16* __restrict__ wqkl,
    __half* __restrict__ wvt, __half* __restrict__ wof,
    __half* __restrict__ fif, __half* __restrict__ fof)
{
    __shared__ float t[64][33];
    int id = blockIdx.x;
    if (id < 2048) {
        dev_tsplit(t, wq, wqkh, wqkl, Dd, Dd, id & 63, id >> 6);
    } else if (id < 4096) {
        id -= 2048;
        dev_tsplit(t, wk, wqkh + (size_t)Dd * Dd, wqkl + (size_t)Dd * Dd, Dd, Dd, id & 63, id >> 6);
    } else if (id < 6144) {
        id -= 4096;
        dev_tfp16(t, wv, wvt, Dd, Dd, id & 63, id >> 6);
    } else if (id < 8192) {
        id -= 6144;
        dev_tfp16(t, wo, wof, Dd, Dd, id & 63, id >> 6);
    } else if (id < 16384) {
        id -= 8192;
        dev_tfp16(t, fiw, fif, Dd, FFf, id & 255, id >> 8);
    } else if (id < 24576) {
        id -= 16384;
        dev_tfp16(t, fow, fof, FFf, Dd, id & 63, id >> 6);
    } else {
        int tt = (id - 24576) * 256 + threadIdx.x;
        int p = tt >> 6, i = tt & 63;
        double inv = pow(10000.0, -((double)(2 * i)) / 128.0);
        float ang = (float)p * (float)inv;
        g_sin[tt] = (float)sin((double)ang);
        g_cos[tt] = (float)cos((double)ang);
    }
}

// V^T per head, fp16 in/out
__global__ __launch_bounds__(256) void vtrans_h(
    const __half* __restrict__ v, __half* __restrict__ oh)
{
    __shared__ float t[64][33];
    int bh = blockIdx.z;
    int b = bh >> 4, h = bh & 15;
    const __half* in = v + (size_t)b * Ss * Dd + h * DHd;
    size_t obase = (size_t)bh * DHd * Ss;
    int n0 = blockIdx.x * 32, s0 = blockIdx.y * 64;
    int tx = threadIdx.x, ty = threadIdx.y;
#pragma unroll
    for (int i = 0; i < 64; i += 8)
        t[ty + i][tx] = __half2float(in[(size_t)(s0 + ty + i) * Dd + n0 + tx]);
    __syncthreads();
#pragma unroll
    for (int i = 0; i < 32; i += 8) {
        int r = ty + i;
        __half2 h2 = __floats2half2_rn(t[2 * tx][r], t[2 * tx + 1][r]);
        *(__half2*)(oh + obase + (size_t)(n0 + r) * Ss + s0 + 2 * tx) = h2;
    }
}

// ================= LayerNorm =================
__global__ __launch_bounds__(256) void ln_kernel(
    const float* __restrict__ x, const float* __restrict__ x2,
    const float* __restrict__ g, const float* __restrict__ bta,
    float* __restrict__ outf, bf16* __restrict__ outh, bf16* __restrict__ outl,
    __half* __restrict__ o16)
{
    __shared__ float red[256];
    int row = blockIdx.x, tid = threadIdx.x;
    size_t base = (size_t)row * Dd;
    float r[8];
    float s = 0.f;
#pragma unroll
    for (int t = 0; t < 8; t++) {
        int i = tid + t * 256;
        float v = x[base + i];
        if (x2) v += x2[base + i];
        r[t] = v; s += v;
    }
    red[tid] = s; __syncthreads();
    for (int o = 128; o > 0; o >>= 1) { if (tid < o) red[tid] += red[tid + o]; __syncthreads(); }
    float mean = red[0] * (1.0f / Dd);
    __syncthreads();
    float vs = 0.f;
#pragma unroll
    for (int t = 0; t < 8; t++) { float d = r[t] - mean; vs += d * d; }
    red[tid] = vs; __syncthreads();
    for (int o = 128; o > 0; o >>= 1) { if (tid < o) red[tid] += red[tid + o]; __syncthreads(); }
    float var = red[0] * (1.0f / Dd);
    float rs = rsqrtf(var + 1e-5f);
#pragma unroll
    for (int t = 0; t < 8; t++) {
        int i = tid + t * 256;
        float v = (r[t] - mean) * rs * g[i] + bta[i];
        if (outf) outf[base + i] = v;
        if (outh) {
            bf16 h = __float2bfloat16_rn(v);
            outh[base + i] = h;
            outl[base + i] = __float2bfloat16_rn(v - __bfloat162float(h));
        }
        if (o16) o16[base + i] = __float2half_rn(v);
    }
}

// ================= mixed-precision mma.sync GEMM =================
// MODE 0: bf16x3. MODE 1: fp16x2. MODE 2: fp16x1.
// flags: 1=bias 2=gelu 4=resid 8=qkv(rope+scatter) 16=score 32=ctx
//        64=bf16 hi/lo out 256=fp16 hi/lo out 512=fp16 single out
#define PPA 10240u            // A part bytes (128 rows * 80B)

template<int BN, int MODE, int MINCTAS, int NSTG>
__global__ __launch_bounds__(256, MINCTAS) void gemm_mp(
    const void* __restrict__ Ahv, const void* __restrict__ Alv,
    const void* __restrict__ Bhv, const void* __restrict__ Blv,
    const float* __restrict__ bias, const float* __restrict__ resid,
    float* __restrict__ Cf, void* __restrict__ Chv, void* __restrict__ Clv,
    const int* __restrict__ pid,
    int K, int lda, int ldb, int ldc, int flags)
{
    constexpr uint32_t PPB = (uint32_t)BN * 80u;
    constexpr uint32_t APARTS = (MODE == 2) ? 1u : 2u;
    constexpr uint32_t BPARTS = (MODE == 0) ? 2u : 1u;
    constexpr uint32_t STG = APARTS * PPA + BPARTS * PPB;
    constexpr int NFR = BN / 32;
    constexpr int NPAIR = NFR / 2;
    extern __shared__ char sm[];
    int bx = blockIdx.x, by = blockIdx.y, bz = blockIdx.z;
    const uint16_t* Ahp = (const uint16_t*)Ahv;
    const uint16_t* Alp = (const uint16_t*)Alv;
    const uint16_t* Bhp = (const uint16_t*)Bhv;
    const uint16_t* Blp = (const uint16_t*)Blv;
    float* Cfp = Cf;
    uint16_t* Chp = (uint16_t*)Chv;
    uint16_t* Clp = (uint16_t*)Clv;
    int Keff = K;
    if (flags & 16) {
        if (bx * BN > by * 128 + 127) return;
        int b = bz >> 4, h = bz & 15;
        size_t ao = (size_t)b * Ss * Dd + h * DHd;
        Ahp += ao; Alp += ao; Bhp += ao; Blp += ao;
        Cfp += (size_t)bz * Ss * Ss;
    }
    if (flags & 32) {
        bz = blockIdx.x;
        by = gridDim.y - 1 - blockIdx.y;
        bx = 0;
        int b = bz >> 4, h = bz & 15;
        size_t ao = (size_t)bz * Ss * Ss;
        size_t bo = (size_t)bz * DHd * Ss;
        Ahp += ao; Alp += ao; Bhp += bo; Blp += bo;
        size_t co = (size_t)b * Ss * Dd + h * DHd;
        Chp += co; Clp += co;
        Keff = (by + 1) * 128;
    }
    const int tid = threadIdx.x, lane = tid & 31, warp = tid >> 5;
    const int m0 = by * 128, n0 = bx * BN;
    const int wm = (warp >> 2) * 64, wn = (warp & 3) * (BN / 4);
    const uint32_t sbase = smem_u32(sm);

    float acc[4][NFR][4];
#pragma unroll
    for (int i = 0; i < 4; i++)
#pragma unroll
        for (int j = 0; j < NFR; j++)
#pragma unroll
            for (int e = 0; e < 4; e++) acc[i][j][e] = 0.f;

#define ISSUE_CHUNK(ST, K0) do { \
    uint32_t sb0 = sbase + (uint32_t)(ST) * STG; \
    _Pragma("unroll") \
    for (int i = 0; i < 2; i++) { \
        int idx = tid + i * 256; \
        int r = idx >> 2; int cc = idx & 3; \
        uint32_t d = sb0 + (uint32_t)r * 80u + (uint32_t)cc * 16u; \
        size_t sa = (size_t)(m0 + r) * lda + (K0) + cc * 8; \
        cp16(d, Ahp + sa); \
        if (MODE != 2) cp16(d + PPA, Alp + sa); \
    } \
    _Pragma("unroll") \
    for (int i = 0; i < BN / 64; i++) { \
        int idx = tid + i * 256; \
        int r = idx >> 2; int cc = idx & 3; \
        uint32_t d = sb0 + APARTS * PPA + (uint32_t)r * 80u + (uint32_t)cc * 16u; \
        size_t sb2 = (size_t)(n0 + r) * ldb + (K0) + cc * 8; \
        cp16(d, Bhp + sb2); \
        if (MODE == 0) cp16(d + PPB, Blp + sb2); \
    } \
    cp_commit(); \
} while(0)

    const uint32_t a_lane_off = (uint32_t)(wm + (lane & 15)) * 80u + (uint32_t)((lane >> 4) * 16);
    const uint32_t b_lane_off = (uint32_t)(wn + ((lane >> 4) * 8) + (lane & 7)) * 80u
                              + (uint32_t)(((lane >> 3) & 1) * 16);

    auto compute_chunk = [&](uint32_t boff) {
#pragma unroll
        for (int ks = 0; ks < 2; ks++) {
            uint32_t ahi[4][4], alo[4][4];
            uint32_t abase = sbase + boff + a_lane_off + (uint32_t)(ks * 32);
            uint32_t bbase = sbase + boff + APARTS * PPA + b_lane_off + (uint32_t)(ks * 32);
#pragma unroll
            for (int mti = 0; mti < 4; mti++) {
                ldm4(ahi[mti], abase + (uint32_t)(mti * 16) * 80u);
                if (MODE != 2) ldm4(alo[mti], abase + (uint32_t)(mti * 16) * 80u + PPA);
            }
#pragma unroll
            for (int p = 0; p < NPAIR; p++) {
                uint32_t bh4[4];
                ldm4(bh4, bbase + (uint32_t)(p * 16) * 80u);
                if (MODE == 0) {
                    uint32_t bl4[4];
                    ldm4(bl4, bbase + (uint32_t)(p * 16) * 80u + PPB);
#pragma unroll
                    for (int mti = 0; mti < 4; mti++) {
                        mma_bf16(acc[mti][2 * p],     ahi[mti], bh4);
                        mma_bf16(acc[mti][2 * p + 1], ahi[mti], bh4 + 2);
                    }
#pragma unroll
                    for (int mti = 0; mti < 4; mti++) {
                        mma_bf16(acc[mti][2 * p],     ahi[mti], bl4);
                        mma_bf16(acc[mti][2 * p + 1], ahi[mti], bl4 + 2);
                    }
#pragma unroll
                    for (int mti = 0; mti < 4; mti++) {
                        mma_bf16(acc[mti][2 * p],     alo[mti], bh4);
                        mma_bf16(acc[mti][2 * p + 1], alo[mti], bh4 + 2);
                    }
                } else if (MODE == 1) {
#pragma unroll
                    for (int mti = 0; mti < 4; mti++) {
                        mma_fp16(acc[mti][2 * p],     ahi[mti], bh4);
                        mma_fp16(acc[mti][2 * p + 1], ahi[mti], bh4 + 2);
                    }
#pragma unroll
                    for (int mti = 0; mti < 4; mti++) {
                        mma_fp16(acc[mti][2 * p],     alo[mti], bh4);
                        mma_fp16(acc[mti][2 * p + 1], alo[mti], bh4 + 2);
                    }
                } else {
#pragma unroll
                    for (int mti = 0; mti < 4; mti++) {
                        mma_fp16(acc[mti][2 * p],     ahi[mti], bh4);
                        mma_fp16(acc[mti][2 * p + 1], ahi[mti], bh4 + 2);
                    }
                }
            }
        }
    };

    const int nch = Keff / 32;
    if (NSTG == 2) {
        // double buffer with trailing barrier (race-free, overlaps load c+1 with compute c)
        ISSUE_CHUNK(0, 0);
        for (int c = 0; c < nch; c++) {
            if (c + 1 < nch) { ISSUE_CHUNK((c + 1) & 1, (c + 1) * 32); cp_wait1(); }
            else cp_wait0();
            __syncthreads();
            compute_chunk((uint32_t)(c & 1) * STG);
            __syncthreads();
        }
    } else {
#pragma unroll
        for (int s = 0; s < NSTG - 1; s++)
            if (s < nch) ISSUE_CHUNK(s, s * 32);
        for (int c = 0; c < nch; c++) {
            int rem = nch - 1 - c;
            if (NSTG >= 4 && rem >= 2) cp_wait2();
            else if (rem >= 1) cp_wait1();
            else cp_wait0();
            __syncthreads();
            compute_chunk((uint32_t)(c % NSTG) * STG);
            if (c + NSTG - 1 < nch) ISSUE_CHUNK((c + NSTG - 1) % NSTG, (c + NSTG - 1) * 32);
        }
    }
#undef ISSUE_CHUNK

    // ---------------- epilogue ----------------
#pragma unroll
    for (int mti = 0; mti < 4; mti++) {
#pragma unroll
        for (int ntj = 0; ntj < NFR; ntj++) {
            int row = m0 + wm + mti * 16 + (lane >> 2);
            int col = n0 + wn + ntj * 8 + (lane & 3) * 2;
#pragma unroll
            for (int half = 0; half < 2; half++) {
                int rr = row + half * 8;
                float v0 = acc[mti][ntj][half * 2];
                float v1 = acc[mti][ntj][half * 2 + 1];
                if (flags & 1) { v0 += bias[col]; v1 += bias[col + 1]; }
                if (flags & 2) {
                    v0 = 0.5f * v0 * (1.0f + erff(v0 * 0.70710678118654752f));
                    v1 = 0.5f * v1 * (1.0f + erff(v1 * 0.70710678118654752f));
                }
                if (flags & 4) {
                    const float* rp = resid + (size_t)rr * ldc + col;
                    v0 += rp[0]; v1 += rp[1];
                }
                if (flags & 8) {
                    int sel = col >> 11, cl = col & 2047;
                    int b = rr >> 11, s = rr & 2047;
                    int pos = pid[b * Ss + s];
                    int i = (cl & 127) >> 1;
                    float sn = g_sin[pos * 64 + i], cs = g_cos[pos * 64 + i];
                    float r0 = v0 * cs - v1 * sn;
                    float r1 = v1 * cs + v0 * sn;
                    size_t o = (size_t)(sel * ROWS + rr) * Dd + cl;
                    split2(r0, r1, (bf16*)(Chp + o), (bf16*)(Clp + o));
                } else if (flags & 64) {
                    size_t o = (size_t)rr * ldc + col;
                    split2(v0, v1, (bf16*)(Chp + o), (bf16*)(Clp + o));
                } else if (flags & 256) {
                    size_t o = (size_t)rr * ldc + col;
                    split2h(v0, v1, (__half*)(Chp + o), (__half*)(Clp + o));
                } else if (flags & 512) {
                    size_t o = (size_t)rr * ldc + col;
                    *(__half2*)((__half*)Chp + o) = __floats2half2_rn(v0, v1);
                } else {
                    *(float2*)(Cfp + (size_t)rr * ldc + col) = make_float2(v0, v1);
                }
            }
        }
    }
}

// ================= row softmax (causal trunc, vectorized, read-skip) =================
__global__ __launch_bounds__(256) void softmax_kernel(
    float* __restrict__ attn, __half* __restrict__ ah, __half* __restrict__ al)
{
    int rid = blockIdx.x;
    int qpos = rid & (Ss - 1);
    int L = qpos + 1;
    int Lpad = ((qpos >> 7) + 1) << 7;
    float* row = attn + (size_t)rid * Ss;
    __half* rh = ah + (size_t)rid * Ss;
    __half* rl = al + (size_t)rid * Ss;
    __shared__ float red[256];
    int tid = threadIdx.x;
    int base = tid * 8;
    float r[8];
    if (base < L) {      // skip loads entirely beyond the causal boundary
        float4 ra = *(const float4*)(row + base);
        float4 rb = *(const float4*)(row + base + 4);
        r[0] = ra.x; r[1] = ra.y; r[2] = ra.z; r[3] = ra.w;
        r[4] = rb.x; r[5] = rb.y; r[6] = rb.z; r[7] = rb.w;
    } else {
#pragma unroll
        for (int t = 0; t < 8; t++) r[t] = -3.4e38f;
    }
    float mx = -3.4e38f;
#pragma unroll
    for (int t = 0; t < 8; t++) {
        if (base + t >= L) r[t] = -3.4e38f;
        mx = fmaxf(mx, r[t]);
    }
    red[tid] = mx; __syncthreads();
    for (int o = 128; o > 0; o >>= 1) { if (tid < o) red[tid] = fmaxf(red[tid], red[tid + o]); __syncthreads(); }
    mx = red[0]; __syncthreads();
    float s = 0.f;
#pragma unroll
    for (int t = 0; t < 8; t++) {
        float e = (base + t < L) ? expf(r[t] - mx) : 0.0f;
        r[t] = e; s += e;
    }
    red[tid] = s; __syncthreads();
    for (int o = 128; o > 0; o >>= 1) { if (tid < o) red[tid] += red[tid + o]; __syncthreads(); }
    float inv = 1.0f / red[0];
#pragma unroll
    for (int t = 0; t < 8; t++) r[t] *= inv;
    *(float4*)(row + base)     = make_float4(r[0], r[1], r[2], r[3]);
    *(float4*)(row + base + 4) = make_float4(r[4], r[5], r[6], r[7]);
    if (base < Lpad) {
        __half2 hh[4], ll[4];
#pragma unroll
        for (int j = 0; j < 4; j++) {
            __half h0 = __float2half_rn(r[2 * j]), h1 = __float2half_rn(r[2 * j + 1]);
            hh[j] = __halves2half2(h0, h1);
            ll[j] = __floats2half2_rn(r[2 * j] - __half2float(h0), r[2 * j + 1] - __half2float(h1));
        }
        *(uint4*)(rh + base) = *(uint4*)hh;
        *(uint4*)(rl + base) = *(uint4*)ll;
    }
}

// ================= launch =================
extern "C" void kernel_launch(void* const* d_in, const int* in_sizes, int n_in,
                              void* d_out, int out_size)
{
    const float* hs   = (const float*)d_in[0];
    const int*   pid  = (const int*)  d_in[1];
    const float* wq   = (const float*)d_in[2];
    const float* wk   = (const float*)d_in[3];
    const float* wv   = (const float*)d_in[4];
    const float* wo   = (const float*)d_in[5];
    const float* ln1g = (const float*)d_in[6];
    const float* ln1b = (const float*)d_in[7];
    const float* ln2g = (const float*)d_in[8];
    const float* ln2b = (const float*)d_in[9];
    const float* fiw  = (const float*)d_in[10];
    const float* fib  = (const float*)d_in[11];
    const float* fow  = (const float*)d_in[12];
    const float* fob  = (const float*)d_in[13];

    float* out  = (float*)d_out;
    float* attn = out + (size_t)ROWS * Dd;

    float *aproj, *h2;
    bf16 *h1h, *h1l, *wqkh, *wqkl, *qkh, *qkl;
    __half *h116, *wvt, *wof, *fif, *fof, *v16, *vt16, *ah16, *al16;
    __half *ctxh16, *ctxl16, *h216, *ffn16;
    cudaGetSymbolAddress((void**)&aproj,  g_aproj);
    cudaGetSymbolAddress((void**)&h2,     g_h2);
    cudaGetSymbolAddress((void**)&h1h,    g_h1h);
    cudaGetSymbolAddress((void**)&h1l,    g_h1l);
    cudaGetSymbolAddress((void**)&h116,   g_h116);
    cudaGetSymbolAddress((void**)&wqkh,   g_wqkh);
    cudaGetSymbolAddress((void**)&wqkl,   g_wqkl);
    cudaGetSymbolAddress((void**)&wvt,    g_wvt16);
    cudaGetSymbolAddress((void**)&wof,    g_wof16);
    cudaGetSymbolAddress((void**)&fif,    g_fif16);
    cudaGetSymbolAddress((void**)&fof,    g_fof16);
    cudaGetSymbolAddress((void**)&qkh,    g_qkh);
    cudaGetSymbolAddress((void**)&qkl,    g_qkl);
    cudaGetSymbolAddress((void**)&v16,    g_v16);
    cudaGetSymbolAddress((void**)&vt16,   g_vt16);
    cudaGetSymbolAddress((void**)&ah16,   g_ah16);
    cudaGetSymbolAddress((void**)&al16,   g_al16);
    cudaGetSymbolAddress((void**)&ctxh16, g_ctxh16);
    cudaGetSymbolAddress((void**)&ctxl16, g_ctxl16);
    cudaGetSymbolAddress((void**)&h216,   g_h216);
    cudaGetSymbolAddress((void**)&ffn16,  g_ffn16);

    const uint32_t SMT128_0 = 2u * (2u * PPA + 2u * 128u * 80u);   // 81920, 2 CTAs
    const uint32_t SMT128_1 = 3u * (2u * PPA + 1u * 128u * 80u);   // 92160, 2 CTAs
    const uint32_t SMT128_2 = 4u * (1u * PPA + 1u * 128u * 80u);   // 81920, 2 CTAs
    cudaFuncSetAttribute((const void*)gemm_mp<128, 0, 2, 2>, cudaFuncAttributeMaxDynamicSharedMemorySize, SMT128_0);
    cudaFuncSetAttribute((const void*)gemm_mp<128, 1, 2, 3>, cudaFuncAttributeMaxDynamicSharedMemorySize, SMT128_1);
    cudaFuncSetAttribute((const void*)gemm_mp<128, 2, 2, 4>, cudaFuncAttributeMaxDynamicSharedMemorySize, SMT128_2);

    // fused prep: all weight transposes + rope table in one launch
    prep_kernel<<<25088, 256>>>(wq, wk, wv, wo, fiw, fow,
                                wqkh, wqkl, wvt, wof, fif, fof);

    // ln1 -> bf16 hi/lo (for qk) + fp16 single (for v)
    ln_kernel<<<ROWS, 256>>>(hs, nullptr, ln1g, ln1b, nullptr, h1h, h1l, h116);

    // qk projection (bf16x3, BN=128, 2 CTAs/SM, RoPE in epilogue); v projection (fp16x1)
    gemm_mp<128, 0, 2, 2><<<dim3(32, 32), 256, SMT128_0>>>(h1h, h1l, wqkh, wqkl,
        nullptr, nullptr, nullptr, qkh, qkl, pid, Dd, Dd, Dd, Dd, 8);
    gemm_mp<128, 2, 2, 4><<<dim3(16, 32), 256, SMT128_2>>>(h116, nullptr, wvt, nullptr,
        nullptr, nullptr, nullptr, v16, nullptr, nullptr, Dd, Dd, Dd, Dd, 512);

    dim3 tb(32, 8);
    vtrans_h<<<dim3(DHd / 32, Ss / 64, Bb * Hh), tb>>>(v16, vt16);

    // scores (bf16x3, BN=128, 2 CTAs/SM, causal) -> softmax -> ctx (fp16x2)
    gemm_mp<128, 0, 2, 2><<<dim3(16, 16, Bb * Hh), 256, SMT128_0>>>(qkh, qkl,
        qkh + (size_t)ROWS * Dd, qkl + (size_t)ROWS * Dd,
        nullptr, nullptr, attn, nullptr, nullptr, nullptr, DHd, Dd, Dd, Ss, 16);
    softmax_kernel<<<Bb * Hh * Ss, 256>>>(attn, ah16, al16);
    gemm_mp<128, 1, 2, 3><<<dim3(Bb * Hh, 16), 256, SMT128_1>>>(ah16, al16, vt16, nullptr,
        nullptr, nullptr, nullptr, ctxh16, ctxl16, nullptr, Ss, Ss, Ss, Dd, 32 | 256);

    // output projection (fp16x2)
    gemm_mp<128, 1, 2, 3><<<dim3(16, 32), 256, SMT128_1>>>(ctxh16, ctxl16, wof, nullptr,
        nullptr, nullptr, aproj, nullptr, nullptr, nullptr, Dd, Dd, Dd, Dd, 0);

    // ln2 -> fp32 + fp16 single
    ln_kernel<<<ROWS, 256>>>(hs, aproj, ln2g, ln2b, h2, nullptr, nullptr, h216);

    // FFN (fp16x1)
    gemm_mp<128, 2, 2, 4><<<dim3(64, 32), 256, SMT128_2>>>(h216, nullptr, fif, nullptr,
        fib, nullptr, nullptr, ffn16, nullptr, nullptr, Dd, Dd, Dd, FFf, 1 | 2 | 512);
    gemm_mp<128, 2, 2, 4><<<dim3(16, 32), 256, SMT128_2>>>(ffn16, nullptr, fof, nullptr,
        fob, h2, out, nullptr, nullptr, nullptr, FFf, FFf, FFf, Dd, 1 | 4);
}

// round 14
// speedup vs baseline: 1.9647x; 1.0055x over previous
#include <cuda_runtime.h>
#include <cuda_bf16.h>
#include <cuda_fp16.h>
#include <math.h>
#include <stdint.h>

#define Bb   2
#define Ss   2048
#define Dd   2048
#define Hh   16
#define DHd  128
#define FFf  8192
#define ROWS 4096   // B*S

typedef __nv_bfloat16 bf16;

// ================= scratch (device globals) =================
__device__ bf16  g_h1h[(size_t)ROWS * Dd],  g_h1l[(size_t)ROWS * Dd];
__device__ __half g_h116[(size_t)ROWS * Dd];
__device__ bf16  g_wqkh[(size_t)2 * Dd * Dd], g_wqkl[(size_t)2 * Dd * Dd];
__device__ __half g_wvt16[(size_t)Dd * Dd];
__device__ __half g_wof16[(size_t)Dd * Dd];
__device__ __half g_fif16[(size_t)Dd * FFf];
__device__ __half g_fof16[(size_t)Dd * FFf];
__device__ bf16  g_qkh[(size_t)2 * ROWS * Dd], g_qkl[(size_t)2 * ROWS * Dd];
__device__ __half g_v16[(size_t)ROWS * Dd];
__device__ __half g_vt16[(size_t)Bb * Hh * DHd * Ss];
__device__ __half g_ah16[(size_t)Bb * Hh * Ss * Ss], g_al16[(size_t)Bb * Hh * Ss * Ss];
__device__ __half g_ctxh16[(size_t)ROWS * Dd], g_ctxl16[(size_t)ROWS * Dd];
__device__ float g_aproj[(size_t)ROWS * Dd];
__device__ float g_h2[(size_t)ROWS * Dd];
__device__ __half g_h216[(size_t)ROWS * Dd];
__device__ __half g_ffn16[(size_t)ROWS * FFf];
__device__ float g_sin[Ss * 64];
__device__ float g_cos[Ss * 64];

// ================= helpers =================
__device__ __forceinline__ uint32_t smem_u32(const void* p) {
    uint32_t a;
    asm("{ .reg .u64 t; cvta.to.shared.u64 t, %1; cvt.u32.u64 %0, t; }" : "=r"(a) : "l"(p));
    return a;
}
__device__ __forceinline__ void ldm4(uint32_t* r, uint32_t addr) {
    asm volatile("ldmatrix.sync.aligned.m8n8.x4.shared.b16 {%0,%1,%2,%3}, [%4];"
        : "=r"(r[0]), "=r"(r[1]), "=r"(r[2]), "=r"(r[3]) : "r"(addr));
}
__device__ __forceinline__ void mma_bf16(float* c, const uint32_t* a, const uint32_t* b) {
    asm volatile(
        "mma.sync.aligned.m16n8k16.row.col.f32.bf16.bf16.f32 "
        "{%0,%1,%2,%3}, {%4,%5,%6,%7}, {%8,%9}, {%0,%1,%2,%3};"
        : "+f"(c[0]), "+f"(c[1]), "+f"(c[2]), "+f"(c[3])
        : "r"(a[0]), "r"(a[1]), "r"(a[2]), "r"(a[3]), "r"(b[0]), "r"(b[1]));
}
__device__ __forceinline__ void mma_fp16(float* c, const uint32_t* a, const uint32_t* b) {
    asm volatile(
        "mma.sync.aligned.m16n8k16.row.col.f32.f16.f16.f32 "
        "{%0,%1,%2,%3}, {%4,%5,%6,%7}, {%8,%9}, {%0,%1,%2,%3};"
        : "+f"(c[0]), "+f"(c[1]), "+f"(c[2]), "+f"(c[3])
        : "r"(a[0]), "r"(a[1]), "r"(a[2]), "r"(a[3]), "r"(b[0]), "r"(b[1]));
}
__device__ __forceinline__ void cp16(uint32_t dst, const void* src) {
    asm volatile("cp.async.cg.shared.global [%0], [%1], 16;" :: "r"(dst), "l"(src));
}
__device__ __forceinline__ void cp_commit() { asm volatile("cp.async.commit_group;"); }
__device__ __forceinline__ void cp_wait2() { asm volatile("cp.async.wait_group 2;"); }
__device__ __forceinline__ void cp_wait1() { asm volatile("cp.async.wait_group 1;"); }
__device__ __forceinline__ void cp_wait0() { asm volatile("cp.async.wait_group 0;"); }

__device__ __forceinline__ void split2(float x, float y, bf16* ph, bf16* pl) {
    bf16 hx = __float2bfloat16_rn(x), hy = __float2bfloat16_rn(y);
    float fx = __bfloat162float(hx), fy = __bfloat162float(hy);
    __nv_bfloat162 h2; h2.x = hx; h2.y = hy;
    __nv_bfloat162 l2; l2.x = __float2bfloat16_rn(x - fx); l2.y = __float2bfloat16_rn(y - fy);
    *(__nv_bfloat162*)ph = h2;
    *(__nv_bfloat162*)pl = l2;
}
__device__ __forceinline__ void split2h(float x, float y, __half* ph, __half* pl) {
    __half hx = __float2half_rn(x), hy = __float2half_rn(y);
    __half2 h2 = __halves2half2(hx, hy);
    __half2 l2 = __floats2half2_rn(x - __half2float(hx), y - __half2float(hy));
    *(__half2*)ph = h2;
    *(__half2*)pl = l2;
}

// ================= fused prep: 6 weight transposes + rope table =================
__device__ __forceinline__ void dev_tsplit(
    float (*t)[33], const float* __restrict__ in,
    bf16* __restrict__ oh, bf16* __restrict__ ol,
    int R, int Cc, int bxb, int byb)
{
    int bx = bxb * 32, by = byb * 64;
    int tx = threadIdx.x & 31, ty = threadIdx.x >> 5;
#pragma unroll
    for (int i = 0; i < 64; i += 8)
        t[ty + i][tx] = in[(size_t)(by + ty + i) * Cc + bx + tx];
    __syncthreads();
#pragma unroll
    for (int i = 0; i < 32; i += 8) {
        int r = ty + i;
        size_t o = (size_t)(bx + r) * R + by + 2 * tx;
        split2(t[2 * tx][r], t[2 * tx + 1][r], oh + o, ol + o);
    }
}
__device__ __forceinline__ void dev_tfp16(
    float (*t)[33], const float* __restrict__ in, __half* __restrict__ oh,
    int R, int Cc, int bxb, int byb)
{
    int bx = bxb * 32, by = byb * 64;
    int tx = threadIdx.x & 31, ty = threadIdx.x >> 5;
#pragma unroll
    for (int i = 0; i < 64; i += 8)
        t[ty + i][tx] = in[(size_t)(by + ty + i) * Cc + bx + tx];
    __syncthreads();
#pragma unroll
    for (int i = 0; i < 32; i += 8) {
        int r = ty + i;
        __half2 h2 = __floats2half2_rn(t[2 * tx][r], t[2 * tx + 1][r]);
        *(__half2*)(oh + (size_t)(bx + r) * R + by + 2 * tx) = h2;
    }
}

__global__ __launch_bounds__(256) void prep_kernel(
    const float* __restrict__ wq, const float* __restrict__ wk,
    const float* __restrict__ wv, const float* __restrict__ wo,
    const float* __restrict__ fiw, const float* __restrict__ fow,
    bf16* __restrict__ wqkh, bf16* __restrict__ wqkl,
    __half* __restrict__ wvt, __half* __restrict__ wof,
    __half* __restrict__ fif, __half* __restrict__ fof)
{
    __shared__ float t[64][33];
    int id = blockIdx.x;
    if (id < 2048) {
        dev_tsplit(t, wq, wqkh, wqkl, Dd, Dd, id & 63, id >> 6);
    } else if (id < 4096) {
        id -= 2048;
        dev_tsplit(t, wk, wqkh + (size_t)Dd * Dd, wqkl + (size_t)Dd * Dd, Dd, Dd, id & 63, id >> 6);
    } else if (id < 6144) {
        id -= 4096;
        dev_tfp16(t, wv, wvt, Dd, Dd, id & 63, id >> 6);
    } else if (id < 8192) {
        id -= 6144;
        dev_tfp16(t, wo, wof, Dd, Dd, id & 63, id >> 6);
    } else if (id < 16384) {
        id -= 8192;
        dev_tfp16(t, fiw, fif, Dd, FFf, id & 255, id >> 8);
    } else if (id < 24576) {
        id -= 16384;
        dev_tfp16(t, fow, fof, FFf, Dd, id & 63, id >> 6);
    } else {
        int tt = (id - 24576) * 256 + threadIdx.x;
        int p = tt >> 6, i = tt & 63;
        double inv = pow(10000.0, -((double)(2 * i)) / 128.0);
        float ang = (float)p * (float)inv;
        g_sin[tt] = (float)sin((double)ang);
        g_cos[tt] = (float)cos((double)ang);
    }
}

// V^T per head, fp16 in/out
__global__ __launch_bounds__(256) void vtrans_h(
    const __half* __restrict__ v, __half* __restrict__ oh)
{
    __shared__ float t[64][33];
    int bh = blockIdx.z;
    int b = bh >> 4, h = bh & 15;
    const __half* in = v + (size_t)b * Ss * Dd + h * DHd;
    size_t obase = (size_t)bh * DHd * Ss;
    int n0 = blockIdx.x * 32, s0 = blockIdx.y * 64;
    int tx = threadIdx.x, ty = threadIdx.y;
#pragma unroll
    for (int i = 0; i < 64; i += 8)
        t[ty + i][tx] = __half2float(in[(size_t)(s0 + ty + i) * Dd + n0 + tx]);
    __syncthreads();
#pragma unroll
    for (int i = 0; i < 32; i += 8) {
        int r = ty + i;
        __half2 h2 = __floats2half2_rn(t[2 * tx][r], t[2 * tx + 1][r]);
        *(__half2*)(oh + obase + (size_t)(n0 + r) * Ss + s0 + 2 * tx) = h2;
    }
}

// ================= LayerNorm =================
__global__ __launch_bounds__(256) void ln_kernel(
    const float* __restrict__ x, const float* __restrict__ x2,
    const float* __restrict__ g, const float* __restrict__ bta,
    float* __restrict__ outf, bf16* __restrict__ outh, bf16* __restrict__ outl,
    __half* __restrict__ o16)
{
    __shared__ float red[256];
    int row = blockIdx.x, tid = threadIdx.x;
    size_t base = (size_t)row * Dd;
    float r[8];
    float s = 0.f;
#pragma unroll
    for (int t = 0; t < 8; t++) {
        int i = tid + t * 256;
        float v = x[base + i];
        if (x2) v += x2[base + i];
        r[t] = v; s += v;
    }
    red[tid] = s; __syncthreads();
    for (int o = 128; o > 0; o >>= 1) { if (tid < o) red[tid] += red[tid + o]; __syncthreads(); }
    float mean = red[0] * (1.0f / Dd);
    __syncthreads();
    float vs = 0.f;
#pragma unroll
    for (int t = 0; t < 8; t++) { float d = r[t] - mean; vs += d * d; }
    red[tid] = vs; __syncthreads();
    for (int o = 128; o > 0; o >>= 1) { if (tid < o) red[tid] += red[tid + o]; __syncthreads(); }
    float var = red[0] * (1.0f / Dd);
    float rs = rsqrtf(var + 1e-5f);
#pragma unroll
    for (int t = 0; t < 8; t++) {
        int i = tid + t * 256;
        float v = (r[t] - mean) * rs * g[i] + bta[i];
        if (outf) outf[base + i] = v;
        if (outh) {
            bf16 h = __float2bfloat16_rn(v);
            outh[base + i] = h;
            outl[base + i] = __float2bfloat16_rn(v - __bfloat162float(h));
        }
        if (o16) o16[base + i] = __float2half_rn(v);
    }
}

// ================= mixed-precision mma.sync GEMM =================
// MODE 0: bf16x3. MODE 1: fp16x2. MODE 2: fp16x1.
// flags: 1=bias 2=gelu 4=resid 8=qkv(rope+scatter) 16=score 32=ctx
//        64=bf16 hi/lo out 256=fp16 hi/lo out 512=fp16 single out
#define PPA 10240u            // A part bytes (128 rows * 80B)

template<int BN, int MODE, int MINCTAS, int NSTG>
__global__ __launch_bounds__(256, MINCTAS) void gemm_mp(
    const void* __restrict__ Ahv, const void* __restrict__ Alv,
    const void* __restrict__ Bhv, const void* __restrict__ Blv,
    const float* __restrict__ bias, const float* __restrict__ resid,
    float* __restrict__ Cf, void* __restrict__ Chv, void* __restrict__ Clv,
    const int* __restrict__ pid,
    int K, int lda, int ldb, int ldc, int flags)
{
    constexpr uint32_t PPB = (uint32_t)BN * 80u;
    constexpr uint32_t APARTS = (MODE == 2) ? 1u : 2u;
    constexpr uint32_t BPARTS = (MODE == 0) ? 2u : 1u;
    constexpr uint32_t STG = APARTS * PPA + BPARTS * PPB;
    constexpr int NFR = BN / 32;
    constexpr int NPAIR = NFR / 2;
    extern __shared__ char sm[];
    int bx = blockIdx.x, by = blockIdx.y, bz = blockIdx.z;
    const uint16_t* Ahp = (const uint16_t*)Ahv;
    const uint16_t* Alp = (const uint16_t*)Alv;
    const uint16_t* Bhp = (const uint16_t*)Bhv;
    const uint16_t* Blp = (const uint16_t*)Blv;
    float* Cfp = Cf;
    uint16_t* Chp = (uint16_t*)Chv;
    uint16_t* Clp = (uint16_t*)Clv;
    int Keff = K;
    const int tid = threadIdx.x, lane = tid & 31, warp = tid >> 5;
    if (flags & 16) {
        int b = bz >> 4, h = bz & 15;
        size_t ao = (size_t)b * Ss * Dd + h * DHd;
        Ahp += ao; Alp += ao; Bhp += ao; Blp += ao;
        Cfp += (size_t)bz * Ss * Ss;
        if (bx * BN > by * 128 + 127) {
            // fully-masked tile: zero-fill attn fp32 here (DRAM idle in this kernel);
            // softmax then only stores [0, Lpad) per row.
            float4 z = make_float4(0.f, 0.f, 0.f, 0.f);
            float* tb = Cfp + (size_t)(by * 128) * ldc + bx * BN;
#pragma unroll
            for (int i = 0; i < (128 * BN / 4) / 256; i++) {
                int idx = tid + i * 256;
                int r = idx / (BN / 4), c4 = (idx % (BN / 4)) * 4;
                *(float4*)(tb + (size_t)r * ldc + c4) = z;
            }
            return;
        }
    }
    if (flags & 32) {
        bz = blockIdx.x;
        by = gridDim.y - 1 - blockIdx.y;
        bx = 0;
        int b = bz >> 4, h = bz & 15;
        size_t ao = (size_t)bz * Ss * Ss;
        size_t bo = (size_t)bz * DHd * Ss;
        Ahp += ao; Alp += ao; Bhp += bo; Blp += bo;
        size_t co = (size_t)b * Ss * Dd + h * DHd;
        Chp += co; Clp += co;
        Keff = (by + 1) * 128;
    }
    const int m0 = by * 128, n0 = bx * BN;
    const int wm = (warp >> 2) * 64, wn = (warp & 3) * (BN / 4);
    const uint32_t sbase = smem_u32(sm);

    float acc[4][NFR][4];
#pragma unroll
    for (int i = 0; i < 4; i++)
#pragma unroll
        for (int j = 0; j < NFR; j++)
#pragma unroll
            for (int e = 0; e < 4; e++) acc[i][j][e] = 0.f;

#define ISSUE_CHUNK(ST, K0) do { \
    uint32_t sb0 = sbase + (uint32_t)(ST) * STG; \
    _Pragma("unroll") \
    for (int i = 0; i < 2; i++) { \
        int idx = tid + i * 256; \
        int r = idx >> 2; int cc = idx & 3; \
        uint32_t d = sb0 + (uint32_t)r * 80u + (uint32_t)cc * 16u; \
        size_t sa = (size_t)(m0 + r) * lda + (K0) + cc * 8; \
        cp16(d, Ahp + sa); \
        if (MODE != 2) cp16(d + PPA, Alp + sa); \
    } \
    _Pragma("unroll") \
    for (int i = 0; i < BN / 64; i++) { \
        int idx = tid + i * 256; \
        int r = idx >> 2; int cc = idx & 3; \
        uint32_t d = sb0 + APARTS * PPA + (uint32_t)r * 80u + (uint32_t)cc * 16u; \
        size_t sb2 = (size_t)(n0 + r) * ldb + (K0) + cc * 8; \
        cp16(d, Bhp + sb2); \
        if (MODE == 0) cp16(d + PPB, Blp + sb2); \
    } \
    cp_commit(); \
} while(0)

    const uint32_t a_lane_off = (uint32_t)(wm + (lane & 15)) * 80u + (uint32_t)((lane >> 4) * 16);
    const uint32_t b_lane_off = (uint32_t)(wn + ((lane >> 4) * 8) + (lane & 7)) * 80u
                              + (uint32_t)(((lane >> 3) & 1) * 16);

    auto compute_chunk = [&](uint32_t boff) {
#pragma unroll
        for (int ks = 0; ks < 2; ks++) {
            uint32_t ahi[4][4], alo[4][4];
            uint32_t abase = sbase + boff + a_lane_off + (uint32_t)(ks * 32);
            uint32_t bbase = sbase + boff + APARTS * PPA + b_lane_off + (uint32_t)(ks * 32);
#pragma unroll
            for (int mti = 0; mti < 4; mti++) {
                ldm4(ahi[mti], abase + (uint32_t)(mti * 16) * 80u);
                if (MODE != 2) ldm4(alo[mti], abase + (uint32_t)(mti * 16) * 80u + PPA);
            }
#pragma unroll
            for (int p = 0; p < NPAIR; p++) {
                uint32_t bh4[4];
                ldm4(bh4, bbase + (uint32_t)(p * 16) * 80u);
                if (MODE == 0) {
                    uint32_t bl4[4];
                    ldm4(bl4, bbase + (uint32_t)(p * 16) * 80u + PPB);
#pragma unroll
                    for (int mti = 0; mti < 4; mti++) {
                        mma_bf16(acc[mti][2 * p],     ahi[mti], bh4);
                        mma_bf16(acc[mti][2 * p + 1], ahi[mti], bh4 + 2);
                    }
#pragma unroll
                    for (int mti = 0; mti < 4; mti++) {
                        mma_bf16(acc[mti][2 * p],     ahi[mti], bl4);
                        mma_bf16(acc[mti][2 * p + 1], ahi[mti], bl4 + 2);
                    }
#pragma unroll
                    for (int mti = 0; mti < 4; mti++) {
                        mma_bf16(acc[mti][2 * p],     alo[mti], bh4);
                        mma_bf16(acc[mti][2 * p + 1], alo[mti], bh4 + 2);
                    }
                } else if (MODE == 1) {
#pragma unroll
                    for (int mti = 0; mti < 4; mti++) {
                        mma_fp16(acc[mti][2 * p],     ahi[mti], bh4);
                        mma_fp16(acc[mti][2 * p + 1], ahi[mti], bh4 + 2);
                    }
#pragma unroll
                    for (int mti = 0; mti < 4; mti++) {
                        mma_fp16(acc[mti][2 * p],     alo[mti], bh4);
                        mma_fp16(acc[mti][2 * p + 1], alo[mti], bh4 + 2);
                    }
                } else {
#pragma unroll
                    for (int mti = 0; mti < 4; mti++) {
                        mma_fp16(acc[mti][2 * p],     ahi[mti], bh4);
                        mma_fp16(acc[mti][2 * p + 1], ahi[mti], bh4 + 2);
                    }
                }
            }
        }
    };

    const int nch = Keff / 32;
    if (NSTG == 2) {
        ISSUE_CHUNK(0, 0);
        for (int c = 0; c < nch; c++) {
            if (c + 1 < nch) { ISSUE_CHUNK((c + 1) & 1, (c + 1) * 32); cp_wait1(); }
            else cp_wait0();
            __syncthreads();
            compute_chunk((uint32_t)(c & 1) * STG);
            __syncthreads();
        }
    } else {
#pragma unroll
        for (int s = 0; s < NSTG - 1; s++)
            if (s < nch) ISSUE_CHUNK(s, s * 32);
        for (int c = 0; c < nch; c++) {
            int rem = nch - 1 - c;
            if (NSTG >= 4 && rem >= 2) cp_wait2();
            else if (rem >= 1) cp_wait1();
            else cp_wait0();
            __syncthreads();
            compute_chunk((uint32_t)(c % NSTG) * STG);
            if (c + NSTG - 1 < nch) ISSUE_CHUNK((c + NSTG - 1) % NSTG, (c + NSTG - 1) * 32);
        }
    }
#undef ISSUE_CHUNK

    // ---------------- epilogue ----------------
#pragma unroll
    for (int mti = 0; mti < 4; mti++) {
#pragma unroll
        for (int ntj = 0; ntj < NFR; ntj++) {
            int row = m0 + wm + mti * 16 + (lane >> 2);
            int col = n0 + wn + ntj * 8 + (lane & 3) * 2;
#pragma unroll
            for (int half = 0; half < 2; half++) {
                int rr = row + half * 8;
                float v0 = acc[mti][ntj][half * 2];
                float v1 = acc[mti][ntj][half * 2 + 1];
                if (flags & 1) { v0 += bias[col]; v1 += bias[col + 1]; }
                if (flags & 2) {
                    v0 = 0.5f * v0 * (1.0f + erff(v0 * 0.70710678118654752f));
                    v1 = 0.5f * v1 * (1.0f + erff(v1 * 0.70710678118654752f));
                }
                if (flags & 4) {
                    const float* rp = resid + (size_t)rr * ldc + col;
                    v0 += rp[0]; v1 += rp[1];
                }
                if (flags & 8) {
                    int sel = col >> 11, cl = col & 2047;
                    int b = rr >> 11, s = rr & 2047;
                    int pos = pid[b * Ss + s];
                    int i = (cl & 127) >> 1;
                    float sn = g_sin[pos * 64 + i], cs = g_cos[pos * 64 + i];
                    float r0 = v0 * cs - v1 * sn;
                    float r1 = v1 * cs + v0 * sn;
                    size_t o = (size_t)(sel * ROWS + rr) * Dd + cl;
                    split2(r0, r1, (bf16*)(Chp + o), (bf16*)(Clp + o));
                } else if (flags & 64) {
                    size_t o = (size_t)rr * ldc + col;
                    split2(v0, v1, (bf16*)(Chp + o), (bf16*)(Clp + o));
                } else if (flags & 256) {
                    size_t o = (size_t)rr * ldc + col;
                    split2h(v0, v1, (__half*)(Chp + o), (__half*)(Clp + o));
                } else if (flags & 512) {
                    size_t o = (size_t)rr * ldc + col;
                    *(__half2*)((__half*)Chp + o) = __floats2half2_rn(v0, v1);
                } else {
                    *(float2*)(Cfp + (size_t)rr * ldc + col) = make_float2(v0, v1);
                }
            }
        }
    }
}

// ================= row softmax (causal trunc, vectorized, read+write skip) =================
__global__ __launch_bounds__(256) void softmax_kernel(
    float* __restrict__ attn, __half* __restrict__ ah, __half* __restrict__ al)
{
    int rid = blockIdx.x;
    int qpos = rid & (Ss - 1);
    int L = qpos + 1;
    int Lpad = ((qpos >> 7) + 1) << 7;
    float* row = attn + (size_t)rid * Ss;
    __half* rh = ah + (size_t)rid * Ss;
    __half* rl = al + (size_t)rid * Ss;
    __shared__ float red[256];
    int tid = threadIdx.x;
    int base = tid * 8;
    float r[8];
    if (base < L) {
        float4 ra = *(const float4*)(row + base);
        float4 rb = *(const float4*)(row + base + 4);
        r[0] = ra.x; r[1] = ra.y; r[2] = ra.z; r[3] = ra.w;
        r[4] = rb.x; r[5] = rb.y; r[6] = rb.z; r[7] = rb.w;
    } else {
#pragma unroll
        for (int t = 0; t < 8; t++) r[t] = -3.4e38f;
    }
    float mx = -3.4e38f;
#pragma unroll
    for (int t = 0; t < 8; t++) {
        if (base + t >= L) r[t] = -3.4e38f;
        mx = fmaxf(mx, r[t]);
    }
    red[tid] = mx; __syncthreads();
    for (int o = 128; o > 0; o >>= 1) { if (tid < o) red[tid] = fmaxf(red[tid], red[tid + o]); __syncthreads(); }
    mx = red[0]; __syncthreads();
    float s = 0.f;
#pragma unroll
    for (int t = 0; t < 8; t++) {
        float e = (base + t < L) ? expf(r[t] - mx) : 0.0f;
        r[t] = e; s += e;
    }
    red[tid] = s; __syncthreads();
    for (int o = 128; o > 0; o >>= 1) { if (tid < o) red[tid] += red[tid + o]; __syncthreads(); }
    float inv = 1.0f / red[0];
#pragma unroll
    for (int t = 0; t < 8; t++) r[t] *= inv;
    if (base < Lpad) {
        // fp32 graded output: zeros beyond Lpad are written by the score kernel's
        // skipped-tile fill; rows [L, Lpad) get zeros here (r[t]=0 there).
        *(float4*)(row + base)     = make_float4(r[0], r[1], r[2], r[3]);
        *(float4*)(row + base + 4) = make_float4(r[4], r[5], r[6], r[7]);
        __half2 hh[4], ll[4];
#pragma unroll
        for (int j = 0; j < 4; j++) {
            __half h0 = __float2half_rn(r[2 * j]), h1 = __float2half_rn(r[2 * j + 1]);
            hh[j] = __halves2half2(h0, h1);
            ll[j] = __floats2half2_rn(r[2 * j] - __half2float(h0), r[2 * j + 1] - __half2float(h1));
        }
        *(uint4*)(rh + base) = *(uint4*)hh;
        *(uint4*)(rl + base) = *(uint4*)ll;
    }
}

// ================= launch =================
extern "C" void kernel_launch(void* const* d_in, const int* in_sizes, int n_in,
                              void* d_out, int out_size)
{
    const float* hs   = (const float*)d_in[0];
    const int*   pid  = (const int*)  d_in[1];
    const float* wq   = (const float*)d_in[2];
    const float* wk   = (const float*)d_in[3];
    const float* wv   = (const float*)d_in[4];
    const float* wo   = (const float*)d_in[5];
    const float* ln1g = (const float*)d_in[6];
    const float* ln1b = (const float*)d_in[7];
    const float* ln2g = (const float*)d_in[8];
    const float* ln2b = (const float*)d_in[9];
    const float* fiw  = (const float*)d_in[10];
    const float* fib  = (const float*)d_in[11];
    const float* fow  = (const float*)d_in[12];
    const float* fob  = (const float*)d_in[13];

    float* out  = (float*)d_out;
    float* attn = out + (size_t)ROWS * Dd;

    float *aproj, *h2;
    bf16 *h1h, *h1l, *wqkh, *wqkl, *qkh, *qkl;
    __half *h116, *wvt, *wof, *fif, *fof, *v16, *vt16, *ah16, *al16;
    __half *ctxh16, *ctxl16, *h216, *ffn16;
    cudaGetSymbolAddress((void**)&aproj,  g_aproj);
    cudaGetSymbolAddress((void**)&h2,     g_h2);
    cudaGetSymbolAddress((void**)&h1h,    g_h1h);
    cudaGetSymbolAddress((void**)&h1l,    g_h1l);
    cudaGetSymbolAddress((void**)&h116,   g_h116);
    cudaGetSymbolAddress((void**)&wqkh,   g_wqkh);
    cudaGetSymbolAddress((void**)&wqkl,   g_wqkl);
    cudaGetSymbolAddress((void**)&wvt,    g_wvt16);
    cudaGetSymbolAddress((void**)&wof,    g_wof16);
    cudaGetSymbolAddress((void**)&fif,    g_fif16);
    cudaGetSymbolAddress((void**)&fof,    g_fof16);
    cudaGetSymbolAddress((void**)&qkh,    g_qkh);
    cudaGetSymbolAddress((void**)&qkl,    g_qkl);
    cudaGetSymbolAddress((void**)&v16,    g_v16);
    cudaGetSymbolAddress((void**)&vt16,   g_vt16);
    cudaGetSymbolAddress((void**)&ah16,   g_ah16);
    cudaGetSymbolAddress((void**)&al16,   g_al16);
    cudaGetSymbolAddress((void**)&ctxh16, g_ctxh16);
    cudaGetSymbolAddress((void**)&ctxl16, g_ctxl16);
    cudaGetSymbolAddress((void**)&h216,   g_h216);
    cudaGetSymbolAddress((void**)&ffn16,  g_ffn16);

    const uint32_t SMT128_0 = 2u * (2u * PPA + 2u * 128u * 80u);   // 81920, 2 CTAs
    const uint32_t SMT128_1 = 3u * (2u * PPA + 1u * 128u * 80u);   // 92160, 2 CTAs
    const uint32_t SMT128_2 = 4u * (1u * PPA + 1u * 128u * 80u);   // 81920, 2 CTAs
    cudaFuncSetAttribute((const void*)gemm_mp<128, 0, 2, 2>, cudaFuncAttributeMaxDynamicSharedMemorySize, SMT128_0);
    cudaFuncSetAttribute((const void*)gemm_mp<128, 1, 2, 3>, cudaFuncAttributeMaxDynamicSharedMemorySize, SMT128_1);
    cudaFuncSetAttribute((const void*)gemm_mp<128, 2, 2, 4>, cudaFuncAttributeMaxDynamicSharedMemorySize, SMT128_2);

    // fused prep: all weight transposes + rope table in one launch
    prep_kernel<<<25088, 256>>>(wq, wk, wv, wo, fiw, fow,
                                wqkh, wqkl, wvt, wof, fif, fof);

    // ln1 -> bf16 hi/lo (for qk) + fp16 single (for v)
    ln_kernel<<<ROWS, 256>>>(hs, nullptr, ln1g, ln1b, nullptr, h1h, h1l, h116);

    // qk projection (bf16x3, BN=128, 2 CTAs/SM, RoPE in epilogue); v projection (fp16x1)
    gemm_mp<128, 0, 2, 2><<<dim3(32, 32), 256, SMT128_0>>>(h1h, h1l, wqkh, wqkl,
        nullptr, nullptr, nullptr, qkh, qkl, pid, Dd, Dd, Dd, Dd, 8);
    gemm_mp<128, 2, 2, 4><<<dim3(16, 32), 256, SMT128_2>>>(h116, nullptr, wvt, nullptr,
        nullptr, nullptr, nullptr, v16, nullptr, nullptr, Dd, Dd, Dd, Dd, 512);

    dim3 tb(32, 8);
    vtrans_h<<<dim3(DHd / 32, Ss / 64, Bb * Hh), tb>>>(v16, vt16);

    // scores (bf16x3, causal, zero-fill of masked tiles) -> softmax -> ctx (fp16x2)
    gemm_mp<128, 0, 2, 2><<<dim3(16, 16, Bb * Hh), 256, SMT128_0>>>(qkh, qkl,
        qkh + (size_t)ROWS * Dd, qkl + (size_t)ROWS * Dd,
        nullptr, nullptr, attn, nullptr, nullptr, nullptr, DHd, Dd, Dd, Ss, 16);
    softmax_kernel<<<Bb * Hh * Ss, 256>>>(attn, ah16, al16);
    gemm_mp<128, 1, 2, 3><<<dim3(Bb * Hh, 16), 256, SMT128_1>>>(ah16, al16, vt16, nullptr,
        nullptr, nullptr, nullptr, ctxh16, ctxl16, nullptr, Ss, Ss, Ss, Dd, 32 | 256);

    // output projection (fp16x2)
    gemm_mp<128, 1, 2, 3><<<dim3(16, 32), 256, SMT128_1>>>(ctxh16, ctxl16, wof, nullptr,
        nullptr, nullptr, aproj, nullptr, nullptr, nullptr, Dd, Dd, Dd, Dd, 0);

    // ln2 -> fp32 + fp16 single
    ln_kernel<<<ROWS, 256>>>(hs, aproj, ln2g, ln2b, h2, nullptr, nullptr, h216);

    // FFN (fp16x1)
    gemm_mp<128, 2, 2, 4><<<dim3(64, 32), 256, SMT128_2>>>(h216, nullptr, fif, nullptr,
        fib, nullptr, nullptr, ffn16, nullptr, nullptr, Dd, Dd, Dd, FFf, 1 | 2 | 512);
    gemm_mp<128, 2, 2, 4><<<dim3(16, 32), 256, SMT128_2>>>(ffn16, nullptr, fof, nullptr,
        fob, h2, out, nullptr, nullptr, nullptr, FFf, FFf, FFf, Dd, 1 | 4);
}

// round 15
// speedup vs baseline: 2.0185x; 1.0274x over previous
#include <cuda_runtime.h>
#include <cuda_bf16.h>
#include <cuda_fp16.h>
#include <math.h>
#include <stdint.h>

#define Bb   2
#define Ss   2048
#define Dd   2048
#define Hh   16
#define DHd  128
#define FFf  8192
#define ROWS 4096   // B*S

typedef __nv_bfloat16 bf16;

// ================= scratch (device globals) =================
__device__ bf16  g_h1h[(size_t)ROWS * Dd],  g_h1l[(size_t)ROWS * Dd];
__device__ __half g_h116[(size_t)ROWS * Dd];
__device__ bf16  g_wqkh[(size_t)2 * Dd * Dd], g_wqkl[(size_t)2 * Dd * Dd];
__device__ __half g_wvt16[(size_t)Dd * Dd];
__device__ __half g_wof16[(size_t)Dd * Dd];
__device__ __half g_fif16[(size_t)Dd * FFf];
__device__ __half g_fof16[(size_t)Dd * FFf];
__device__ bf16  g_qkh[(size_t)2 * ROWS * Dd], g_qkl[(size_t)2 * ROWS * Dd];
__device__ __half g_v16[(size_t)ROWS * Dd];
__device__ __half g_vt16[(size_t)Bb * Hh * DHd * Ss];
__device__ __half g_ah16[(size_t)Bb * Hh * Ss * Ss];
__device__ __half g_ctxh16[(size_t)ROWS * Dd], g_ctxl16[(size_t)ROWS * Dd];
__device__ float g_aproj[(size_t)ROWS * Dd];
__device__ float g_h2[(size_t)ROWS * Dd];
__device__ __half g_h216[(size_t)ROWS * Dd];
__device__ __half g_ffn16[(size_t)ROWS * FFf];
__device__ float g_sin[Ss * 64];
__device__ float g_cos[Ss * 64];

// ================= helpers =================
__device__ __forceinline__ uint32_t smem_u32(const void* p) {
    uint32_t a;
    asm("{ .reg .u64 t; cvta.to.shared.u64 t, %1; cvt.u32.u64 %0, t; }" : "=r"(a) : "l"(p));
    return a;
}
__device__ __forceinline__ void ldm4(uint32_t* r, uint32_t addr) {
    asm volatile("ldmatrix.sync.aligned.m8n8.x4.shared.b16 {%0,%1,%2,%3}, [%4];"
        : "=r"(r[0]), "=r"(r[1]), "=r"(r[2]), "=r"(r[3]) : "r"(addr));
}
__device__ __forceinline__ void mma_bf16(float* c, const uint32_t* a, const uint32_t* b) {
    asm volatile(
        "mma.sync.aligned.m16n8k16.row.col.f32.bf16.bf16.f32 "
        "{%0,%1,%2,%3}, {%4,%5,%6,%7}, {%8,%9}, {%0,%1,%2,%3};"
        : "+f"(c[0]), "+f"(c[1]), "+f"(c[2]), "+f"(c[3])
        : "r"(a[0]), "r"(a[1]), "r"(a[2]), "r"(a[3]), "r"(b[0]), "r"(b[1]));
}
__device__ __forceinline__ void mma_fp16(float* c, const uint32_t* a, const uint32_t* b) {
    asm volatile(
        "mma.sync.aligned.m16n8k16.row.col.f32.f16.f16.f32 "
        "{%0,%1,%2,%3}, {%4,%5,%6,%7}, {%8,%9}, {%0,%1,%2,%3};"
        : "+f"(c[0]), "+f"(c[1]), "+f"(c[2]), "+f"(c[3])
        : "r"(a[0]), "r"(a[1]), "r"(a[2]), "r"(a[3]), "r"(b[0]), "r"(b[1]));
}
__device__ __forceinline__ void cp16(uint32_t dst, const void* src) {
    asm volatile("cp.async.cg.shared.global [%0], [%1], 16;" :: "r"(dst), "l"(src));
}
__device__ __forceinline__ void cp_commit() { asm volatile("cp.async.commit_group;"); }
__device__ __forceinline__ void cp_wait2() { asm volatile("cp.async.wait_group 2;"); }
__device__ __forceinline__ void cp_wait1() { asm volatile("cp.async.wait_group 1;"); }
__device__ __forceinline__ void cp_wait0() { asm volatile("cp.async.wait_group 0;"); }

__device__ __forceinline__ void split2(float x, float y, bf16* ph, bf16* pl) {
    bf16 hx = __float2bfloat16_rn(x), hy = __float2bfloat16_rn(y);
    float fx = __bfloat162float(hx), fy = __bfloat162float(hy);
    __nv_bfloat162 h2; h2.x = hx; h2.y = hy;
    __nv_bfloat162 l2; l2.x = __float2bfloat16_rn(x - fx); l2.y = __float2bfloat16_rn(y - fy);
    *(__nv_bfloat162*)ph = h2;
    *(__nv_bfloat162*)pl = l2;
}
__device__ __forceinline__ void split2h(float x, float y, __half* ph, __half* pl) {
    __half hx = __float2half_rn(x), hy = __float2half_rn(y);
    __half2 h2 = __halves2half2(hx, hy);
    __half2 l2 = __floats2half2_rn(x - __half2float(hx), y - __half2float(hy));
    *(__half2*)ph = h2;
    *(__half2*)pl = l2;
}

// ================= fused prep: 6 weight transposes + rope table =================
__device__ __forceinline__ void dev_tsplit(
    float (*t)[33], const float* __restrict__ in,
    bf16* __restrict__ oh, bf16* __restrict__ ol,
    int R, int Cc, int bxb, int byb)
{
    int bx = bxb * 32, by = byb * 64;
    int tx = threadIdx.x & 31, ty = threadIdx.x >> 5;
#pragma unroll
    for (int i = 0; i < 64; i += 8)
        t[ty + i][tx] = in[(size_t)(by + ty + i) * Cc + bx + tx];
    __syncthreads();
#pragma unroll
    for (int i = 0; i < 32; i += 8) {
        int r = ty + i;
        size_t o = (size_t)(bx + r) * R + by + 2 * tx;
        split2(t[2 * tx][r], t[2 * tx + 1][r], oh + o, ol + o);
    }
}
__device__ __forceinline__ void dev_tfp16(
    float (*t)[33], const float* __restrict__ in, __half* __restrict__ oh,
    int R, int Cc, int bxb, int byb)
{
    int bx = bxb * 32, by = byb * 64;
    int tx = threadIdx.x & 31, ty = threadIdx.x >> 5;
#pragma unroll
    for (int i = 0; i < 64; i += 8)
        t[ty + i][tx] = in[(size_t)(by + ty + i) * Cc + bx + tx];
    __syncthreads();
#pragma unroll
    for (int i = 0; i < 32; i += 8) {
        int r = ty + i;
        __half2 h2 = __floats2half2_rn(t[2 * tx][r], t[2 * tx + 1][r]);
        *(__half2*)(oh + (size_t)(bx + r) * R + by + 2 * tx) = h2;
    }
}

__global__ __launch_bounds__(256) void prep_kernel(
    const float* __restrict__ wq, const float* __restrict__ wk,
    const float* __restrict__ wv, const float* __restrict__ wo,
    const float* __restrict__ fiw, const float* __restrict__ fow,
    bf16* __restrict__ wqkh, bf16* __restrict__ wqkl,
    __half* __restrict__ wvt, __half* __restrict__ wof,
    __half* __restrict__ fif, __half* __restrict__ fof)
{
    __shared__ float t[64][33];
    int id = blockIdx.x;
    if (id < 2048) {
        dev_tsplit(t, wq, wqkh, wqkl, Dd, Dd, id & 63, id >> 6);
    } else if (id < 4096) {
        id -= 2048;
        dev_tsplit(t, wk, wqkh + (size_t)Dd * Dd, wqkl + (size_t)Dd * Dd, Dd, Dd, id & 63, id >> 6);
    } else if (id < 6144) {
        id -= 4096;
        dev_tfp16(t, wv, wvt, Dd, Dd, id & 63, id >> 6);
    } else if (id < 8192) {
        id -= 6144;
        dev_tfp16(t, wo, wof, Dd, Dd, id & 63, id >> 6);
    } else if (id < 16384) {
        id -= 8192;
        dev_tfp16(t, fiw, fif, Dd, FFf, id & 255, id >> 8);
    } else if (id < 24576) {
        id -= 16384;
        dev_tfp16(t, fow, fof, FFf, Dd, id & 63, id >> 6);
    } else {
        int tt = (id - 24576) * 256 + threadIdx.x;
        int p = tt >> 6, i = tt & 63;
        double inv = pow(10000.0, -((double)(2 * i)) / 128.0);
        float ang = (float)p * (float)inv;
        g_sin[tt] = (float)sin((double)ang);
        g_cos[tt] = (float)cos((double)ang);
    }
}

// V^T per head, fp16 in/out
__global__ __launch_bounds__(256) void vtrans_h(
    const __half* __restrict__ v, __half* __restrict__ oh)
{
    __shared__ float t[64][33];
    int bh = blockIdx.z;
    int b = bh >> 4, h = bh & 15;
    const __half* in = v + (size_t)b * Ss * Dd + h * DHd;
    size_t obase = (size_t)bh * DHd * Ss;
    int n0 = blockIdx.x * 32, s0 = blockIdx.y * 64;
    int tx = threadIdx.x, ty = threadIdx.y;
#pragma unroll
    for (int i = 0; i < 64; i += 8)
        t[ty + i][tx] = __half2float(in[(size_t)(s0 + ty + i) * Dd + n0 + tx]);
    __syncthreads();
#pragma unroll
    for (int i = 0; i < 32; i += 8) {
        int r = ty + i;
        __half2 h2 = __floats2half2_rn(t[2 * tx][r], t[2 * tx + 1][r]);
        *(__half2*)(oh + obase + (size_t)(n0 + r) * Ss + s0 + 2 * tx) = h2;
    }
}

// ================= LayerNorm =================
__global__ __launch_bounds__(256) void ln_kernel(
    const float* __restrict__ x, const float* __restrict__ x2,
    const float* __restrict__ g, const float* __restrict__ bta,
    float* __restrict__ outf, bf16* __restrict__ outh, bf16* __restrict__ outl,
    __half* __restrict__ o16)
{
    __shared__ float red[256];
    int row = blockIdx.x, tid = threadIdx.x;
    size_t base = (size_t)row * Dd;
    float r[8];
    float s = 0.f;
#pragma unroll
    for (int t = 0; t < 8; t++) {
        int i = tid + t * 256;
        float v = x[base + i];
        if (x2) v += x2[base + i];
        r[t] = v; s += v;
    }
    red[tid] = s; __syncthreads();
    for (int o = 128; o > 0; o >>= 1) { if (tid < o) red[tid] += red[tid + o]; __syncthreads(); }
    float mean = red[0] * (1.0f / Dd);
    __syncthreads();
    float vs = 0.f;
#pragma unroll
    for (int t = 0; t < 8; t++) { float d = r[t] - mean; vs += d * d; }
    red[tid] = vs; __syncthreads();
    for (int o = 128; o > 0; o >>= 1) { if (tid < o) red[tid] += red[tid + o]; __syncthreads(); }
    float var = red[0] * (1.0f / Dd);
    float rs = rsqrtf(var + 1e-5f);
#pragma unroll
    for (int t = 0; t < 8; t++) {
        int i = tid + t * 256;
        float v = (r[t] - mean) * rs * g[i] + bta[i];
        if (outf) outf[base + i] = v;
        if (outh) {
            bf16 h = __float2bfloat16_rn(v);
            outh[base + i] = h;
            outl[base + i] = __float2bfloat16_rn(v - __bfloat162float(h));
        }
        if (o16) o16[base + i] = __float2half_rn(v);
    }
}

// ================= mixed-precision mma.sync GEMM =================
// MODE 0: bf16x3. MODE 1: fp16x2. MODE 2: fp16x1.
// flags: 1=bias 2=gelu 4=resid 8=qkv(rope+scatter) 16=score 32=ctx
//        64=bf16 hi/lo out 256=fp16 hi/lo out 512=fp16 single out
#define PPA 10240u            // A part bytes (128 rows * 80B)

template<int BN, int MODE, int MINCTAS, int NSTG>
__global__ __launch_bounds__(256, MINCTAS) void gemm_mp(
    const void* __restrict__ Ahv, const void* __restrict__ Alv,
    const void* __restrict__ Bhv, const void* __restrict__ Blv,
    const float* __restrict__ bias, const float* __restrict__ resid,
    float* __restrict__ Cf, void* __restrict__ Chv, void* __restrict__ Clv,
    const int* __restrict__ pid,
    int K, int lda, int ldb, int ldc, int flags)
{
    constexpr uint32_t PPB = (uint32_t)BN * 80u;
    constexpr uint32_t APARTS = (MODE == 2) ? 1u : 2u;
    constexpr uint32_t BPARTS = (MODE == 0) ? 2u : 1u;
    constexpr uint32_t STG = APARTS * PPA + BPARTS * PPB;
    constexpr int NFR = BN / 32;
    constexpr int NPAIR = NFR / 2;
    extern __shared__ char sm[];
    int bx = blockIdx.x, by = blockIdx.y, bz = blockIdx.z;
    const uint16_t* Ahp = (const uint16_t*)Ahv;
    const uint16_t* Alp = (const uint16_t*)Alv;
    const uint16_t* Bhp = (const uint16_t*)Bhv;
    const uint16_t* Blp = (const uint16_t*)Blv;
    float* Cfp = Cf;
    uint16_t* Chp = (uint16_t*)Chv;
    uint16_t* Clp = (uint16_t*)Clv;
    int Keff = K;
    const int tid = threadIdx.x, lane = tid & 31, warp = tid >> 5;
    if (flags & 16) {
        int b = bz >> 4, h = bz & 15;
        size_t ao = (size_t)b * Ss * Dd + h * DHd;
        Ahp += ao; Alp += ao; Bhp += ao; Blp += ao;
        Cfp += (size_t)bz * Ss * Ss;
        if (bx * BN > by * 128 + 127) {
            // fully-masked tile: zero-fill attn fp32 here (DRAM idle in this kernel)
            float4 z = make_float4(0.f, 0.f, 0.f, 0.f);
            float* tb = Cfp + (size_t)(by * 128) * ldc + bx * BN;
#pragma unroll
            for (int i = 0; i < (128 * BN / 4) / 256; i++) {
                int idx = tid + i * 256;
                int r = idx / (BN / 4), c4 = (idx % (BN / 4)) * 4;
                *(float4*)(tb + (size_t)r * ldc + c4) = z;
            }
            return;
        }
    }
    if (flags & 32) {
        bz = blockIdx.x;
        by = gridDim.y - 1 - blockIdx.y;
        bx = 0;
        int b = bz >> 4, h = bz & 15;
        size_t ao = (size_t)bz * Ss * Ss;
        size_t bo = (size_t)bz * DHd * Ss;
        Ahp += ao; Alp += ao; Bhp += bo; Blp += bo;
        size_t co = (size_t)b * Ss * Dd + h * DHd;
        Chp += co; Clp += co;
        Keff = (by + 1) * 128;
    }
    const int m0 = by * 128, n0 = bx * BN;
    const int wm = (warp >> 2) * 64, wn = (warp & 3) * (BN / 4);
    const uint32_t sbase = smem_u32(sm);

    float acc[4][NFR][4];
#pragma unroll
    for (int i = 0; i < 4; i++)
#pragma unroll
        for (int j = 0; j < NFR; j++)
#pragma unroll
            for (int e = 0; e < 4; e++) acc[i][j][e] = 0.f;

#define ISSUE_CHUNK(ST, K0) do { \
    uint32_t sb0 = sbase + (uint32_t)(ST) * STG; \
    _Pragma("unroll") \
    for (int i = 0; i < 2; i++) { \
        int idx = tid + i * 256; \
        int r = idx >> 2; int cc = idx & 3; \
        uint32_t d = sb0 + (uint32_t)r * 80u + (uint32_t)cc * 16u; \
        size_t sa = (size_t)(m0 + r) * lda + (K0) + cc * 8; \
        cp16(d, Ahp + sa); \
        if (MODE != 2) cp16(d + PPA, Alp + sa); \
    } \
    _Pragma("unroll") \
    for (int i = 0; i < BN / 64; i++) { \
        int idx = tid + i * 256; \
        int r = idx >> 2; int cc = idx & 3; \
        uint32_t d = sb0 + APARTS * PPA + (uint32_t)r * 80u + (uint32_t)cc * 16u; \
        size_t sb2 = (size_t)(n0 + r) * ldb + (K0) + cc * 8; \
        cp16(d, Bhp + sb2); \
        if (MODE == 0) cp16(d + PPB, Blp + sb2); \
    } \
    cp_commit(); \
} while(0)

    const uint32_t a_lane_off = (uint32_t)(wm + (lane & 15)) * 80u + (uint32_t)((lane >> 4) * 16);
    const uint32_t b_lane_off = (uint32_t)(wn + ((lane >> 4) * 8) + (lane & 7)) * 80u
                              + (uint32_t)(((lane >> 3) & 1) * 16);

    auto compute_chunk = [&](uint32_t boff) {
#pragma unroll
        for (int ks = 0; ks < 2; ks++) {
            uint32_t ahi[4][4], alo[4][4];
            uint32_t abase = sbase + boff + a_lane_off + (uint32_t)(ks * 32);
            uint32_t bbase = sbase + boff + APARTS * PPA + b_lane_off + (uint32_t)(ks * 32);
#pragma unroll
            for (int mti = 0; mti < 4; mti++) {
                ldm4(ahi[mti], abase + (uint32_t)(mti * 16) * 80u);
                if (MODE != 2) ldm4(alo[mti], abase + (uint32_t)(mti * 16) * 80u + PPA);
            }
#pragma unroll
            for (int p = 0; p < NPAIR; p++) {
                uint32_t bh4[4];
                ldm4(bh4, bbase + (uint32_t)(p * 16) * 80u);
                if (MODE == 0) {
                    uint32_t bl4[4];
                    ldm4(bl4, bbase + (uint32_t)(p * 16) * 80u + PPB);
#pragma unroll
                    for (int mti = 0; mti < 4; mti++) {
                        mma_bf16(acc[mti][2 * p],     ahi[mti], bh4);
                        mma_bf16(acc[mti][2 * p + 1], ahi[mti], bh4 + 2);
                    }
#pragma unroll
                    for (int mti = 0; mti < 4; mti++) {
                        mma_bf16(acc[mti][2 * p],     ahi[mti], bl4);
                        mma_bf16(acc[mti][2 * p + 1], ahi[mti], bl4 + 2);
                    }
#pragma unroll
                    for (int mti = 0; mti < 4; mti++) {
                        mma_bf16(acc[mti][2 * p],     alo[mti], bh4);
                        mma_bf16(acc[mti][2 * p + 1], alo[mti], bh4 + 2);
                    }
                } else if (MODE == 1) {
#pragma unroll
                    for (int mti = 0; mti < 4; mti++) {
                        mma_fp16(acc[mti][2 * p],     ahi[mti], bh4);
                        mma_fp16(acc[mti][2 * p + 1], ahi[mti], bh4 + 2);
                    }
#pragma unroll
                    for (int mti = 0; mti < 4; mti++) {
                        mma_fp16(acc[mti][2 * p],     alo[mti], bh4);
                        mma_fp16(acc[mti][2 * p + 1], alo[mti], bh4 + 2);
                    }
                } else {
#pragma unroll
                    for (int mti = 0; mti < 4; mti++) {
                        mma_fp16(acc[mti][2 * p],     ahi[mti], bh4);
                        mma_fp16(acc[mti][2 * p + 1], ahi[mti], bh4 + 2);
                    }
                }
            }
        }
    };

    const int nch = Keff / 32;
    if (NSTG == 2) {
        ISSUE_CHUNK(0, 0);
        for (int c = 0; c < nch; c++) {
            if (c + 1 < nch) { ISSUE_CHUNK((c + 1) & 1, (c + 1) * 32); cp_wait1(); }
            else cp_wait0();
            __syncthreads();
            compute_chunk((uint32_t)(c & 1) * STG);
            __syncthreads();
        }
    } else {
#pragma unroll
        for (int s = 0; s < NSTG - 1; s++)
            if (s < nch) ISSUE_CHUNK(s, s * 32);
        for (int c = 0; c < nch; c++) {
            int rem = nch - 1 - c;
            if (NSTG >= 4 && rem >= 2) cp_wait2();
            else if (rem >= 1) cp_wait1();
            else cp_wait0();
            __syncthreads();
            compute_chunk((uint32_t)(c % NSTG) * STG);
            if (c + NSTG - 1 < nch) ISSUE_CHUNK((c + NSTG - 1) % NSTG, (c + NSTG - 1) * 32);
        }
    }
#undef ISSUE_CHUNK

    // ---------------- epilogue ----------------
#pragma unroll
    for (int mti = 0; mti < 4; mti++) {
#pragma unroll
        for (int ntj = 0; ntj < NFR; ntj++) {
            int row = m0 + wm + mti * 16 + (lane >> 2);
            int col = n0 + wn + ntj * 8 + (lane & 3) * 2;
#pragma unroll
            for (int half = 0; half < 2; half++) {
                int rr = row + half * 8;
                float v0 = acc[mti][ntj][half * 2];
                float v1 = acc[mti][ntj][half * 2 + 1];
                if (flags & 1) { v0 += bias[col]; v1 += bias[col + 1]; }
                if (flags & 2) {
                    v0 = 0.5f * v0 * (1.0f + erff(v0 * 0.70710678118654752f));
                    v1 = 0.5f * v1 * (1.0f + erff(v1 * 0.70710678118654752f));
                }
                if (flags & 4) {
                    const float* rp = resid + (size_t)rr * ldc + col;
                    v0 += rp[0]; v1 += rp[1];
                }
                if (flags & 8) {
                    int sel = col >> 11, cl = col & 2047;
                    int b = rr >> 11, s = rr & 2047;
                    int pos = pid[b * Ss + s];
                    int i = (cl & 127) >> 1;
                    float sn = g_sin[pos * 64 + i], cs = g_cos[pos * 64 + i];
                    float r0 = v0 * cs - v1 * sn;
                    float r1 = v1 * cs + v0 * sn;
                    size_t o = (size_t)(sel * ROWS + rr) * Dd + cl;
                    split2(r0, r1, (bf16*)(Chp + o), (bf16*)(Clp + o));
                } else if (flags & 64) {
                    size_t o = (size_t)rr * ldc + col;
                    split2(v0, v1, (bf16*)(Chp + o), (bf16*)(Clp + o));
                } else if (flags & 256) {
                    size_t o = (size_t)rr * ldc + col;
                    split2h(v0, v1, (__half*)(Chp + o), (__half*)(Clp + o));
                } else if (flags & 512) {
                    size_t o = (size_t)rr * ldc + col;
                    *(__half2*)((__half*)Chp + o) = __floats2half2_rn(v0, v1);
                } else {
                    *(float2*)(Cfp + (size_t)rr * ldc + col) = make_float2(v0, v1);
                }
            }
        }
    }
}

// ================= row softmax (causal trunc, vectorized) + single fp16 out =================
__global__ __launch_bounds__(256) void softmax_kernel(
    float* __restrict__ attn, __half* __restrict__ ah)
{
    int rid = blockIdx.x;
    int qpos = rid & (Ss - 1);
    int L = qpos + 1;
    int Lpad = ((qpos >> 7) + 1) << 7;
    float* row = attn + (size_t)rid * Ss;
    __half* rh = ah + (size_t)rid * Ss;
    __shared__ float red[256];
    int tid = threadIdx.x;
    int base = tid * 8;
    float r[8];
    if (base < L) {
        float4 ra = *(const float4*)(row + base);
        float4 rb = *(const float4*)(row + base + 4);
        r[0] = ra.x; r[1] = ra.y; r[2] = ra.z; r[3] = ra.w;
        r[4] = rb.x; r[5] = rb.y; r[6] = rb.z; r[7] = rb.w;
    } else {
#pragma unroll
        for (int t = 0; t < 8; t++) r[t] = -3.4e38f;
    }
    float mx = -3.4e38f;
#pragma unroll
    for (int t = 0; t < 8; t++) {
        if (base + t >= L) r[t] = -3.4e38f;
        mx = fmaxf(mx, r[t]);
    }
    red[tid] = mx; __syncthreads();
    for (int o = 128; o > 0; o >>= 1) { if (tid < o) red[tid] = fmaxf(red[tid], red[tid + o]); __syncthreads(); }
    mx = red[0]; __syncthreads();
    float s = 0.f;
#pragma unroll
    for (int t = 0; t < 8; t++) {
        float e = (base + t < L) ? expf(r[t] - mx) : 0.0f;
        r[t] = e; s += e;
    }
    red[tid] = s; __syncthreads();
    for (int o = 128; o > 0; o >>= 1) { if (tid < o) red[tid] += red[tid + o]; __syncthreads(); }
    float inv = 1.0f / red[0];
#pragma unroll
    for (int t = 0; t < 8; t++) r[t] *= inv;
    if (base < Lpad) {
        // fp32 graded output: zeros beyond Lpad come from the score kernel's fill
        *(float4*)(row + base)     = make_float4(r[0], r[1], r[2], r[3]);
        *(float4*)(row + base + 4) = make_float4(r[4], r[5], r[6], r[7]);
        __half2 hh[4];
#pragma unroll
        for (int j = 0; j < 4; j++)
            hh[j] = __floats2half2_rn(r[2 * j], r[2 * j + 1]);
        *(uint4*)(rh + base) = *(uint4*)hh;
    }
}

// ================= launch =================
extern "C" void kernel_launch(void* const* d_in, const int* in_sizes, int n_in,
                              void* d_out, int out_size)
{
    const float* hs   = (const float*)d_in[0];
    const int*   pid  = (const int*)  d_in[1];
    const float* wq   = (const float*)d_in[2];
    const float* wk   = (const float*)d_in[3];
    const float* wv   = (const float*)d_in[4];
    const float* wo   = (const float*)d_in[5];
    const float* ln1g = (const float*)d_in[6];
    const float* ln1b = (const float*)d_in[7];
    const float* ln2g = (const float*)d_in[8];
    const float* ln2b = (const float*)d_in[9];
    const float* fiw  = (const float*)d_in[10];
    const float* fib  = (const float*)d_in[11];
    const float* fow  = (const float*)d_in[12];
    const float* fob  = (const float*)d_in[13];

    float* out  = (float*)d_out;
    float* attn = out + (size_t)ROWS * Dd;

    float *aproj, *h2;
    bf16 *h1h, *h1l, *wqkh, *wqkl, *qkh, *qkl;
    __half *h116, *wvt, *wof, *fif, *fof, *v16, *vt16, *ah16;
    __half *ctxh16, *ctxl16, *h216, *ffn16;
    cudaGetSymbolAddress((void**)&aproj,  g_aproj);
    cudaGetSymbolAddress((void**)&h2,     g_h2);
    cudaGetSymbolAddress((void**)&h1h,    g_h1h);
    cudaGetSymbolAddress((void**)&h1l,    g_h1l);
    cudaGetSymbolAddress((void**)&h116,   g_h116);
    cudaGetSymbolAddress((void**)&wqkh,   g_wqkh);
    cudaGetSymbolAddress((void**)&wqkl,   g_wqkl);
    cudaGetSymbolAddress((void**)&wvt,    g_wvt16);
    cudaGetSymbolAddress((void**)&wof,    g_wof16);
    cudaGetSymbolAddress((void**)&fif,    g_fif16);
    cudaGetSymbolAddress((void**)&fof,    g_fof16);
    cudaGetSymbolAddress((void**)&qkh,    g_qkh);
    cudaGetSymbolAddress((void**)&qkl,    g_qkl);
    cudaGetSymbolAddress((void**)&v16,    g_v16);
    cudaGetSymbolAddress((void**)&vt16,   g_vt16);
    cudaGetSymbolAddress((void**)&ah16,   g_ah16);
    cudaGetSymbolAddress((void**)&ctxh16, g_ctxh16);
    cudaGetSymbolAddress((void**)&ctxl16, g_ctxl16);
    cudaGetSymbolAddress((void**)&h216,   g_h216);
    cudaGetSymbolAddress((void**)&ffn16,  g_ffn16);

    const uint32_t SMT128_0 = 2u * (2u * PPA + 2u * 128u * 80u);   // 81920, 2 CTAs
    const uint32_t SMT128_1 = 3u * (2u * PPA + 1u * 128u * 80u);   // 92160, 2 CTAs
    const uint32_t SMT128_2 = 4u * (1u * PPA + 1u * 128u * 80u);   // 81920, 2 CTAs
    cudaFuncSetAttribute((const void*)gemm_mp<128, 0, 2, 2>, cudaFuncAttributeMaxDynamicSharedMemorySize, SMT128_0);
    cudaFuncSetAttribute((const void*)gemm_mp<128, 1, 2, 3>, cudaFuncAttributeMaxDynamicSharedMemorySize, SMT128_1);
    cudaFuncSetAttribute((const void*)gemm_mp<128, 2, 2, 4>, cudaFuncAttributeMaxDynamicSharedMemorySize, SMT128_2);

    // fused prep: all weight transposes + rope table in one launch
    prep_kernel<<<25088, 256>>>(wq, wk, wv, wo, fiw, fow,
                                wqkh, wqkl, wvt, wof, fif, fof);

    // ln1 -> bf16 hi/lo (for qk) + fp16 single (for v)
    ln_kernel<<<ROWS, 256>>>(hs, nullptr, ln1g, ln1b, nullptr, h1h, h1l, h116);

    // qk projection (bf16x3, RoPE in epilogue); v projection (fp16x1)
    gemm_mp<128, 0, 2, 2><<<dim3(32, 32), 256, SMT128_0>>>(h1h, h1l, wqkh, wqkl,
        nullptr, nullptr, nullptr, qkh, qkl, pid, Dd, Dd, Dd, Dd, 8);
    gemm_mp<128, 2, 2, 4><<<dim3(16, 32), 256, SMT128_2>>>(h116, nullptr, wvt, nullptr,
        nullptr, nullptr, nullptr, v16, nullptr, nullptr, Dd, Dd, Dd, Dd, 512);

    dim3 tb(32, 8);
    vtrans_h<<<dim3(DHd / 32, Ss / 64, Bb * Hh), tb>>>(v16, vt16);

    // scores (bf16x3, causal, zero-fill) -> softmax (single fp16) -> ctx (fp16x1)
    gemm_mp<128, 0, 2, 2><<<dim3(16, 16, Bb * Hh), 256, SMT128_0>>>(qkh, qkl,
        qkh + (size_t)ROWS * Dd, qkl + (size_t)ROWS * Dd,
        nullptr, nullptr, attn, nullptr, nullptr, nullptr, DHd, Dd, Dd, Ss, 16);
    softmax_kernel<<<Bb * Hh * Ss, 256>>>(attn, ah16);
    gemm_mp<128, 2, 2, 4><<<dim3(Bb * Hh, 16), 256, SMT128_2>>>(ah16, nullptr, vt16, nullptr,
        nullptr, nullptr, nullptr, ctxh16, ctxl16, nullptr, Ss, Ss, Ss, Dd, 32 | 256);

    // output projection (fp16x2)
    gemm_mp<128, 1, 2, 3><<<dim3(16, 32), 256, SMT128_1>>>(ctxh16, ctxl16, wof, nullptr,
        nullptr, nullptr, aproj, nullptr, nullptr, nullptr, Dd, Dd, Dd, Dd, 0);

    // ln2 -> fp32 + fp16 single
    ln_kernel<<<ROWS, 256>>>(hs, aproj, ln2g, ln2b, h2, nullptr, nullptr, h216);

    // FFN (fp16x1)
    gemm_mp<128, 2, 2, 4><<<dim3(64, 32), 256, SMT128_2>>>(h216, nullptr, fif, nullptr,
        fib, nullptr, nullptr, ffn16, nullptr, nullptr, Dd, Dd, Dd, FFf, 1 | 2 | 512);
    gemm_mp<128, 2, 2, 4><<<dim3(16, 32), 256, SMT128_2>>>(ffn16, nullptr, fof, nullptr,
        fob, h2, out, nullptr, nullptr, nullptr, FFf, FFf, FFf, Dd, 1 | 4);
}

// round 16
// speedup vs baseline: 2.1332x; 1.0568x over previous
#include <cuda_runtime.h>
#include <cuda_bf16.h>
#include <cuda_fp16.h>
#include <math.h>
#include <stdint.h>

#define Bb   2
#define Ss   2048
#define Dd   2048
#define Hh   16
#define DHd  128
#define FFf  8192
#define ROWS 4096   // B*S

typedef __nv_bfloat16 bf16;

// ================= scratch (device globals) =================
__device__ bf16  g_h1h[(size_t)ROWS * Dd],  g_h1l[(size_t)ROWS * Dd];
__device__ __half g_h116[(size_t)ROWS * Dd];
__device__ bf16  g_wqkh[(size_t)2 * Dd * Dd], g_wqkl[(size_t)2 * Dd * Dd];
__device__ __half g_wvt16[(size_t)Dd * Dd];
__device__ __half g_wof16[(size_t)Dd * Dd];
__device__ __half g_fif16[(size_t)Dd * FFf];
__device__ __half g_fof16[(size_t)Dd * FFf];
__device__ bf16  g_qkh[(size_t)2 * ROWS * Dd], g_qkl[(size_t)2 * ROWS * Dd];
__device__ __half g_vt16[(size_t)Bb * Hh * DHd * Ss];
__device__ __half g_ah16[(size_t)Bb * Hh * Ss * Ss];
__device__ __half g_ctxh16[(size_t)ROWS * Dd];
__device__ float g_aproj[(size_t)ROWS * Dd];
__device__ float g_h2[(size_t)ROWS * Dd];
__device__ __half g_h216[(size_t)ROWS * Dd];
__device__ __half g_ffn16[(size_t)ROWS * FFf];
__device__ float g_sin[Ss * 64];
__device__ float g_cos[Ss * 64];

// ================= helpers =================
__device__ __forceinline__ uint32_t smem_u32(const void* p) {
    uint32_t a;
    asm("{ .reg .u64 t; cvta.to.shared.u64 t, %1; cvt.u32.u64 %0, t; }" : "=r"(a) : "l"(p));
    return a;
}
__device__ __forceinline__ void ldm4(uint32_t* r, uint32_t addr) {
    asm volatile("ldmatrix.sync.aligned.m8n8.x4.shared.b16 {%0,%1,%2,%3}, [%4];"
        : "=r"(r[0]), "=r"(r[1]), "=r"(r[2]), "=r"(r[3]) : "r"(addr));
}
__device__ __forceinline__ void mma_bf16(float* c, const uint32_t* a, const uint32_t* b) {
    asm volatile(
        "mma.sync.aligned.m16n8k16.row.col.f32.bf16.bf16.f32 "
        "{%0,%1,%2,%3}, {%4,%5,%6,%7}, {%8,%9}, {%0,%1,%2,%3};"
        : "+f"(c[0]), "+f"(c[1]), "+f"(c[2]), "+f"(c[3])
        : "r"(a[0]), "r"(a[1]), "r"(a[2]), "r"(a[3]), "r"(b[0]), "r"(b[1]));
}
__device__ __forceinline__ void mma_fp16(float* c, const uint32_t* a, const uint32_t* b) {
    asm volatile(
        "mma.sync.aligned.m16n8k16.row.col.f32.f16.f16.f32 "
        "{%0,%1,%2,%3}, {%4,%5,%6,%7}, {%8,%9}, {%0,%1,%2,%3};"
        : "+f"(c[0]), "+f"(c[1]), "+f"(c[2]), "+f"(c[3])
        : "r"(a[0]), "r"(a[1]), "r"(a[2]), "r"(a[3]), "r"(b[0]), "r"(b[1]));
}
__device__ __forceinline__ void cp16(uint32_t dst, const void* src) {
    asm volatile("cp.async.cg.shared.global [%0], [%1], 16;" :: "r"(dst), "l"(src));
}
__device__ __forceinline__ void cp_commit() { asm volatile("cp.async.commit_group;"); }
__device__ __forceinline__ void cp_wait2() { asm volatile("cp.async.wait_group 2;"); }
__device__ __forceinline__ void cp_wait1() { asm volatile("cp.async.wait_group 1;"); }
__device__ __forceinline__ void cp_wait0() { asm volatile("cp.async.wait_group 0;"); }

__device__ __forceinline__ void split2(float x, float y, bf16* ph, bf16* pl) {
    bf16 hx = __float2bfloat16_rn(x), hy = __float2bfloat16_rn(y);
    float fx = __bfloat162float(hx), fy = __bfloat162float(hy);
    __nv_bfloat162 h2; h2.x = hx; h2.y = hy;
    __nv_bfloat162 l2; l2.x = __float2bfloat16_rn(x - fx); l2.y = __float2bfloat16_rn(y - fy);
    *(__nv_bfloat162*)ph = h2;
    *(__nv_bfloat162*)pl = l2;
}
__device__ __forceinline__ void split2h(float x, float y, __half* ph, __half* pl) {
    __half hx = __float2half_rn(x), hy = __float2half_rn(y);
    __half2 h2 = __halves2half2(hx, hy);
    __half2 l2 = __floats2half2_rn(x - __half2float(hx), y - __half2float(hy));
    *(__half2*)ph = h2;
    *(__half2*)pl = l2;
}

// ================= fused prep: 6 weight transposes + rope table =================
__device__ __forceinline__ void dev_tsplit(
    float (*t)[33], const float* __restrict__ in,
    bf16* __restrict__ oh, bf16* __restrict__ ol,
    int R, int Cc, int bxb, int byb)
{
    int bx = bxb * 32, by = byb * 64;
    int tx = threadIdx.x & 31, ty = threadIdx.x >> 5;
#pragma unroll
    for (int i = 0; i < 64; i += 8)
        t[ty + i][tx] = in[(size_t)(by + ty + i) * Cc + bx + tx];
    __syncthreads();
#pragma unroll
    for (int i = 0; i < 32; i += 8) {
        int r = ty + i;
        size_t o = (size_t)(bx + r) * R + by + 2 * tx;
        split2(t[2 * tx][r], t[2 * tx + 1][r], oh + o, ol + o);
    }
}
__device__ __forceinline__ void dev_tfp16(
    float (*t)[33], const float* __restrict__ in, __half* __restrict__ oh,
    int R, int Cc, int bxb, int byb)
{
    int bx = bxb * 32, by = byb * 64;
    int tx = threadIdx.x & 31, ty = threadIdx.x >> 5;
#pragma unroll
    for (int i = 0; i < 64; i += 8)
        t[ty + i][tx] = in[(size_t)(by + ty + i) * Cc + bx + tx];
    __syncthreads();
#pragma unroll
    for (int i = 0; i < 32; i += 8) {
        int r = ty + i;
        __half2 h2 = __floats2half2_rn(t[2 * tx][r], t[2 * tx + 1][r]);
        *(__half2*)(oh + (size_t)(bx + r) * R + by + 2 * tx) = h2;
    }
}

__global__ __launch_bounds__(256) void prep_kernel(
    const float* __restrict__ wq, const float* __restrict__ wk,
    const float* __restrict__ wv, const float* __restrict__ wo,
    const float* __restrict__ fiw, const float* __restrict__ fow,
    bf16* __restrict__ wqkh, bf16* __restrict__ wqkl,
    __half* __restrict__ wvt, __half* __restrict__ wof,
    __half* __restrict__ fif, __half* __restrict__ fof)
{
    __shared__ float t[64][33];
    int id = blockIdx.x;
    if (id < 2048) {
        dev_tsplit(t, wq, wqkh, wqkl, Dd, Dd, id & 63, id >> 6);
    } else if (id < 4096) {
        id -= 2048;
        dev_tsplit(t, wk, wqkh + (size_t)Dd * Dd, wqkl + (size_t)Dd * Dd, Dd, Dd, id & 63, id >> 6);
    } else if (id < 6144) {
        id -= 4096;
        dev_tfp16(t, wv, wvt, Dd, Dd, id & 63, id >> 6);
    } else if (id < 8192) {
        id -= 6144;
        dev_tfp16(t, wo, wof, Dd, Dd, id & 63, id >> 6);
    } else if (id < 16384) {
        id -= 8192;
        dev_tfp16(t, fiw, fif, Dd, FFf, id & 255, id >> 8);
    } else if (id < 24576) {
        id -= 16384;
        dev_tfp16(t, fow, fof, FFf, Dd, id & 63, id >> 6);
    } else {
        int tt = (id - 24576) * 256 + threadIdx.x;
        int p = tt >> 6, i = tt & 63;
        double inv = pow(10000.0, -((double)(2 * i)) / 128.0);
        float ang = (float)p * (float)inv;
        g_sin[tt] = (float)sin((double)ang);
        g_cos[tt] = (float)cos((double)ang);
    }
}

// ================= LayerNorm =================
__global__ __launch_bounds__(256) void ln_kernel(
    const float* __restrict__ x, const float* __restrict__ x2,
    const float* __restrict__ g, const float* __restrict__ bta,
    float* __restrict__ outf, bf16* __restrict__ outh, bf16* __restrict__ outl,
    __half* __restrict__ o16)
{
    __shared__ float red[256];
    int row = blockIdx.x, tid = threadIdx.x;
    size_t base = (size_t)row * Dd;
    float r[8];
    float s = 0.f;
#pragma unroll
    for (int t = 0; t < 8; t++) {
        int i = tid + t * 256;
        float v = x[base + i];
        if (x2) v += x2[base + i];
        r[t] = v; s += v;
    }
    red[tid] = s; __syncthreads();
    for (int o = 128; o > 0; o >>= 1) { if (tid < o) red[tid] += red[tid + o]; __syncthreads(); }
    float mean = red[0] * (1.0f / Dd);
    __syncthreads();
    float vs = 0.f;
#pragma unroll
    for (int t = 0; t < 8; t++) { float d = r[t] - mean; vs += d * d; }
    red[tid] = vs; __syncthreads();
    for (int o = 128; o > 0; o >>= 1) { if (tid < o) red[tid] += red[tid + o]; __syncthreads(); }
    float var = red[0] * (1.0f / Dd);
    float rs = rsqrtf(var + 1e-5f);
#pragma unroll
    for (int t = 0; t < 8; t++) {
        int i = tid + t * 256;
        float v = (r[t] - mean) * rs * g[i] + bta[i];
        if (outf) outf[base + i] = v;
        if (outh) {
            bf16 h = __float2bfloat16_rn(v);
            outh[base + i] = h;
            outl[base + i] = __float2bfloat16_rn(v - __bfloat162float(h));
        }
        if (o16) o16[base + i] = __float2half_rn(v);
    }
}

// ================= mixed-precision mma.sync GEMM =================
// MODE 0: bf16x3. MODE 1: fp16x2. MODE 2: fp16x1.
// flags: 1=bias 2=gelu 4=resid 8=qkv(rope+scatter) 16=score 32=ctx
//        64=bf16 hi/lo out 256=fp16 hi/lo out 512=fp16 single out 1024=vtrans fp16 out
#define PPA 10240u            // A part bytes (128 rows * 80B)

template<int BN, int MODE, int MINCTAS, int NSTG>
__global__ __launch_bounds__(256, MINCTAS) void gemm_mp(
    const void* __restrict__ Ahv, const void* __restrict__ Alv,
    const void* __restrict__ Bhv, const void* __restrict__ Blv,
    const float* __restrict__ bias, const float* __restrict__ resid,
    float* __restrict__ Cf, void* __restrict__ Chv, void* __restrict__ Clv,
    const int* __restrict__ pid,
    int K, int lda, int ldb, int ldc, int flags)
{
    constexpr uint32_t PPB = (uint32_t)BN * 80u;
    constexpr uint32_t APARTS = (MODE == 2) ? 1u : 2u;
    constexpr uint32_t BPARTS = (MODE == 0) ? 2u : 1u;
    constexpr uint32_t STG = APARTS * PPA + BPARTS * PPB;
    constexpr int NFR = BN / 32;
    constexpr int NPAIR = NFR / 2;
    extern __shared__ char sm[];
    int bx = blockIdx.x, by = blockIdx.y, bz = blockIdx.z;
    const uint16_t* Ahp = (const uint16_t*)Ahv;
    const uint16_t* Alp = (const uint16_t*)Alv;
    const uint16_t* Bhp = (const uint16_t*)Bhv;
    const uint16_t* Blp = (const uint16_t*)Blv;
    float* Cfp = Cf;
    uint16_t* Chp = (uint16_t*)Chv;
    uint16_t* Clp = (uint16_t*)Clv;
    int Keff = K;
    const int tid = threadIdx.x, lane = tid & 31, warp = tid >> 5;
    if (flags & 16) {
        int b = bz >> 4, h = bz & 15;
        size_t ao = (size_t)b * Ss * Dd + h * DHd;
        Ahp += ao; Alp += ao; Bhp += ao; Blp += ao;
        Cfp += (size_t)bz * Ss * Ss;
        if (bx * BN > by * 128 + 127) {
            // fully-masked tile: zero-fill attn fp32 here (DRAM idle in this kernel)
            float4 z = make_float4(0.f, 0.f, 0.f, 0.f);
            float* tb = Cfp + (size_t)(by * 128) * ldc + bx * BN;
#pragma unroll
            for (int i = 0; i < (128 * BN / 4) / 256; i++) {
                int idx = tid + i * 256;
                int r = idx / (BN / 4), c4 = (idx % (BN / 4)) * 4;
                *(float4*)(tb + (size_t)r * ldc + c4) = z;
            }
            return;
        }
    }
    if (flags & 32) {
        bz = blockIdx.x;
        by = gridDim.y - 1 - blockIdx.y;
        bx = 0;
        int b = bz >> 4, h = bz & 15;
        size_t ao = (size_t)bz * Ss * Ss;
        size_t bo = (size_t)bz * DHd * Ss;
        Ahp += ao; Alp += ao; Bhp += bo; Blp += bo;
        size_t co = (size_t)b * Ss * Dd + h * DHd;
        Chp += co; Clp += co;
        Keff = (by + 1) * 128;
    }
    const int m0 = by * 128, n0 = bx * BN;
    const int wm = (warp >> 2) * 64, wn = (warp & 3) * (BN / 4);
    const uint32_t sbase = smem_u32(sm);

    float acc[4][NFR][4];
#pragma unroll
    for (int i = 0; i < 4; i++)
#pragma unroll
        for (int j = 0; j < NFR; j++)
#pragma unroll
            for (int e = 0; e < 4; e++) acc[i][j][e] = 0.f;

#define ISSUE_CHUNK(ST, K0) do { \
    uint32_t sb0 = sbase + (uint32_t)(ST) * STG; \
    _Pragma("unroll") \
    for (int i = 0; i < 2; i++) { \
        int idx = tid + i * 256; \
        int r = idx >> 2; int cc = idx & 3; \
        uint32_t d = sb0 + (uint32_t)r * 80u + (uint32_t)cc * 16u; \
        size_t sa = (size_t)(m0 + r) * lda + (K0) + cc * 8; \
        cp16(d, Ahp + sa); \
        if (MODE != 2) cp16(d + PPA, Alp + sa); \
    } \
    _Pragma("unroll") \
    for (int i = 0; i < BN / 64; i++) { \
        int idx = tid + i * 256; \
        int r = idx >> 2; int cc = idx & 3; \
        uint32_t d = sb0 + APARTS * PPA + (uint32_t)r * 80u + (uint32_t)cc * 16u; \
        size_t sb2 = (size_t)(n0 + r) * ldb + (K0) + cc * 8; \
        cp16(d, Bhp + sb2); \
        if (MODE == 0) cp16(d + PPB, Blp + sb2); \
    } \
    cp_commit(); \
} while(0)

    const uint32_t a_lane_off = (uint32_t)(wm + (lane & 15)) * 80u + (uint32_t)((lane >> 4) * 16);
    const uint32_t b_lane_off = (uint32_t)(wn + ((lane >> 4) * 8) + (lane & 7)) * 80u
                              + (uint32_t)(((lane >> 3) & 1) * 16);

    auto compute_chunk = [&](uint32_t boff) {
#pragma unroll
        for (int ks = 0; ks < 2; ks++) {
            uint32_t ahi[4][4], alo[4][4];
            uint32_t abase = sbase + boff + a_lane_off + (uint32_t)(ks * 32);
            uint32_t bbase = sbase + boff + APARTS * PPA + b_lane_off + (uint32_t)(ks * 32);
#pragma unroll
            for (int mti = 0; mti < 4; mti++) {
                ldm4(ahi[mti], abase + (uint32_t)(mti * 16) * 80u);
                if (MODE != 2) ldm4(alo[mti], abase + (uint32_t)(mti * 16) * 80u + PPA);
            }
#pragma unroll
            for (int p = 0; p < NPAIR; p++) {
                uint32_t bh4[4];
                ldm4(bh4, bbase + (uint32_t)(p * 16) * 80u);
                if (MODE == 0) {
                    uint32_t bl4[4];
                    ldm4(bl4, bbase + (uint32_t)(p * 16) * 80u + PPB);
#pragma unroll
                    for (int mti = 0; mti < 4; mti++) {
                        mma_bf16(acc[mti][2 * p],     ahi[mti], bh4);
                        mma_bf16(acc[mti][2 * p + 1], ahi[mti], bh4 + 2);
                    }
#pragma unroll
                    for (int mti = 0; mti < 4; mti++) {
                        mma_bf16(acc[mti][2 * p],     ahi[mti], bl4);
                        mma_bf16(acc[mti][2 * p + 1], ahi[mti], bl4 + 2);
                    }
#pragma unroll
                    for (int mti = 0; mti < 4; mti++) {
                        mma_bf16(acc[mti][2 * p],     alo[mti], bh4);
                        mma_bf16(acc[mti][2 * p + 1], alo[mti], bh4 + 2);
                    }
                } else if (MODE == 1) {
#pragma unroll
                    for (int mti = 0; mti < 4; mti++) {
                        mma_fp16(acc[mti][2 * p],     ahi[mti], bh4);
                        mma_fp16(acc[mti][2 * p + 1], ahi[mti], bh4 + 2);
                    }
#pragma unroll
                    for (int mti = 0; mti < 4; mti++) {
                        mma_fp16(acc[mti][2 * p],     alo[mti], bh4);
                        mma_fp16(acc[mti][2 * p + 1], alo[mti], bh4 + 2);
                    }
                } else {
#pragma unroll
                    for (int mti = 0; mti < 4; mti++) {
                        mma_fp16(acc[mti][2 * p],     ahi[mti], bh4);
                        mma_fp16(acc[mti][2 * p + 1], ahi[mti], bh4 + 2);
                    }
                }
            }
        }
    };

    const int nch = Keff / 32;
    if (NSTG == 2) {
        ISSUE_CHUNK(0, 0);
        for (int c = 0; c < nch; c++) {
            if (c + 1 < nch) { ISSUE_CHUNK((c + 1) & 1, (c + 1) * 32); cp_wait1(); }
            else cp_wait0();
            __syncthreads();
            compute_chunk((uint32_t)(c & 1) * STG);
            __syncthreads();
        }
    } else {
#pragma unroll
        for (int s = 0; s < NSTG - 1; s++)
            if (s < nch) ISSUE_CHUNK(s, s * 32);
        for (int c = 0; c < nch; c++) {
            int rem = nch - 1 - c;
            if (NSTG >= 4 && rem >= 2) cp_wait2();
            else if (rem >= 1) cp_wait1();
            else cp_wait0();
            __syncthreads();
            compute_chunk((uint32_t)(c % NSTG) * STG);
            if (c + NSTG - 1 < nch) ISSUE_CHUNK((c + NSTG - 1) % NSTG, (c + NSTG - 1) * 32);
        }
    }
#undef ISSUE_CHUNK

    // ---------------- vtrans epilogue: smem transpose -> vt16[bh][n][s] ----------------
    if (flags & 1024) {
        __syncthreads();                    // stage buffers free only after all warps done
        __half* tile = (__half*)sm;
        const int PITCH = 136;              // conflict-free write pattern
#pragma unroll
        for (int mti = 0; mti < 4; mti++)
#pragma unroll
            for (int ntj = 0; ntj < NFR; ntj++)
#pragma unroll
                for (int half = 0; half < 2; half++) {
                    int rowl = wm + mti * 16 + (lane >> 2) + half * 8;
                    int coll = wn + ntj * 8 + (lane & 3) * 2;
                    *(__half2*)&tile[rowl * PITCH + coll] =
                        __floats2half2_rn(acc[mti][ntj][half * 2], acc[mti][ntj][half * 2 + 1]);
                }
        __syncthreads();
        // rows m0..m0+127 = sequence positions; cols = head bx (BN==DHd==128)
        __half* dst = (__half*)Chp
            + ((size_t)((m0 >> 11) * Hh + bx) * DHd) * Ss + (m0 & 2047);
#pragma unroll
        for (int i = 0; i < 8; i++) {
            int linear = tid + i * 256;
            int n = linear & 127, s8 = (linear >> 7) * 8;
            __half tmp[8];
#pragma unroll
            for (int j = 0; j < 8; j++) tmp[j] = tile[(s8 + j) * PITCH + n];
            *(uint4*)(dst + (size_t)n * Ss + s8) = *(uint4*)tmp;
        }
        return;
    }

    // ---------------- standard epilogue ----------------
#pragma unroll
    for (int mti = 0; mti < 4; mti++) {
#pragma unroll
        for (int ntj = 0; ntj < NFR; ntj++) {
            int row = m0 + wm + mti * 16 + (lane >> 2);
            int col = n0 + wn + ntj * 8 + (lane & 3) * 2;
#pragma unroll
            for (int half = 0; half < 2; half++) {
                int rr = row + half * 8;
                float v0 = acc[mti][ntj][half * 2];
                float v1 = acc[mti][ntj][half * 2 + 1];
                if (flags & 1) { v0 += bias[col]; v1 += bias[col + 1]; }
                if (flags & 2) {
                    v0 = 0.5f * v0 * (1.0f + erff(v0 * 0.70710678118654752f));
                    v1 = 0.5f * v1 * (1.0f + erff(v1 * 0.70710678118654752f));
                }
                if (flags & 4) {
                    const float* rp = resid + (size_t)rr * ldc + col;
                    v0 += rp[0]; v1 += rp[1];
                }
                if (flags & 8) {
                    int sel = col >> 11, cl = col & 2047;
                    int b = rr >> 11, s = rr & 2047;
                    int pos = pid[b * Ss + s];
                    int i = (cl & 127) >> 1;
                    float sn = g_sin[pos * 64 + i], cs = g_cos[pos * 64 + i];
                    float r0 = v0 * cs - v1 * sn;
                    float r1 = v1 * cs + v0 * sn;
                    size_t o = (size_t)(sel * ROWS + rr) * Dd + cl;
                    split2(r0, r1, (bf16*)(Chp + o), (bf16*)(Clp + o));
                } else if (flags & 64) {
                    size_t o = (size_t)rr * ldc + col;
                    split2(v0, v1, (bf16*)(Chp + o), (bf16*)(Clp + o));
                } else if (flags & 256) {
                    size_t o = (size_t)rr * ldc + col;
                    split2h(v0, v1, (__half*)(Chp + o), (__half*)(Clp + o));
                } else if (flags & 512) {
                    size_t o = (size_t)rr * ldc + col;
                    *(__half2*)((__half*)Chp + o) = __floats2half2_rn(v0, v1);
                } else {
                    *(float2*)(Cfp + (size_t)rr * ldc + col) = make_float2(v0, v1);
                }
            }
        }
    }
}

// ================= row softmax (causal trunc, vectorized) + single fp16 out =================
__global__ __launch_bounds__(256) void softmax_kernel(
    float* __restrict__ attn, __half* __restrict__ ah)
{
    int rid = blockIdx.x;
    int qpos = rid & (Ss - 1);
    int L = qpos + 1;
    int Lpad = ((qpos >> 7) + 1) << 7;
    float* row = attn + (size_t)rid * Ss;
    __half* rh = ah + (size_t)rid * Ss;
    __shared__ float red[256];
    int tid = threadIdx.x;
    int base = tid * 8;
    float r[8];
    if (base < L) {
        float4 ra = *(const float4*)(row + base);
        float4 rb = *(const float4*)(row + base + 4);
        r[0] = ra.x; r[1] = ra.y; r[2] = ra.z; r[3] = ra.w;
        r[4] = rb.x; r[5] = rb.y; r[6] = rb.z; r[7] = rb.w;
    } else {
#pragma unroll
        for (int t = 0; t < 8; t++) r[t] = -3.4e38f;
    }
    float mx = -3.4e38f;
#pragma unroll
    for (int t = 0; t < 8; t++) {
        if (base + t >= L) r[t] = -3.4e38f;
        mx = fmaxf(mx, r[t]);
    }
    red[tid] = mx; __syncthreads();
    for (int o = 128; o > 0; o >>= 1) { if (tid < o) red[tid] = fmaxf(red[tid], red[tid + o]); __syncthreads(); }
    mx = red[0]; __syncthreads();
    float s = 0.f;
#pragma unroll
    for (int t = 0; t < 8; t++) {
        float e = (base + t < L) ? expf(r[t] - mx) : 0.0f;
        r[t] = e; s += e;
    }
    red[tid] = s; __syncthreads();
    for (int o = 128; o > 0; o >>= 1) { if (tid < o) red[tid] += red[tid + o]; __syncthreads(); }
    float inv = 1.0f / red[0];
#pragma unroll
    for (int t = 0; t < 8; t++) r[t] *= inv;
    if (base < Lpad) {
        *(float4*)(row + base)     = make_float4(r[0], r[1], r[2], r[3]);
        *(float4*)(row + base + 4) = make_float4(r[4], r[5], r[6], r[7]);
        __half2 hh[4];
#pragma unroll
        for (int j = 0; j < 4; j++)
            hh[j] = __floats2half2_rn(r[2 * j], r[2 * j + 1]);
        *(uint4*)(rh + base) = *(uint4*)hh;
    }
}

// ================= launch =================
extern "C" void kernel_launch(void* const* d_in, const int* in_sizes, int n_in,
                              void* d_out, int out_size)
{
    const float* hs   = (const float*)d_in[0];
    const int*   pid  = (const int*)  d_in[1];
    const float* wq   = (const float*)d_in[2];
    const float* wk   = (const float*)d_in[3];
    const float* wv   = (const float*)d_in[4];
    const float* wo   = (const float*)d_in[5];
    const float* ln1g = (const float*)d_in[6];
    const float* ln1b = (const float*)d_in[7];
    const float* ln2g = (const float*)d_in[8];
    const float* ln2b = (const float*)d_in[9];
    const float* fiw  = (const float*)d_in[10];
    const float* fib  = (const float*)d_in[11];
    const float* fow  = (const float*)d_in[12];
    const float* fob  = (const float*)d_in[13];

    float* out  = (float*)d_out;
    float* attn = out + (size_t)ROWS * Dd;

    float *aproj, *h2;
    bf16 *h1h, *h1l, *wqkh, *wqkl, *qkh, *qkl;
    __half *h116, *wvt, *wof, *fif, *fof, *vt16, *ah16;
    __half *ctxh16, *h216, *ffn16;
    cudaGetSymbolAddress((void**)&aproj,  g_aproj);
    cudaGetSymbolAddress((void**)&h2,     g_h2);
    cudaGetSymbolAddress((void**)&h1h,    g_h1h);
    cudaGetSymbolAddress((void**)&h1l,    g_h1l);
    cudaGetSymbolAddress((void**)&h116,   g_h116);
    cudaGetSymbolAddress((void**)&wqkh,   g_wqkh);
    cudaGetSymbolAddress((void**)&wqkl,   g_wqkl);
    cudaGetSymbolAddress((void**)&wvt,    g_wvt16);
    cudaGetSymbolAddress((void**)&wof,    g_wof16);
    cudaGetSymbolAddress((void**)&fif,    g_fif16);
    cudaGetSymbolAddress((void**)&fof,    g_fof16);
    cudaGetSymbolAddress((void**)&qkh,    g_qkh);
    cudaGetSymbolAddress((void**)&qkl,    g_qkl);
    cudaGetSymbolAddress((void**)&vt16,   g_vt16);
    cudaGetSymbolAddress((void**)&ah16,   g_ah16);
    cudaGetSymbolAddress((void**)&ctxh16, g_ctxh16);
    cudaGetSymbolAddress((void**)&h216,   g_h216);
    cudaGetSymbolAddress((void**)&ffn16,  g_ffn16);

    const uint32_t SMT128_0 = 2u * (2u * PPA + 2u * 128u * 80u);   // 81920, 2 CTAs
    const uint32_t SMT128_1 = 3u * (2u * PPA + 1u * 128u * 80u);   // 92160, 2 CTAs
    const uint32_t SMT128_2 = 4u * (1u * PPA + 1u * 128u * 80u);   // 81920, 2 CTAs
    cudaFuncSetAttribute((const void*)gemm_mp<128, 0, 2, 2>, cudaFuncAttributeMaxDynamicSharedMemorySize, SMT128_0);
    cudaFuncSetAttribute((const void*)gemm_mp<128, 1, 2, 3>, cudaFuncAttributeMaxDynamicSharedMemorySize, SMT128_1);
    cudaFuncSetAttribute((const void*)gemm_mp<128, 2, 2, 4>, cudaFuncAttributeMaxDynamicSharedMemorySize, SMT128_2);

    // fused prep: all weight transposes + rope table in one launch
    prep_kernel<<<25088, 256>>>(wq, wk, wv, wo, fiw, fow,
                                wqkh, wqkl, wvt, wof, fif, fof);

    // ln1 -> bf16 hi/lo (for qk) + fp16 single (for v)
    ln_kernel<<<ROWS, 256>>>(hs, nullptr, ln1g, ln1b, nullptr, h1h, h1l, h116);

    // qk projection (bf16x3, RoPE in epilogue); v projection (fp16x1, fused V^T epilogue)
    gemm_mp<128, 0, 2, 2><<<dim3(32, 32), 256, SMT128_0>>>(h1h, h1l, wqkh, wqkl,
        nullptr, nullptr, nullptr, qkh, qkl, pid, Dd, Dd, Dd, Dd, 8);
    gemm_mp<128, 2, 2, 4><<<dim3(16, 32), 256, SMT128_2>>>(h116, nullptr, wvt, nullptr,
        nullptr, nullptr, nullptr, vt16, nullptr, nullptr, Dd, Dd, Dd, Dd, 1024);

    // scores (bf16x3, causal, zero-fill) -> softmax (single fp16) -> ctx (fp16x1, single out)
    gemm_mp<128, 0, 2, 2><<<dim3(16, 16, Bb * Hh), 256, SMT128_0>>>(qkh, qkl,
        qkh + (size_t)ROWS * Dd, qkl + (size_t)ROWS * Dd,
        nullptr, nullptr, attn, nullptr, nullptr, nullptr, DHd, Dd, Dd, Ss, 16);
    softmax_kernel<<<Bb * Hh * Ss, 256>>>(attn, ah16);
    gemm_mp<128, 2, 2, 4><<<dim3(Bb * Hh, 16), 256, SMT128_2>>>(ah16, nullptr, vt16, nullptr,
        nullptr, nullptr, nullptr, ctxh16, nullptr, nullptr, Ss, Ss, Ss, Dd, 32 | 512);

    // output projection (fp16x1)
    gemm_mp<128, 2, 2, 4><<<dim3(16, 32), 256, SMT128_2>>>(ctxh16, nullptr, wof, nullptr,
        nullptr, nullptr, aproj, nullptr, nullptr, nullptr, Dd, Dd, Dd, Dd, 0);

    // ln2 -> fp32 + fp16 single
    ln_kernel<<<ROWS, 256>>>(hs, aproj, ln2g, ln2b, h2, nullptr, nullptr, h216);

    // FFN (fp16x1)
    gemm_mp<128, 2, 2, 4><<<dim3(64, 32), 256, SMT128_2>>>(h216, nullptr, fif, nullptr,
        fib, nullptr, nullptr, ffn16, nullptr, nullptr, Dd, Dd, Dd, FFf, 1 | 2 | 512);
    gemm_mp<128, 2, 2, 4><<<dim3(16, 32), 256, SMT128_2>>>(ffn16, nullptr, fof, nullptr,
        fob, h2, out, nullptr, nullptr, nullptr, FFf, FFf, FFf, Dd, 1 | 4);
}